// round 6
// baseline (speedup 1.0000x reference)
#include <cuda_runtime.h>

#define EPSF 2e-5f
#define NB 4096

typedef unsigned long long u64;

__device__ __forceinline__ u64 ld2(const float* p) {
    return *reinterpret_cast<const u64*>(p);
}
__device__ __forceinline__ u64 fma2(u64 a, u64 b, u64 c) {
    u64 d;
    asm("fma.rn.f32x2 %0, %1, %2, %3;" : "=l"(d) : "l"(a), "l"(b), "l"(c));
    return d;
}
__device__ __forceinline__ float2 up2(u64 v) {
    float2 r;
    asm("mov.b64 {%0,%1}, %2;" : "=f"(r.x), "=f"(r.y) : "l"(v));
    return r;
}
__device__ __forceinline__ u64 dupw(float w) {
    u64 d;
    asm("mov.b64 %0, {%1,%1};" : "=l"(d) : "f"(w));
    return d;
}

// ---------------- scratch planes, [feature][batch] ----------------
__device__ __align__(16) float  g_xT [600*NB];   // [(t*6+c)][b]
__device__ __align__(16) float  g_m1 [2700*NB];  // (12,9,25) max-pooled relu'd lift
__device__ __align__(16) float  g_m2 [1008*NB];  // (24,7,6)  max-pooled relu'd conv2
__device__ __align__(16) float  g_a3 [720*NB];   // (48,5,3)  relu'd pooled conv3
__device__ __align__(16) float  g_a4T[288*NB];   // (96,3)    relu'd pooled conv4
__device__ double g_stats[360];   // s1:0 q1:12 s2:24 q2:48 s3:72 q3:120 s4:168 q4:264
__device__ float  g_bias2[4200];  // [ii(7)][x(25)][co(24)]
__device__ float  g_bias3[1440];  // [ii(5)][x(6)][co(48)]
__device__ float  g_bias4[576];   // [ii(3)][x(2)][co(96)]
__device__ float  g_Wc[6*288];
__device__ float  g_bc[6];

__global__ void k_zero() {
    int t = threadIdx.x;
    if (t < 360) g_stats[t] = 0.0;
}

// ---------------- transpose x (4096,600) -> xT (600,4096) ----------------
__global__ void k_tr(const float* __restrict__ x) {
    __shared__ float tile[32][33];
    int bx = blockIdx.x * 32;
    int fy = blockIdx.y * 32;
    int tx = threadIdx.x, ty = threadIdx.y;
    #pragma unroll
    for (int m = 0; m < 4; m++) {
        int ff = fy + tx;
        tile[ty + m*8][tx] = (ff < 600) ? x[(bx + ty + m*8)*600 + ff] : 0.f;
    }
    __syncthreads();
    #pragma unroll
    for (int m = 0; m < 4; m++) {
        int ff = fy + ty + m*8;
        if (ff < 600) g_xT[ff*NB + bx + tx] = tile[tx][ty + m*8];
    }
}

// ---------------- Phase 1: lift conv + pool1(relu) + pool2(max) + stats ----------------
// task = (hh, op): 4 pre-pool positions 4op..4op+3 -> 2 pooled-1 (stats) -> 1 pooled-2 stored.
__global__ __launch_bounds__(256) void k_p1(const float* __restrict__ w1) {
    __shared__ u64 wd[504];           // [(c*7+j)*12 + co]
    __shared__ float ssum[12], ssq[12];
    int tid = threadIdx.x, lane = tid & 31, wid = tid >> 5;
    int b = blockIdx.x * 64 + lane * 2;
    for (int i = tid; i < 504; i += 256) { int co = i/42, k = i%42; wd[k*12+co] = dupw(w1[i]); }
    if (tid < 12) { ssum[tid] = 0.f; ssq[tid] = 0.f; }
    __syncthreads();
    float s[12], q[12];
    #pragma unroll
    for (int u = 0; u < 12; u++) { s[u] = 0.f; q[u] = 0.f; }
    for (int t = blockIdx.y*8 + wid; t < 225; t += 64) {
        int hh = t / 25, op = t % 25;
        int sc = 1 << hh, px = 4*op;
        u64 acc[12][4];
        #pragma unroll
        for (int u = 0; u < 12; u++)
            #pragma unroll
            for (int d = 0; d < 4; d++) acc[u][d] = 0ull;
        for (int c = 0; c < 6; c++) {
            const float* pc = &g_xT[(size_t)c*NB + b];
            #pragma unroll
            for (int j = 0; j < 7; j++) {
                int t0 = px + (j-3)*sc;
                u64 a0 = (t0   >= 0 && t0   < 100) ? ld2(pc + (size_t)(t0  )*6*NB) : 0ull;
                u64 a1 = (t0+1 >= 0 && t0+1 < 100) ? ld2(pc + (size_t)(t0+1)*6*NB) : 0ull;
                u64 a2 = (t0+2 >= 0 && t0+2 < 100) ? ld2(pc + (size_t)(t0+2)*6*NB) : 0ull;
                u64 a3 = (t0+3 >= 0 && t0+3 < 100) ? ld2(pc + (size_t)(t0+3)*6*NB) : 0ull;
                const u64* wp = &wd[(c*7 + j)*12];
                #pragma unroll
                for (int u = 0; u < 12; u++) {
                    u64 w = wp[u];
                    acc[u][0] = fma2(w, a0, acc[u][0]);
                    acc[u][1] = fma2(w, a1, acc[u][1]);
                    acc[u][2] = fma2(w, a2, acc[u][2]);
                    acc[u][3] = fma2(w, a3, acc[u][3]);
                }
            }
        }
        float inv = 1.f/(float)sc;
        #pragma unroll
        for (int u = 0; u < 12; u++) {
            float2 p0 = up2(acc[u][0]), p1 = up2(acc[u][1]);
            float2 p2 = up2(acc[u][2]), p3 = up2(acc[u][3]);
            float v0x = fmaxf(fmaxf(p0.x, p1.x), 0.f)*inv;
            float v0y = fmaxf(fmaxf(p0.y, p1.y), 0.f)*inv;
            float v1x = fmaxf(fmaxf(p2.x, p3.x), 0.f)*inv;
            float v1y = fmaxf(fmaxf(p2.y, p3.y), 0.f)*inv;
            s[u] += v0x + v0y + v1x + v1y;
            q[u] += v0x*v0x + v0y*v0y + v1x*v1x + v1y*v1y;
            *reinterpret_cast<float2*>(&g_m1[(size_t)((u*9+hh)*25 + op)*NB + b]) =
                make_float2(fmaxf(v0x, v1x), fmaxf(v0y, v1y));
        }
    }
    #pragma unroll
    for (int u = 0; u < 12; u++) {
        #pragma unroll
        for (int o = 16; o; o >>= 1) {
            s[u] += __shfl_down_sync(0xffffffffu, s[u], o);
            q[u] += __shfl_down_sync(0xffffffffu, q[u], o);
        }
    }
    if (lane == 0) {
        #pragma unroll
        for (int u = 0; u < 12; u++) { atomicAdd(&ssum[u], s[u]); atomicAdd(&ssq[u], q[u]); }
    }
    __syncthreads();
    if (tid < 12) {
        atomicAdd(&g_stats[tid],    (double)ssum[tid]);
        atomicAdd(&g_stats[12+tid], (double)ssq[tid]);
    }
}

// ---------------- bias precompute kernels ----------------
__global__ __launch_bounds__(256) void k_bias2(const float* __restrict__ w2,
                                               const float* __restrict__ g1,
                                               const float* __restrict__ b1) {
    __shared__ float Bc[12];
    int tid = threadIdx.x;
    if (tid < 12) {
        double m = g_stats[tid] / 1843200.0;
        double v = g_stats[12+tid] / 1843200.0 - m*m;
        float a = g1[tid] * rsqrtf((float)v + EPSF);
        Bc[tid] = b1[tid] - (float)m*a;
    }
    __syncthreads();
    int idx = blockIdx.x*256 + tid;
    if (idx >= 4200) return;
    int ii = idx / 600, rem = idx % 600, x = rem / 24, co = rem % 24;
    int sc = 1 << ii;
    float acc = 0.f;
    for (int c = 0; c < 12; c++) {
        float bc = Bc[c];
        for (int r = 0; r < 3; r++)
            for (int j = 0; j < 5; j++) {
                int x0 = x + (j-2)*sc;
                if (x0 >= 0 && x0 < 25) acc += w2[co*180 + c*15 + r*5 + j] * bc;
            }
    }
    g_bias2[idx] = acc;
}

__global__ __launch_bounds__(256) void k_bias3(const float* __restrict__ w3,
                                               const float* __restrict__ g2,
                                               const float* __restrict__ b2) {
    __shared__ float Bc[24];
    int tid = threadIdx.x;
    if (tid < 24) {
        double m = g_stats[24+tid] / 344064.0;
        double v = g_stats[48+tid] / 344064.0 - m*m;
        float a = g2[tid] * rsqrtf((float)v + EPSF);
        Bc[tid] = b2[tid] - (float)m*a;
    }
    __syncthreads();
    int idx = blockIdx.x*256 + tid;
    if (idx >= 1440) return;
    int ii = idx / 288, rem = idx % 288, x = rem / 48, co = rem % 48;
    int sc = 1 << ii;
    float acc = 0.f;
    for (int c = 0; c < 24; c++) {
        float bc = Bc[c];
        for (int r = 0; r < 3; r++)
            for (int j = 0; j < 5; j++) {
                int x0 = x + (j-2)*sc;
                if (x0 >= 0 && x0 < 6) acc += w3[co*360 + c*15 + r*5 + j] * bc;
            }
    }
    g_bias3[idx] = acc;
}

__global__ __launch_bounds__(256) void k_bias4(const float* __restrict__ w4,
                                               const float* __restrict__ g3,
                                               const float* __restrict__ b3) {
    __shared__ float Bc[48];
    int tid = threadIdx.x;
    if (tid < 48) {
        double m = g_stats[72+tid] / 61440.0;
        double v = g_stats[120+tid] / 61440.0 - m*m;
        float a = g3[tid] * rsqrtf((float)v + EPSF);
        Bc[tid] = b3[tid] - (float)m*a;
    }
    __syncthreads();
    int idx = blockIdx.x*256 + tid;
    if (idx >= 576) return;
    int ii = idx / 192, rem = idx % 192, x = rem / 96, co = rem % 96;
    int sc = 1 << ii;
    float acc = 0.f;
    for (int c = 0; c < 48; c++) {
        float bc = Bc[c];
        for (int r = 0; r < 3; r++)
            for (int j = 0; j < 3; j++) {
                int x0 = x + (j-1)*sc;
                if (x0 >= 0 && x0 < 3) acc += w4[co*432 + c*9 + r*3 + j] * bc;
            }
    }
    g_bias4[idx] = acc;
}

// ---------------- Phase 2: gg_conv w2 (bn1 folded) + pool + stats ----------------
// warp: fixed cog (12 cos); task = (ii, op): 4 pre-pool x -> 2 pooled-1 (stats) -> 1 stored
__global__ __launch_bounds__(256) void k_p2(const float* __restrict__ w2,
                                            const float* __restrict__ g1) {
    __shared__ u64 wd[4320];          // [(c*15+r*5+j)*24 + co], scaled by A1[c]
    __shared__ float A1[12];
    __shared__ float ssum[24], ssq[24];
    int tid = threadIdx.x, lane = tid & 31, wid = tid >> 5;
    int b = blockIdx.x * 64 + lane * 2;
    if (tid < 12) {
        double m = g_stats[tid] / 1843200.0;
        double v = g_stats[12+tid] / 1843200.0 - m*m;
        A1[tid] = g1[tid] * rsqrtf((float)v + EPSF);
    }
    if (tid < 24) { ssum[tid] = 0.f; ssq[tid] = 0.f; }
    __syncthreads();
    for (int i = tid; i < 4320; i += 256) {
        int co = i/180, k = i%180, c = k/15;
        wd[k*24+co] = dupw(w2[i] * A1[c]);
    }
    __syncthreads();
    int gw = blockIdx.y * 8 + wid;    // 0..31
    int cog = gw & 1;
    int co0 = cog * 12;
    float s[12], q[12];
    #pragma unroll
    for (int u = 0; u < 12; u++) { s[u] = 0.f; q[u] = 0.f; }
    for (int t = gw >> 1; t < 42; t += 16) {
        int ii = t / 6, op = t % 6;
        int sc = 1 << ii, px = 4*op;
        u64 acc[12][4];
        #pragma unroll
        for (int u = 0; u < 12; u++)
            #pragma unroll
            for (int d = 0; d < 4; d++) acc[u][d] = 0ull;
        for (int c = 0; c < 12; c++) {
            #pragma unroll
            for (int r = 0; r < 3; r++) {
                const float* pb = &g_m1[(size_t)((c*9 + ii + r)*25)*NB + b];
                const u64* wk = &wd[(c*15 + r*5)*24 + co0];
                #pragma unroll
                for (int j = 0; j < 5; j++) {
                    int x0 = px + (j-2)*sc;
                    u64 a0 = (x0   >= 0 && x0   < 25) ? ld2(pb + (size_t)(x0  )*NB) : 0ull;
                    u64 a1 = (x0+1 >= 0 && x0+1 < 25) ? ld2(pb + (size_t)(x0+1)*NB) : 0ull;
                    u64 a2 = (x0+2 >= 0 && x0+2 < 25) ? ld2(pb + (size_t)(x0+2)*NB) : 0ull;
                    u64 a3 = (x0+3 >= 0 && x0+3 < 25) ? ld2(pb + (size_t)(x0+3)*NB) : 0ull;
                    const u64* wp = wk + j*24;
                    #pragma unroll
                    for (int u = 0; u < 12; u++) {
                        u64 w = wp[u];
                        acc[u][0] = fma2(w, a0, acc[u][0]);
                        acc[u][1] = fma2(w, a1, acc[u][1]);
                        acc[u][2] = fma2(w, a2, acc[u][2]);
                        acc[u][3] = fma2(w, a3, acc[u][3]);
                    }
                }
            }
        }
        float inv = 1.f/(float)sc;
        #pragma unroll
        for (int u = 0; u < 12; u++) {
            float bias0 = g_bias2[(ii*25 + px    )*24 + co0 + u];
            float bias1 = g_bias2[(ii*25 + px + 1)*24 + co0 + u];
            float bias2v= g_bias2[(ii*25 + px + 2)*24 + co0 + u];
            float bias3v= g_bias2[(ii*25 + px + 3)*24 + co0 + u];
            float2 p0 = up2(acc[u][0]), p1 = up2(acc[u][1]);
            float2 p2 = up2(acc[u][2]), p3 = up2(acc[u][3]);
            float v0x = fmaxf(fmaxf(p0.x + bias0, p1.x + bias1), 0.f)*inv;
            float v0y = fmaxf(fmaxf(p0.y + bias0, p1.y + bias1), 0.f)*inv;
            float v1x = fmaxf(fmaxf(p2.x + bias2v, p3.x + bias3v), 0.f)*inv;
            float v1y = fmaxf(fmaxf(p2.y + bias2v, p3.y + bias3v), 0.f)*inv;
            s[u] += v0x + v0y + v1x + v1y;
            q[u] += v0x*v0x + v0y*v0y + v1x*v1x + v1y*v1y;
            *reinterpret_cast<float2*>(&g_m2[(size_t)(((co0+u)*7+ii)*6 + op)*NB + b]) =
                make_float2(fmaxf(v0x, v1x), fmaxf(v0y, v1y));
        }
    }
    #pragma unroll
    for (int u = 0; u < 12; u++) {
        #pragma unroll
        for (int o = 16; o; o >>= 1) {
            s[u] += __shfl_down_sync(0xffffffffu, s[u], o);
            q[u] += __shfl_down_sync(0xffffffffu, q[u], o);
        }
    }
    if (lane == 0) {
        #pragma unroll
        for (int u = 0; u < 12; u++) { atomicAdd(&ssum[co0+u], s[u]); atomicAdd(&ssq[co0+u], q[u]); }
    }
    __syncthreads();
    if (tid < 24) {
        atomicAdd(&g_stats[24+tid], (double)ssum[tid]);
        atomicAdd(&g_stats[48+tid], (double)ssq[tid]);
    }
}

// ---------------- Phase 3: gg_conv w3 (bn2 folded) + pool + stats ----------------
// blockIdx.y: bit1 = half (24 of 48 cos), bit0 = task group. units per cog: 10 = ii(5) x {pair, single}
__global__ __launch_bounds__(256) void k_p3(const float* __restrict__ w3,
                                            const float* __restrict__ g2) {
    extern __shared__ u64 wd3[];        // 8640: [(c*15+r*5+j)*24 + u], scaled by A2[c]
    __shared__ float A2[24];
    __shared__ float ssum[24], ssq[24];
    int tid = threadIdx.x, lane = tid & 31, wid = tid >> 5;
    int b = blockIdx.x * 64 + lane * 2;
    int half = blockIdx.y >> 1;
    int tg   = blockIdx.y & 1;
    int cbase = half * 24;
    if (tid < 24) {
        double m = g_stats[24+tid] / 344064.0;
        double v = g_stats[48+tid] / 344064.0 - m*m;
        A2[tid] = g2[tid] * rsqrtf((float)v + EPSF);
        ssum[tid] = 0.f; ssq[tid] = 0.f;
    }
    __syncthreads();
    for (int i = tid; i < 8640; i += 256) {
        int u = i/360, k = i%360, c = k/15;
        wd3[k*24+u] = dupw(w3[(cbase+u)*360 + k] * A2[c]);
    }
    __syncthreads();
    int gw = tg * 8 + wid;    // 0..15
    int cog = gw & 1;
    int co0 = cog * 12;
    float s[12], q[12];
    #pragma unroll
    for (int u = 0; u < 12; u++) { s[u] = 0.f; q[u] = 0.f; }
    for (int un = gw >> 1; un < 10; un += 8) {
        int ii = un / 2, kind = un & 1;
        int sc = 1 << ii;
        float inv = 1.f/(float)sc;
        if (kind == 0) {
            // pooled ox 0,1 from pre-pool x 0..3
            u64 acc[12][4];
            #pragma unroll
            for (int u = 0; u < 12; u++)
                #pragma unroll
                for (int d = 0; d < 4; d++) acc[u][d] = 0ull;
            for (int c = 0; c < 24; c++) {
                #pragma unroll
                for (int r = 0; r < 3; r++) {
                    const float* pb = &g_m2[(size_t)((c*7 + ii + r)*6)*NB + b];
                    const u64* wk = &wd3[(c*15 + r*5)*24 + co0];
                    #pragma unroll
                    for (int j = 0; j < 5; j++) {
                        int x0 = (j-2)*sc;
                        u64 a0 = (x0   >= 0 && x0   < 6) ? ld2(pb + (size_t)(x0  )*NB) : 0ull;
                        u64 a1 = (x0+1 >= 0 && x0+1 < 6) ? ld2(pb + (size_t)(x0+1)*NB) : 0ull;
                        u64 a2 = (x0+2 >= 0 && x0+2 < 6) ? ld2(pb + (size_t)(x0+2)*NB) : 0ull;
                        u64 a3 = (x0+3 >= 0 && x0+3 < 6) ? ld2(pb + (size_t)(x0+3)*NB) : 0ull;
                        const u64* wp = wk + j*24;
                        #pragma unroll
                        for (int u = 0; u < 12; u++) {
                            u64 w = wp[u];
                            acc[u][0] = fma2(w, a0, acc[u][0]);
                            acc[u][1] = fma2(w, a1, acc[u][1]);
                            acc[u][2] = fma2(w, a2, acc[u][2]);
                            acc[u][3] = fma2(w, a3, acc[u][3]);
                        }
                    }
                }
            }
            #pragma unroll
            for (int u = 0; u < 12; u++) {
                int gco = cbase + co0 + u;
                float bias0 = g_bias3[(ii*6 + 0)*48 + gco];
                float bias1 = g_bias3[(ii*6 + 1)*48 + gco];
                float bias2v= g_bias3[(ii*6 + 2)*48 + gco];
                float bias3v= g_bias3[(ii*6 + 3)*48 + gco];
                float2 p0 = up2(acc[u][0]), p1 = up2(acc[u][1]);
                float2 p2 = up2(acc[u][2]), p3 = up2(acc[u][3]);
                float v0x = fmaxf(fmaxf(p0.x + bias0, p1.x + bias1), 0.f)*inv;
                float v0y = fmaxf(fmaxf(p0.y + bias0, p1.y + bias1), 0.f)*inv;
                float v1x = fmaxf(fmaxf(p2.x + bias2v, p3.x + bias3v), 0.f)*inv;
                float v1y = fmaxf(fmaxf(p2.y + bias2v, p3.y + bias3v), 0.f)*inv;
                s[u] += v0x + v0y + v1x + v1y;
                q[u] += v0x*v0x + v0y*v0y + v1x*v1x + v1y*v1y;
                *reinterpret_cast<float2*>(&g_a3[(size_t)(gco*15 + ii*3 + 0)*NB + b]) = make_float2(v0x, v0y);
                *reinterpret_cast<float2*>(&g_a3[(size_t)(gco*15 + ii*3 + 1)*NB + b]) = make_float2(v1x, v1y);
            }
        } else {
            // pooled ox 2 from pre-pool x 4,5
            u64 acc[12][2];
            #pragma unroll
            for (int u = 0; u < 12; u++) { acc[u][0] = 0ull; acc[u][1] = 0ull; }
            for (int c = 0; c < 24; c++) {
                #pragma unroll
                for (int r = 0; r < 3; r++) {
                    const float* pb = &g_m2[(size_t)((c*7 + ii + r)*6)*NB + b];
                    const u64* wk = &wd3[(c*15 + r*5)*24 + co0];
                    #pragma unroll
                    for (int j = 0; j < 5; j++) {
                        int x0 = 4 + (j-2)*sc;
                        u64 a0 = (x0   >= 0 && x0   < 6) ? ld2(pb + (size_t)(x0  )*NB) : 0ull;
                        u64 a1 = (x0+1 >= 0 && x0+1 < 6) ? ld2(pb + (size_t)(x0+1)*NB) : 0ull;
                        const u64* wp = wk + j*24;
                        #pragma unroll
                        for (int u = 0; u < 12; u++) {
                            u64 w = wp[u];
                            acc[u][0] = fma2(w, a0, acc[u][0]);
                            acc[u][1] = fma2(w, a1, acc[u][1]);
                        }
                    }
                }
            }
            #pragma unroll
            for (int u = 0; u < 12; u++) {
                int gco = cbase + co0 + u;
                float bias0 = g_bias3[(ii*6 + 4)*48 + gco];
                float bias1 = g_bias3[(ii*6 + 5)*48 + gco];
                float2 p0 = up2(acc[u][0]), p1 = up2(acc[u][1]);
                float vx = fmaxf(fmaxf(p0.x + bias0, p1.x + bias1), 0.f)*inv;
                float vy = fmaxf(fmaxf(p0.y + bias0, p1.y + bias1), 0.f)*inv;
                s[u] += vx + vy;
                q[u] += vx*vx + vy*vy;
                *reinterpret_cast<float2*>(&g_a3[(size_t)(gco*15 + ii*3 + 2)*NB + b]) = make_float2(vx, vy);
            }
        }
    }
    #pragma unroll
    for (int u = 0; u < 12; u++) {
        #pragma unroll
        for (int o = 16; o; o >>= 1) {
            s[u] += __shfl_down_sync(0xffffffffu, s[u], o);
            q[u] += __shfl_down_sync(0xffffffffu, q[u], o);
        }
    }
    if (lane == 0) {
        #pragma unroll
        for (int u = 0; u < 12; u++) { atomicAdd(&ssum[co0+u], s[u]); atomicAdd(&ssq[co0+u], q[u]); }
    }
    __syncthreads();
    if (tid < 24) {
        atomicAdd(&g_stats[72+cbase+tid],  (double)ssum[tid]);
        atomicAdd(&g_stats[120+cbase+tid], (double)ssq[tid]);
    }
}

// ---------------- Phase 4: gg_conv w4 (bn3 folded) + pool + stats ----------------
// blockIdx.y: 24 cos each. 6 warps: cog(3: co-tile 8) x unit(2: ii-pair{0,1} / ii-single{2})
__global__ __launch_bounds__(192) void k_p4(const float* __restrict__ w4,
                                            const float* __restrict__ g3) {
    extern __shared__ u64 wd4[];        // 10368: [(c*9+r*3+j)*24 + u], scaled by A3[c]
    __shared__ float A3[48];
    __shared__ float ssum[24], ssq[24];
    int tid = threadIdx.x, lane = tid & 31, wid = tid >> 5;
    int b = blockIdx.x * 64 + lane * 2;
    int cbase = blockIdx.y * 24;
    if (tid < 48) {
        double m = g_stats[72+tid] / 61440.0;
        double v = g_stats[120+tid] / 61440.0 - m*m;
        A3[tid] = g3[tid] * rsqrtf((float)v + EPSF);
    }
    if (tid < 24) { ssum[tid] = 0.f; ssq[tid] = 0.f; }
    __syncthreads();
    for (int i = tid; i < 10368; i += 192) {
        int u = i/432, k = i%432, c = k/9;
        wd4[k*24+u] = dupw(w4[(cbase+u)*432 + k] * A3[c]);
    }
    __syncthreads();
    int cog = wid >> 1;     // 0..2
    int unit = wid & 1;
    int co0 = cog * 8;
    float s[8], q[8];
    #pragma unroll
    for (int u = 0; u < 8; u++) { s[u] = 0.f; q[u] = 0.f; }
    if (unit == 0) {
        // ii = 0 and 1, sharing weight loads
        u64 acc[8][2][2];
        #pragma unroll
        for (int u = 0; u < 8; u++)
            #pragma unroll
            for (int i2 = 0; i2 < 2; i2++) { acc[u][i2][0] = 0ull; acc[u][i2][1] = 0ull; }
        for (int c = 0; c < 48; c++) {
            #pragma unroll
            for (int r = 0; r < 3; r++) {
                const float* pb0 = &g_a3[(size_t)((c*5 + 0 + r)*3)*NB + b];
                const float* pb1 = &g_a3[(size_t)((c*5 + 1 + r)*3)*NB + b];
                const u64* wk = &wd4[(c*9 + r*3)*24 + co0];
                #pragma unroll
                for (int j = 0; j < 3; j++) {
                    int x0a = (j-1);        // ii=0, s=1
                    int x0b = (j-1)*2;      // ii=1, s=2
                    u64 a00 = (x0a   >= 0 && x0a   < 3) ? ld2(pb0 + (size_t)(x0a  )*NB) : 0ull;
                    u64 a01 = (x0a+1 >= 0 && x0a+1 < 3) ? ld2(pb0 + (size_t)(x0a+1)*NB) : 0ull;
                    u64 a10 = (x0b   >= 0 && x0b   < 3) ? ld2(pb1 + (size_t)(x0b  )*NB) : 0ull;
                    u64 a11 = (x0b+1 >= 0 && x0b+1 < 3) ? ld2(pb1 + (size_t)(x0b+1)*NB) : 0ull;
                    const u64* wp = wk + j*24;
                    #pragma unroll
                    for (int u = 0; u < 8; u++) {
                        u64 w = wp[u];
                        acc[u][0][0] = fma2(w, a00, acc[u][0][0]);
                        acc[u][0][1] = fma2(w, a01, acc[u][0][1]);
                        acc[u][1][0] = fma2(w, a10, acc[u][1][0]);
                        acc[u][1][1] = fma2(w, a11, acc[u][1][1]);
                    }
                }
            }
        }
        #pragma unroll
        for (int i2 = 0; i2 < 2; i2++) {
            float inv = (i2 == 0) ? 1.f : 0.5f;
            #pragma unroll
            for (int u = 0; u < 8; u++) {
                int gco = cbase + co0 + u;
                float bias0 = g_bias4[(i2*2 + 0)*96 + gco];
                float bias1 = g_bias4[(i2*2 + 1)*96 + gco];
                float2 p0 = up2(acc[u][i2][0]), p1 = up2(acc[u][i2][1]);
                float vx = fmaxf(fmaxf(p0.x + bias0, p1.x + bias1), 0.f)*inv;
                float vy = fmaxf(fmaxf(p0.y + bias0, p1.y + bias1), 0.f)*inv;
                s[u] += vx + vy;
                q[u] += vx*vx + vy*vy;
                *reinterpret_cast<float2*>(&g_a4T[(size_t)(gco*3 + i2)*NB + b]) = make_float2(vx, vy);
            }
        }
    } else {
        // ii = 2, s = 4
        u64 acc[8][2];
        #pragma unroll
        for (int u = 0; u < 8; u++) { acc[u][0] = 0ull; acc[u][1] = 0ull; }
        for (int c = 0; c < 48; c++) {
            #pragma unroll
            for (int r = 0; r < 3; r++) {
                const float* pb = &g_a3[(size_t)((c*5 + 2 + r)*3)*NB + b];
                const u64* wk = &wd4[(c*9 + r*3)*24 + co0];
                #pragma unroll
                for (int j = 0; j < 3; j++) {
                    int x0 = (j-1)*4;
                    u64 a0 = (x0   >= 0 && x0   < 3) ? ld2(pb + (size_t)(x0  )*NB) : 0ull;
                    u64 a1 = (x0+1 >= 0 && x0+1 < 3) ? ld2(pb + (size_t)(x0+1)*NB) : 0ull;
                    const u64* wp = wk + j*24;
                    #pragma unroll
                    for (int u = 0; u < 8; u++) {
                        u64 w = wp[u];
                        acc[u][0] = fma2(w, a0, acc[u][0]);
                        acc[u][1] = fma2(w, a1, acc[u][1]);
                    }
                }
            }
        }
        #pragma unroll
        for (int u = 0; u < 8; u++) {
            int gco = cbase + co0 + u;
            float bias0 = g_bias4[(2*2 + 0)*96 + gco];
            float bias1 = g_bias4[(2*2 + 1)*96 + gco];
            float2 p0 = up2(acc[u][0]), p1 = up2(acc[u][1]);
            float vx = fmaxf(fmaxf(p0.x + bias0, p1.x + bias1), 0.f)*0.25f;
            float vy = fmaxf(fmaxf(p0.y + bias0, p1.y + bias1), 0.f)*0.25f;
            s[u] += vx + vy;
            q[u] += vx*vx + vy*vy;
            *reinterpret_cast<float2*>(&g_a4T[(size_t)(gco*3 + 2)*NB + b]) = make_float2(vx, vy);
        }
    }
    #pragma unroll
    for (int u = 0; u < 8; u++) {
        #pragma unroll
        for (int o = 16; o; o >>= 1) {
            s[u] += __shfl_down_sync(0xffffffffu, s[u], o);
            q[u] += __shfl_down_sync(0xffffffffu, q[u], o);
        }
    }
    if (lane == 0) {
        #pragma unroll
        for (int u = 0; u < 8; u++) { atomicAdd(&ssum[co0+u], s[u]); atomicAdd(&ssq[co0+u], q[u]); }
    }
    __syncthreads();
    if (tid < 24) {
        atomicAdd(&g_stats[168+cbase+tid], (double)ssum[tid]);
        atomicAdd(&g_stats[264+cbase+tid], (double)ssq[tid]);
    }
}

// ---------------- Phase 5a: bn4 affine + collapse 3 FCs into (6x288) + bias ----------------
__global__ __launch_bounds__(256) void k_phase5a(const float* __restrict__ g4, const float* __restrict__ b4,
                                                 const float* __restrict__ f1w, const float* __restrict__ f1b,
                                                 const float* __restrict__ f2w, const float* __restrict__ f2b,
                                                 const float* __restrict__ f3w, const float* __restrict__ f3b) {
    __shared__ float A4[96], B4[96], W23[576], bcs[6];
    int tid = threadIdx.x;
    if (tid < 96) {
        double m = g_stats[168+tid] / 12288.0;
        double v = g_stats[264+tid] / 12288.0 - m*m;
        float a = g4[tid] * rsqrtf((float)v + EPSF);
        A4[tid] = a; B4[tid] = b4[tid] - (float)m*a;
    }
    if (tid < 6) bcs[tid] = 0.f;
    for (int idx = tid; idx < 576; idx += 256) {
        int j = idx / 96, k = idx % 96;
        float s = 0.f;
        for (int l = 0; l < 48; l++) s += f3w[j*48 + l] * f2w[l*96 + k];
        W23[idx] = s;
    }
    __syncthreads();
    for (int idx = tid; idx < 1728; idx += 256) {
        int j = idx / 288, i = idx % 288;
        int c = i / 3;
        float s0 = 0.f;
        for (int k = 0; k < 96; k++) s0 += W23[j*96 + k] * f1w[k*288 + i];
        g_Wc[idx] = s0 * A4[c];
        atomicAdd(&bcs[j], s0 * B4[c]);
    }
    __syncthreads();
    if (tid < 6) {
        int j = tid;
        float bb = f3b[j];
        for (int l = 0; l < 48; l++) bb += f3w[j*48 + l] * f2b[l];
        for (int k = 0; k < 96; k++) bb += W23[j*96 + k] * f1b[k];
        g_bc[j] = bcs[j] + bb;
    }
}

// ---------------- Phase 5b: out[b][6] from a4T planes, 4 samples/thread ----------------
__global__ __launch_bounds__(256) void k_phase5b(float* __restrict__ out) {
    __shared__ float Wcs[1728];
    for (int i = threadIdx.x; i < 1728; i += 256) Wcs[i] = g_Wc[i];
    __syncthreads();
    int b = (blockIdx.x*256 + threadIdx.x)*4;
    float acc[6][4];
    #pragma unroll
    for (int j = 0; j < 6; j++)
        #pragma unroll
        for (int m = 0; m < 4; m++) acc[j][m] = g_bc[j];
    for (int f = 0; f < 288; f++) {
        float4 v = *reinterpret_cast<const float4*>(&g_a4T[(size_t)f*NB + b]);
        #pragma unroll
        for (int j = 0; j < 6; j++) {
            float w = Wcs[j*288 + f];
            acc[j][0] += v.x*w; acc[j][1] += v.y*w; acc[j][2] += v.z*w; acc[j][3] += v.w*w;
        }
    }
    #pragma unroll
    for (int m = 0; m < 4; m++)
        #pragma unroll
        for (int j = 0; j < 6; j++)
            out[(b+m)*6 + j] = acc[j][m];
}

// ---------------- launcher ----------------
extern "C" void kernel_launch(void* const* d_in, const int* in_sizes, int n_in,
                              void* d_out, int out_size) {
    const float* x   = (const float*)d_in[0];
    const float* w1  = (const float*)d_in[1];
    const float* w2  = (const float*)d_in[2];
    const float* w3  = (const float*)d_in[3];
    const float* w4  = (const float*)d_in[4];
    const float* g1  = (const float*)d_in[5];
    const float* b1  = (const float*)d_in[6];
    const float* g2  = (const float*)d_in[7];
    const float* b2  = (const float*)d_in[8];
    const float* g3  = (const float*)d_in[9];
    const float* b3  = (const float*)d_in[10];
    const float* g4  = (const float*)d_in[11];
    const float* b4  = (const float*)d_in[12];
    const float* f1w = (const float*)d_in[13];
    const float* f1b = (const float*)d_in[14];
    const float* f2w = (const float*)d_in[15];
    const float* f2b = (const float*)d_in[16];
    const float* f3w = (const float*)d_in[17];
    const float* f3b = (const float*)d_in[18];
    float* out = (float*)d_out;

    static const int SM3 = 8640 * 8;
    static const int SM4 = 10368 * 8;
    cudaFuncSetAttribute(k_p3, cudaFuncAttributeMaxDynamicSharedMemorySize, SM3);
    cudaFuncSetAttribute(k_p4, cudaFuncAttributeMaxDynamicSharedMemorySize, SM4);

    k_zero<<<1, 384>>>();
    k_tr<<<dim3(128, 19), dim3(32, 8)>>>(x);
    k_p1<<<dim3(64, 8), 256>>>(w1);
    k_bias2<<<17, 256>>>(w2, g1, b1);
    k_p2<<<dim3(64, 4), 256>>>(w2, g1);
    k_bias3<<<6, 256>>>(w3, g2, b2);
    k_p3<<<dim3(64, 4), 256, SM3>>>(w3, g2);
    k_bias4<<<3, 256>>>(w4, g3, b3);
    k_p4<<<dim3(64, 4), 192, SM4>>>(w4, g3);
    k_phase5a<<<1, 256>>>(g4, b4, f1w, f1b, f2w, f2b, f3w, f3b);
    k_phase5b<<<4, 256>>>(out);
}

// round 7
// speedup vs baseline: 1.0813x; 1.0813x over previous
#include <cuda_runtime.h>

#define EPSF 2e-5f
#define NB 4096

typedef unsigned long long u64;

__device__ __forceinline__ u64 ld2(const float* p) {
    return *reinterpret_cast<const u64*>(p);
}
__device__ __forceinline__ u64 fma2(u64 a, u64 b, u64 c) {
    u64 d;
    asm("fma.rn.f32x2 %0, %1, %2, %3;" : "=l"(d) : "l"(a), "l"(b), "l"(c));
    return d;
}
__device__ __forceinline__ float2 up2(u64 v) {
    float2 r;
    asm("mov.b64 {%0,%1}, %2;" : "=f"(r.x), "=f"(r.y) : "l"(v));
    return r;
}
__device__ __forceinline__ u64 dupw(float w) {
    u64 d;
    asm("mov.b64 %0, {%1,%1};" : "=l"(d) : "f"(w));
    return d;
}

// ---------------- scratch planes, [feature][batch] ----------------
__device__ __align__(16) float  g_xT [600*NB];   // [(t*6+c)][b]
__device__ __align__(16) float  g_m1 [2700*NB];  // (12,9,25) max-pooled relu'd lift (2x pooled)
__device__ __align__(16) float  g_m2 [1008*NB];  // (24,7,6)  2x pooled relu'd conv2
__device__ __align__(16) float  g_a3 [720*NB];   // (48,5,3)  relu'd pooled conv3
__device__ __align__(16) float  g_a4T[288*NB];   // (96,3)    relu'd pooled conv4
__device__ double g_stats[360];   // s1:0 q1:12 s2:24 q2:48 s3:72 q3:120 s4:168 q4:264
__device__ float  g_bias2[4200];  // [ii(7)][x(25)][co(24)]
__device__ float  g_bias3[1440];  // [ii(5)][x(6)][co(48)]
__device__ float  g_bias4[576];   // [ii(3)][x(2)][co(96)]
__device__ float  g_Wc[6*288];
__device__ float  g_bc[6];

__global__ void k_zero() {
    int t = threadIdx.x;
    if (t < 360) g_stats[t] = 0.0;
}

// ---------------- transpose x (4096,600) -> xT (600,4096) ----------------
__global__ void k_tr(const float* __restrict__ x) {
    __shared__ float tile[32][33];
    int bx = blockIdx.x * 32;
    int fy = blockIdx.y * 32;
    int tx = threadIdx.x, ty = threadIdx.y;
    #pragma unroll
    for (int m = 0; m < 4; m++) {
        int ff = fy + tx;
        tile[ty + m*8][tx] = (ff < 600) ? x[(bx + ty + m*8)*600 + ff] : 0.f;
    }
    __syncthreads();
    #pragma unroll
    for (int m = 0; m < 4; m++) {
        int ff = fy + ty + m*8;
        if (ff < 600) g_xT[ff*NB + bx + tx] = tile[tx][ty + m*8];
    }
}

// ---------------- Phase 1: lift conv + pool(relu) + pool(max) + stats ----------------
// co-tile 6 (2 cogs); task t: cog=t&1, r=t>>1, hh=r/25, op=r%25.
__global__ __launch_bounds__(128) void k_p1(const float* __restrict__ w1) {
    __shared__ u64 wd[504];           // [(c*7+j)*12 + co]
    __shared__ float ssum[12], ssq[12];
    int tid = threadIdx.x, lane = tid & 31, wid = tid >> 5;
    int b = blockIdx.x * 64 + lane * 2;
    for (int i = tid; i < 504; i += 128) { int co = i/42, k = i%42; wd[k*12+co] = dupw(w1[i]); }
    if (tid < 12) { ssum[tid] = 0.f; ssq[tid] = 0.f; }
    __syncthreads();
    int gw = blockIdx.y * 4 + wid;    // 0..31
    int cog = gw & 1;
    int co0 = cog * 6;
    float s[6], q[6];
    #pragma unroll
    for (int u = 0; u < 6; u++) { s[u] = 0.f; q[u] = 0.f; }
    for (int t = gw; t < 450; t += 32) {
        int r = t >> 1;
        int hh = r / 25, op = r % 25;
        int sc = 1 << hh, px = 4*op;
        u64 acc[6][4];
        #pragma unroll
        for (int u = 0; u < 6; u++)
            #pragma unroll
            for (int d = 0; d < 4; d++) acc[u][d] = 0ull;
        for (int c = 0; c < 6; c++) {
            const float* pc = &g_xT[(size_t)c*NB + b];
            #pragma unroll
            for (int j = 0; j < 7; j++) {
                int t0 = px + (j-3)*sc;
                u64 a0 = (t0   >= 0 && t0   < 100) ? ld2(pc + (size_t)(t0  )*6*NB) : 0ull;
                u64 a1 = (t0+1 >= 0 && t0+1 < 100) ? ld2(pc + (size_t)(t0+1)*6*NB) : 0ull;
                u64 a2 = (t0+2 >= 0 && t0+2 < 100) ? ld2(pc + (size_t)(t0+2)*6*NB) : 0ull;
                u64 a3 = (t0+3 >= 0 && t0+3 < 100) ? ld2(pc + (size_t)(t0+3)*6*NB) : 0ull;
                const u64* wp = &wd[(c*7 + j)*12 + co0];
                #pragma unroll
                for (int u = 0; u < 6; u++) {
                    u64 w = wp[u];
                    acc[u][0] = fma2(w, a0, acc[u][0]);
                    acc[u][1] = fma2(w, a1, acc[u][1]);
                    acc[u][2] = fma2(w, a2, acc[u][2]);
                    acc[u][3] = fma2(w, a3, acc[u][3]);
                }
            }
        }
        float inv = 1.f/(float)sc;
        #pragma unroll
        for (int u = 0; u < 6; u++) {
            float2 p0 = up2(acc[u][0]), p1 = up2(acc[u][1]);
            float2 p2 = up2(acc[u][2]), p3 = up2(acc[u][3]);
            float v0x = fmaxf(fmaxf(p0.x, p1.x), 0.f)*inv;
            float v0y = fmaxf(fmaxf(p0.y, p1.y), 0.f)*inv;
            float v1x = fmaxf(fmaxf(p2.x, p3.x), 0.f)*inv;
            float v1y = fmaxf(fmaxf(p2.y, p3.y), 0.f)*inv;
            s[u] += v0x + v0y + v1x + v1y;
            q[u] += v0x*v0x + v0y*v0y + v1x*v1x + v1y*v1y;
            *reinterpret_cast<float2*>(&g_m1[(size_t)(((co0+u)*9+hh)*25 + op)*NB + b]) =
                make_float2(fmaxf(v0x, v1x), fmaxf(v0y, v1y));
        }
    }
    #pragma unroll
    for (int u = 0; u < 6; u++) {
        #pragma unroll
        for (int o = 16; o; o >>= 1) {
            s[u] += __shfl_down_sync(0xffffffffu, s[u], o);
            q[u] += __shfl_down_sync(0xffffffffu, q[u], o);
        }
    }
    if (lane == 0) {
        #pragma unroll
        for (int u = 0; u < 6; u++) { atomicAdd(&ssum[co0+u], s[u]); atomicAdd(&ssq[co0+u], q[u]); }
    }
    __syncthreads();
    if (tid < 12) {
        atomicAdd(&g_stats[tid],    (double)ssum[tid]);
        atomicAdd(&g_stats[12+tid], (double)ssq[tid]);
    }
}

// ---------------- bias precompute (two-stage factorized) ----------------
__global__ __launch_bounds__(256) void k_bias2(const float* __restrict__ w2,
                                               const float* __restrict__ g1,
                                               const float* __restrict__ b1) {
    __shared__ float Bc[12], V[24*5];
    int tid = threadIdx.x;
    if (tid < 12) {
        double m = g_stats[tid] / 1843200.0;
        double v = g_stats[12+tid] / 1843200.0 - m*m;
        float a = g1[tid] * rsqrtf((float)v + EPSF);
        Bc[tid] = b1[tid] - (float)m*a;
    }
    __syncthreads();
    for (int idx = tid; idx < 120; idx += 256) {
        int co = idx / 5, j = idx % 5;
        float acc = 0.f;
        for (int c = 0; c < 12; c++) {
            float bc = Bc[c];
            for (int r = 0; r < 3; r++) acc += w2[co*180 + c*15 + r*5 + j] * bc;
        }
        V[idx] = acc;
    }
    __syncthreads();
    for (int idx = tid; idx < 4200; idx += 256) {
        int ii = idx / 600, rem = idx % 600, x = rem / 24, co = rem % 24;
        int sc = 1 << ii;
        float a = 0.f;
        #pragma unroll
        for (int j = 0; j < 5; j++) {
            int x0 = x + (j-2)*sc;
            if (x0 >= 0 && x0 < 25) a += V[co*5 + j];
        }
        g_bias2[idx] = a;
    }
}

__global__ __launch_bounds__(256) void k_bias3(const float* __restrict__ w3,
                                               const float* __restrict__ g2,
                                               const float* __restrict__ b2) {
    __shared__ float Bc[24], V[48*5];
    int tid = threadIdx.x;
    if (tid < 24) {
        double m = g_stats[24+tid] / 344064.0;
        double v = g_stats[48+tid] / 344064.0 - m*m;
        float a = g2[tid] * rsqrtf((float)v + EPSF);
        Bc[tid] = b2[tid] - (float)m*a;
    }
    __syncthreads();
    for (int idx = tid; idx < 240; idx += 256) {
        int co = idx / 5, j = idx % 5;
        float acc = 0.f;
        for (int c = 0; c < 24; c++) {
            float bc = Bc[c];
            for (int r = 0; r < 3; r++) acc += w3[co*360 + c*15 + r*5 + j] * bc;
        }
        V[idx] = acc;
    }
    __syncthreads();
    for (int idx = tid; idx < 1440; idx += 256) {
        int ii = idx / 288, rem = idx % 288, x = rem / 48, co = rem % 48;
        int sc = 1 << ii;
        float a = 0.f;
        #pragma unroll
        for (int j = 0; j < 5; j++) {
            int x0 = x + (j-2)*sc;
            if (x0 >= 0 && x0 < 6) a += V[co*5 + j];
        }
        g_bias3[idx] = a;
    }
}

__global__ __launch_bounds__(256) void k_bias4(const float* __restrict__ w4,
                                               const float* __restrict__ g3,
                                               const float* __restrict__ b3) {
    __shared__ float Bc[48], V[96*3];
    int tid = threadIdx.x;
    if (tid < 48) {
        double m = g_stats[72+tid] / 61440.0;
        double v = g_stats[120+tid] / 61440.0 - m*m;
        float a = g3[tid] * rsqrtf((float)v + EPSF);
        Bc[tid] = b3[tid] - (float)m*a;
    }
    __syncthreads();
    for (int idx = tid; idx < 288; idx += 256) {
        int co = idx / 3, j = idx % 3;
        float acc = 0.f;
        for (int c = 0; c < 48; c++) {
            float bc = Bc[c];
            for (int r = 0; r < 3; r++) acc += w4[co*432 + c*9 + r*3 + j] * bc;
        }
        V[idx] = acc;
    }
    __syncthreads();
    for (int idx = tid; idx < 576; idx += 256) {
        int ii = idx / 192, rem = idx % 192, x = rem / 96, co = rem % 96;
        int sc = 1 << ii;
        float a = 0.f;
        #pragma unroll
        for (int j = 0; j < 3; j++) {
            int x0 = x + (j-1)*sc;
            if (x0 >= 0 && x0 < 3) a += V[co*3 + j];
        }
        g_bias4[idx] = a;
    }
}

// ---------------- Phase 2: gg_conv w2 (bn1 folded) + pool + stats ----------------
// co-tile 8 (3 cogs); task t: cog=t%3, pos=t/3, ii=pos/6, op=pos%6. 126 tasks, stride 24.
__global__ __launch_bounds__(128) void k_p2(const float* __restrict__ w2,
                                            const float* __restrict__ g1) {
    __shared__ u64 wd[4320];          // [(c*15+r*5+j)*24 + co], scaled by A1[c]
    __shared__ float A1[12];
    __shared__ float ssum[24], ssq[24];
    int tid = threadIdx.x, lane = tid & 31, wid = tid >> 5;
    int b = blockIdx.x * 64 + lane * 2;
    if (tid < 12) {
        double m = g_stats[tid] / 1843200.0;
        double v = g_stats[12+tid] / 1843200.0 - m*m;
        A1[tid] = g1[tid] * rsqrtf((float)v + EPSF);
    }
    if (tid < 24) { ssum[tid] = 0.f; ssq[tid] = 0.f; }
    __syncthreads();
    for (int i = tid; i < 4320; i += 128) {
        int co = i/180, k = i%180, c = k/15;
        wd[k*24+co] = dupw(w2[i] * A1[c]);
    }
    __syncthreads();
    int gw = blockIdx.y * 4 + wid;    // 0..23
    int cog = gw % 3;
    int co0 = cog * 8;
    float s[8], q[8];
    #pragma unroll
    for (int u = 0; u < 8; u++) { s[u] = 0.f; q[u] = 0.f; }
    for (int t = gw; t < 126; t += 24) {
        int pos = t / 3;
        int ii = pos / 6, op = pos % 6;
        int sc = 1 << ii, px = 4*op;
        u64 acc[8][4];
        #pragma unroll
        for (int u = 0; u < 8; u++)
            #pragma unroll
            for (int d = 0; d < 4; d++) acc[u][d] = 0ull;
        for (int c = 0; c < 12; c++) {
            #pragma unroll
            for (int r = 0; r < 3; r++) {
                const float* pb = &g_m1[(size_t)((c*9 + ii + r)*25)*NB + b];
                const u64* wk = &wd[(c*15 + r*5)*24 + co0];
                #pragma unroll
                for (int j = 0; j < 5; j++) {
                    int x0 = px + (j-2)*sc;
                    u64 a0 = (x0   >= 0 && x0   < 25) ? ld2(pb + (size_t)(x0  )*NB) : 0ull;
                    u64 a1 = (x0+1 >= 0 && x0+1 < 25) ? ld2(pb + (size_t)(x0+1)*NB) : 0ull;
                    u64 a2 = (x0+2 >= 0 && x0+2 < 25) ? ld2(pb + (size_t)(x0+2)*NB) : 0ull;
                    u64 a3 = (x0+3 >= 0 && x0+3 < 25) ? ld2(pb + (size_t)(x0+3)*NB) : 0ull;
                    const u64* wp = wk + j*24;
                    #pragma unroll
                    for (int u = 0; u < 8; u++) {
                        u64 w = wp[u];
                        acc[u][0] = fma2(w, a0, acc[u][0]);
                        acc[u][1] = fma2(w, a1, acc[u][1]);
                        acc[u][2] = fma2(w, a2, acc[u][2]);
                        acc[u][3] = fma2(w, a3, acc[u][3]);
                    }
                }
            }
        }
        float inv = 1.f/(float)sc;
        #pragma unroll
        for (int u = 0; u < 8; u++) {
            float bias0 = g_bias2[(ii*25 + px    )*24 + co0 + u];
            float bias1 = g_bias2[(ii*25 + px + 1)*24 + co0 + u];
            float bias2v= g_bias2[(ii*25 + px + 2)*24 + co0 + u];
            float bias3v= g_bias2[(ii*25 + px + 3)*24 + co0 + u];
            float2 p0 = up2(acc[u][0]), p1 = up2(acc[u][1]);
            float2 p2 = up2(acc[u][2]), p3 = up2(acc[u][3]);
            float v0x = fmaxf(fmaxf(p0.x + bias0, p1.x + bias1), 0.f)*inv;
            float v0y = fmaxf(fmaxf(p0.y + bias0, p1.y + bias1), 0.f)*inv;
            float v1x = fmaxf(fmaxf(p2.x + bias2v, p3.x + bias3v), 0.f)*inv;
            float v1y = fmaxf(fmaxf(p2.y + bias2v, p3.y + bias3v), 0.f)*inv;
            s[u] += v0x + v0y + v1x + v1y;
            q[u] += v0x*v0x + v0y*v0y + v1x*v1x + v1y*v1y;
            *reinterpret_cast<float2*>(&g_m2[(size_t)(((co0+u)*7+ii)*6 + op)*NB + b]) =
                make_float2(fmaxf(v0x, v1x), fmaxf(v0y, v1y));
        }
    }
    #pragma unroll
    for (int u = 0; u < 8; u++) {
        #pragma unroll
        for (int o = 16; o; o >>= 1) {
            s[u] += __shfl_down_sync(0xffffffffu, s[u], o);
            q[u] += __shfl_down_sync(0xffffffffu, q[u], o);
        }
    }
    if (lane == 0) {
        #pragma unroll
        for (int u = 0; u < 8; u++) { atomicAdd(&ssum[co0+u], s[u]); atomicAdd(&ssq[co0+u], q[u]); }
    }
    __syncthreads();
    if (tid < 24) {
        atomicAdd(&g_stats[24+tid], (double)ssum[tid]);
        atomicAdd(&g_stats[48+tid], (double)ssq[tid]);
    }
}

// ---------------- Phase 3: gg_conv w3 (bn2 folded) + pool + stats ----------------
// blockIdx.y in 0..5: half = y/3 (24 of 48 cos), tg = y%3. co-tile 8 (3 cogs per half).
// task t: cog=t%3, un=t/3 (0..9), ii=un>>1, kind=un&1. 30 tasks, stride 12.
__global__ __launch_bounds__(128) void k_p3(const float* __restrict__ w3,
                                            const float* __restrict__ g2) {
    extern __shared__ u64 wd3[];        // 8640: [(c*15+r*5+j)*24 + u], scaled by A2[c]
    __shared__ float A2[24];
    __shared__ float ssum[24], ssq[24];
    int tid = threadIdx.x, lane = tid & 31, wid = tid >> 5;
    int b = blockIdx.x * 64 + lane * 2;
    int half = blockIdx.y / 3;
    int tg   = blockIdx.y % 3;
    int cbase = half * 24;
    if (tid < 24) {
        double m = g_stats[24+tid] / 344064.0;
        double v = g_stats[48+tid] / 344064.0 - m*m;
        A2[tid] = g2[tid] * rsqrtf((float)v + EPSF);
        ssum[tid] = 0.f; ssq[tid] = 0.f;
    }
    __syncthreads();
    for (int i = tid; i < 8640; i += 128) {
        int u = i/360, k = i%360, c = k/15;
        wd3[k*24+u] = dupw(w3[(cbase+u)*360 + k] * A2[c]);
    }
    __syncthreads();
    int gw = tg * 4 + wid;    // 0..11
    int cog = gw % 3;
    int co0 = cog * 8;
    float s[8], q[8];
    #pragma unroll
    for (int u = 0; u < 8; u++) { s[u] = 0.f; q[u] = 0.f; }
    for (int t = gw; t < 30; t += 12) {
        int un = t / 3;
        int ii = un >> 1, kind = un & 1;
        int sc = 1 << ii;
        float inv = 1.f/(float)sc;
        if (kind == 0) {
            // pooled ox 0,1 from pre-pool x 0..3
            u64 acc[8][4];
            #pragma unroll
            for (int u = 0; u < 8; u++)
                #pragma unroll
                for (int d = 0; d < 4; d++) acc[u][d] = 0ull;
            for (int c = 0; c < 24; c++) {
                #pragma unroll
                for (int r = 0; r < 3; r++) {
                    const float* pb = &g_m2[(size_t)((c*7 + ii + r)*6)*NB + b];
                    const u64* wk = &wd3[(c*15 + r*5)*24 + co0];
                    #pragma unroll
                    for (int j = 0; j < 5; j++) {
                        int x0 = (j-2)*sc;
                        u64 a0 = (x0   >= 0 && x0   < 6) ? ld2(pb + (size_t)(x0  )*NB) : 0ull;
                        u64 a1 = (x0+1 >= 0 && x0+1 < 6) ? ld2(pb + (size_t)(x0+1)*NB) : 0ull;
                        u64 a2 = (x0+2 >= 0 && x0+2 < 6) ? ld2(pb + (size_t)(x0+2)*NB) : 0ull;
                        u64 a3 = (x0+3 >= 0 && x0+3 < 6) ? ld2(pb + (size_t)(x0+3)*NB) : 0ull;
                        const u64* wp = wk + j*24;
                        #pragma unroll
                        for (int u = 0; u < 8; u++) {
                            u64 w = wp[u];
                            acc[u][0] = fma2(w, a0, acc[u][0]);
                            acc[u][1] = fma2(w, a1, acc[u][1]);
                            acc[u][2] = fma2(w, a2, acc[u][2]);
                            acc[u][3] = fma2(w, a3, acc[u][3]);
                        }
                    }
                }
            }
            #pragma unroll
            for (int u = 0; u < 8; u++) {
                int gco = cbase + co0 + u;
                float bias0 = g_bias3[(ii*6 + 0)*48 + gco];
                float bias1 = g_bias3[(ii*6 + 1)*48 + gco];
                float bias2v= g_bias3[(ii*6 + 2)*48 + gco];
                float bias3v= g_bias3[(ii*6 + 3)*48 + gco];
                float2 p0 = up2(acc[u][0]), p1 = up2(acc[u][1]);
                float2 p2 = up2(acc[u][2]), p3 = up2(acc[u][3]);
                float v0x = fmaxf(fmaxf(p0.x + bias0, p1.x + bias1), 0.f)*inv;
                float v0y = fmaxf(fmaxf(p0.y + bias0, p1.y + bias1), 0.f)*inv;
                float v1x = fmaxf(fmaxf(p2.x + bias2v, p3.x + bias3v), 0.f)*inv;
                float v1y = fmaxf(fmaxf(p2.y + bias2v, p3.y + bias3v), 0.f)*inv;
                s[u] += v0x + v0y + v1x + v1y;
                q[u] += v0x*v0x + v0y*v0y + v1x*v1x + v1y*v1y;
                *reinterpret_cast<float2*>(&g_a3[(size_t)(gco*15 + ii*3 + 0)*NB + b]) = make_float2(v0x, v0y);
                *reinterpret_cast<float2*>(&g_a3[(size_t)(gco*15 + ii*3 + 1)*NB + b]) = make_float2(v1x, v1y);
            }
        } else {
            // pooled ox 2 from pre-pool x 4,5
            u64 acc[8][2];
            #pragma unroll
            for (int u = 0; u < 8; u++) { acc[u][0] = 0ull; acc[u][1] = 0ull; }
            for (int c = 0; c < 24; c++) {
                #pragma unroll
                for (int r = 0; r < 3; r++) {
                    const float* pb = &g_m2[(size_t)((c*7 + ii + r)*6)*NB + b];
                    const u64* wk = &wd3[(c*15 + r*5)*24 + co0];
                    #pragma unroll
                    for (int j = 0; j < 5; j++) {
                        int x0 = 4 + (j-2)*sc;
                        u64 a0 = (x0   >= 0 && x0   < 6) ? ld2(pb + (size_t)(x0  )*NB) : 0ull;
                        u64 a1 = (x0+1 >= 0 && x0+1 < 6) ? ld2(pb + (size_t)(x0+1)*NB) : 0ull;
                        const u64* wp = wk + j*24;
                        #pragma unroll
                        for (int u = 0; u < 8; u++) {
                            u64 w = wp[u];
                            acc[u][0] = fma2(w, a0, acc[u][0]);
                            acc[u][1] = fma2(w, a1, acc[u][1]);
                        }
                    }
                }
            }
            #pragma unroll
            for (int u = 0; u < 8; u++) {
                int gco = cbase + co0 + u;
                float bias0 = g_bias3[(ii*6 + 4)*48 + gco];
                float bias1 = g_bias3[(ii*6 + 5)*48 + gco];
                float2 p0 = up2(acc[u][0]), p1 = up2(acc[u][1]);
                float vx = fmaxf(fmaxf(p0.x + bias0, p1.x + bias1), 0.f)*inv;
                float vy = fmaxf(fmaxf(p0.y + bias0, p1.y + bias1), 0.f)*inv;
                s[u] += vx + vy;
                q[u] += vx*vx + vy*vy;
                *reinterpret_cast<float2*>(&g_a3[(size_t)(gco*15 + ii*3 + 2)*NB + b]) = make_float2(vx, vy);
            }
        }
    }
    #pragma unroll
    for (int u = 0; u < 8; u++) {
        #pragma unroll
        for (int o = 16; o; o >>= 1) {
            s[u] += __shfl_down_sync(0xffffffffu, s[u], o);
            q[u] += __shfl_down_sync(0xffffffffu, q[u], o);
        }
    }
    if (lane == 0) {
        #pragma unroll
        for (int u = 0; u < 8; u++) { atomicAdd(&ssum[co0+u], s[u]); atomicAdd(&ssq[co0+u], q[u]); }
    }
    __syncthreads();
    if (tid < 24) {
        atomicAdd(&g_stats[72+cbase+tid],  (double)ssum[tid]);
        atomicAdd(&g_stats[120+cbase+tid], (double)ssq[tid]);
    }
}

// ---------------- Phase 4: gg_conv w4 (bn3 folded) + pool + stats ----------------
// blockIdx.y: 24 cos each. 6 warps: cog(3: co-tile 8) x unit(2: ii-pair{0,1} / ii-single{2})
__global__ __launch_bounds__(192) void k_p4(const float* __restrict__ w4,
                                            const float* __restrict__ g3) {
    extern __shared__ u64 wd4[];        // 10368: [(c*9+r*3+j)*24 + u], scaled by A3[c]
    __shared__ float A3[48];
    __shared__ float ssum[24], ssq[24];
    int tid = threadIdx.x, lane = tid & 31, wid = tid >> 5;
    int b = blockIdx.x * 64 + lane * 2;
    int cbase = blockIdx.y * 24;
    if (tid < 48) {
        double m = g_stats[72+tid] / 61440.0;
        double v = g_stats[120+tid] / 61440.0 - m*m;
        A3[tid] = g3[tid] * rsqrtf((float)v + EPSF);
    }
    if (tid < 24) { ssum[tid] = 0.f; ssq[tid] = 0.f; }
    __syncthreads();
    for (int i = tid; i < 10368; i += 192) {
        int u = i/432, k = i%432, c = k/9;
        wd4[k*24+u] = dupw(w4[(cbase+u)*432 + k] * A3[c]);
    }
    __syncthreads();
    int cog = wid >> 1;     // 0..2
    int unit = wid & 1;
    int co0 = cog * 8;
    float s[8], q[8];
    #pragma unroll
    for (int u = 0; u < 8; u++) { s[u] = 0.f; q[u] = 0.f; }
    if (unit == 0) {
        // ii = 0 and 1, sharing weight loads
        u64 acc[8][2][2];
        #pragma unroll
        for (int u = 0; u < 8; u++)
            #pragma unroll
            for (int i2 = 0; i2 < 2; i2++) { acc[u][i2][0] = 0ull; acc[u][i2][1] = 0ull; }
        for (int c = 0; c < 48; c++) {
            #pragma unroll
            for (int r = 0; r < 3; r++) {
                const float* pb0 = &g_a3[(size_t)((c*5 + 0 + r)*3)*NB + b];
                const float* pb1 = &g_a3[(size_t)((c*5 + 1 + r)*3)*NB + b];
                const u64* wk = &wd4[(c*9 + r*3)*24 + co0];
                #pragma unroll
                for (int j = 0; j < 3; j++) {
                    int x0a = (j-1);        // ii=0, s=1
                    int x0b = (j-1)*2;      // ii=1, s=2
                    u64 a00 = (x0a   >= 0 && x0a   < 3) ? ld2(pb0 + (size_t)(x0a  )*NB) : 0ull;
                    u64 a01 = (x0a+1 >= 0 && x0a+1 < 3) ? ld2(pb0 + (size_t)(x0a+1)*NB) : 0ull;
                    u64 a10 = (x0b   >= 0 && x0b   < 3) ? ld2(pb1 + (size_t)(x0b  )*NB) : 0ull;
                    u64 a11 = (x0b+1 >= 0 && x0b+1 < 3) ? ld2(pb1 + (size_t)(x0b+1)*NB) : 0ull;
                    const u64* wp = wk + j*24;
                    #pragma unroll
                    for (int u = 0; u < 8; u++) {
                        u64 w = wp[u];
                        acc[u][0][0] = fma2(w, a00, acc[u][0][0]);
                        acc[u][0][1] = fma2(w, a01, acc[u][0][1]);
                        acc[u][1][0] = fma2(w, a10, acc[u][1][0]);
                        acc[u][1][1] = fma2(w, a11, acc[u][1][1]);
                    }
                }
            }
        }
        #pragma unroll
        for (int i2 = 0; i2 < 2; i2++) {
            float inv = (i2 == 0) ? 1.f : 0.5f;
            #pragma unroll
            for (int u = 0; u < 8; u++) {
                int gco = cbase + co0 + u;
                float bias0 = g_bias4[(i2*2 + 0)*96 + gco];
                float bias1 = g_bias4[(i2*2 + 1)*96 + gco];
                float2 p0 = up2(acc[u][i2][0]), p1 = up2(acc[u][i2][1]);
                float vx = fmaxf(fmaxf(p0.x + bias0, p1.x + bias1), 0.f)*inv;
                float vy = fmaxf(fmaxf(p0.y + bias0, p1.y + bias1), 0.f)*inv;
                s[u] += vx + vy;
                q[u] += vx*vx + vy*vy;
                *reinterpret_cast<float2*>(&g_a4T[(size_t)(gco*3 + i2)*NB + b]) = make_float2(vx, vy);
            }
        }
    } else {
        // ii = 2, s = 4
        u64 acc[8][2];
        #pragma unroll
        for (int u = 0; u < 8; u++) { acc[u][0] = 0ull; acc[u][1] = 0ull; }
        for (int c = 0; c < 48; c++) {
            #pragma unroll
            for (int r = 0; r < 3; r++) {
                const float* pb = &g_a3[(size_t)((c*5 + 2 + r)*3)*NB + b];
                const u64* wk = &wd4[(c*9 + r*3)*24 + co0];
                #pragma unroll
                for (int j = 0; j < 3; j++) {
                    int x0 = (j-1)*4;
                    u64 a0 = (x0   >= 0 && x0   < 3) ? ld2(pb + (size_t)(x0  )*NB) : 0ull;
                    u64 a1 = (x0+1 >= 0 && x0+1 < 3) ? ld2(pb + (size_t)(x0+1)*NB) : 0ull;
                    const u64* wp = wk + j*24;
                    #pragma unroll
                    for (int u = 0; u < 8; u++) {
                        u64 w = wp[u];
                        acc[u][0] = fma2(w, a0, acc[u][0]);
                        acc[u][1] = fma2(w, a1, acc[u][1]);
                    }
                }
            }
        }
        #pragma unroll
        for (int u = 0; u < 8; u++) {
            int gco = cbase + co0 + u;
            float bias0 = g_bias4[(2*2 + 0)*96 + gco];
            float bias1 = g_bias4[(2*2 + 1)*96 + gco];
            float2 p0 = up2(acc[u][0]), p1 = up2(acc[u][1]);
            float vx = fmaxf(fmaxf(p0.x + bias0, p1.x + bias1), 0.f)*0.25f;
            float vy = fmaxf(fmaxf(p0.y + bias0, p1.y + bias1), 0.f)*0.25f;
            s[u] += vx + vy;
            q[u] += vx*vx + vy*vy;
            *reinterpret_cast<float2*>(&g_a4T[(size_t)(gco*3 + 2)*NB + b]) = make_float2(vx, vy);
        }
    }
    #pragma unroll
    for (int u = 0; u < 8; u++) {
        #pragma unroll
        for (int o = 16; o; o >>= 1) {
            s[u] += __shfl_down_sync(0xffffffffu, s[u], o);
            q[u] += __shfl_down_sync(0xffffffffu, q[u], o);
        }
    }
    if (lane == 0) {
        #pragma unroll
        for (int u = 0; u < 8; u++) { atomicAdd(&ssum[co0+u], s[u]); atomicAdd(&ssq[co0+u], q[u]); }
    }
    __syncthreads();
    if (tid < 24) {
        atomicAdd(&g_stats[168+cbase+tid], (double)ssum[tid]);
        atomicAdd(&g_stats[264+cbase+tid], (double)ssq[tid]);
    }
}

// ---------------- Phase 5a: bn4 affine + collapse 3 FCs into (6x288) + bias ----------------
__global__ __launch_bounds__(256) void k_phase5a(const float* __restrict__ g4, const float* __restrict__ b4,
                                                 const float* __restrict__ f1w, const float* __restrict__ f1b,
                                                 const float* __restrict__ f2w, const float* __restrict__ f2b,
                                                 const float* __restrict__ f3w, const float* __restrict__ f3b) {
    __shared__ float A4[96], B4[96], W23[576], bcs[6];
    int tid = threadIdx.x;
    if (tid < 96) {
        double m = g_stats[168+tid] / 12288.0;
        double v = g_stats[264+tid] / 12288.0 - m*m;
        float a = g4[tid] * rsqrtf((float)v + EPSF);
        A4[tid] = a; B4[tid] = b4[tid] - (float)m*a;
    }
    if (tid < 6) bcs[tid] = 0.f;
    for (int idx = tid; idx < 576; idx += 256) {
        int j = idx / 96, k = idx % 96;
        float s = 0.f;
        for (int l = 0; l < 48; l++) s += f3w[j*48 + l] * f2w[l*96 + k];
        W23[idx] = s;
    }
    __syncthreads();
    for (int idx = tid; idx < 1728; idx += 256) {
        int j = idx / 288, i = idx % 288;
        int c = i / 3;
        float s0 = 0.f;
        for (int k = 0; k < 96; k++) s0 += W23[j*96 + k] * f1w[k*288 + i];
        g_Wc[idx] = s0 * A4[c];
        atomicAdd(&bcs[j], s0 * B4[c]);
    }
    __syncthreads();
    if (tid < 6) {
        int j = tid;
        float bb = f3b[j];
        for (int l = 0; l < 48; l++) bb += f3w[j*48 + l] * f2b[l];
        for (int k = 0; k < 96; k++) bb += W23[j*96 + k] * f1b[k];
        g_bc[j] = bcs[j] + bb;
    }
}

// ---------------- Phase 5b: out[b][6] from a4T planes, 4 samples/thread ----------------
__global__ __launch_bounds__(256) void k_phase5b(float* __restrict__ out) {
    __shared__ float Wcs[1728];
    for (int i = threadIdx.x; i < 1728; i += 256) Wcs[i] = g_Wc[i];
    __syncthreads();
    int b = (blockIdx.x*256 + threadIdx.x)*4;
    float acc[6][4];
    #pragma unroll
    for (int j = 0; j < 6; j++)
        #pragma unroll
        for (int m = 0; m < 4; m++) acc[j][m] = g_bc[j];
    for (int f = 0; f < 288; f++) {
        float4 v = *reinterpret_cast<const float4*>(&g_a4T[(size_t)f*NB + b]);
        #pragma unroll
        for (int j = 0; j < 6; j++) {
            float w = Wcs[j*288 + f];
            acc[j][0] += v.x*w; acc[j][1] += v.y*w; acc[j][2] += v.z*w; acc[j][3] += v.w*w;
        }
    }
    #pragma unroll
    for (int m = 0; m < 4; m++)
        #pragma unroll
        for (int j = 0; j < 6; j++)
            out[(b+m)*6 + j] = acc[j][m];
}

// ---------------- launcher ----------------
extern "C" void kernel_launch(void* const* d_in, const int* in_sizes, int n_in,
                              void* d_out, int out_size) {
    const float* x   = (const float*)d_in[0];
    const float* w1  = (const float*)d_in[1];
    const float* w2  = (const float*)d_in[2];
    const float* w3  = (const float*)d_in[3];
    const float* w4  = (const float*)d_in[4];
    const float* g1  = (const float*)d_in[5];
    const float* b1  = (const float*)d_in[6];
    const float* g2  = (const float*)d_in[7];
    const float* b2  = (const float*)d_in[8];
    const float* g3  = (const float*)d_in[9];
    const float* b3  = (const float*)d_in[10];
    const float* g4  = (const float*)d_in[11];
    const float* b4  = (const float*)d_in[12];
    const float* f1w = (const float*)d_in[13];
    const float* f1b = (const float*)d_in[14];
    const float* f2w = (const float*)d_in[15];
    const float* f2b = (const float*)d_in[16];
    const float* f3w = (const float*)d_in[17];
    const float* f3b = (const float*)d_in[18];
    float* out = (float*)d_out;

    static const int SM3 = 8640 * 8;
    static const int SM4 = 10368 * 8;
    cudaFuncSetAttribute(k_p3, cudaFuncAttributeMaxDynamicSharedMemorySize, SM3);
    cudaFuncSetAttribute(k_p4, cudaFuncAttributeMaxDynamicSharedMemorySize, SM4);

    k_zero<<<1, 384>>>();
    k_tr<<<dim3(128, 19), dim3(32, 8)>>>(x);
    k_p1<<<dim3(64, 8), 128>>>(w1);
    k_bias2<<<1, 256>>>(w2, g1, b1);
    k_p2<<<dim3(64, 6), 128>>>(w2, g1);
    k_bias3<<<1, 256>>>(w3, g2, b2);
    k_p3<<<dim3(64, 6), 128, SM3>>>(w3, g2);
    k_bias4<<<1, 256>>>(w4, g3, b3);
    k_p4<<<dim3(64, 4), 192, SM4>>>(w4, g3);
    k_phase5a<<<1, 256>>>(g4, b4, f1w, f1b, f2w, f2b, f3w, f3b);
    k_phase5b<<<4, 256>>>(out);
}

// round 8
// speedup vs baseline: 1.1306x; 1.0456x over previous
#include <cuda_runtime.h>

#define EPSF 2e-5f
#define NB 4096

typedef unsigned long long u64;

__device__ __forceinline__ u64 ld2(const float* p) {
    return *reinterpret_cast<const u64*>(p);
}
__device__ __forceinline__ u64 fma2(u64 a, u64 b, u64 c) {
    u64 d;
    asm("fma.rn.f32x2 %0, %1, %2, %3;" : "=l"(d) : "l"(a), "l"(b), "l"(c));
    return d;
}
__device__ __forceinline__ float2 up2(u64 v) {
    float2 r;
    asm("mov.b64 {%0,%1}, %2;" : "=f"(r.x), "=f"(r.y) : "l"(v));
    return r;
}
__device__ __forceinline__ u64 dupw(float w) {
    u64 d;
    asm("mov.b64 %0, {%1,%1};" : "=l"(d) : "f"(w));
    return d;
}

// ---------------- scratch planes, [feature][batch] ----------------
__device__ __align__(16) float  g_xT [600*NB];   // [(t*6+c)][b]
__device__ __align__(16) float  g_m1 [2700*NB];  // (12,9,25) double-pooled relu'd lift (pre-bn)
__device__ __align__(16) float  g_m2 [1008*NB];  // (24,7,6)  double-pooled relu'd conv2 (pre-bn)
__device__ __align__(16) float  g_a3 [720*NB];   // (48,5,3)  pooled relu'd conv3 (pre-bn)
__device__ __align__(16) float  g_a4T[288*NB];   // (96,3)    pooled relu'd conv4 (pre-bn)
__device__ double g_stats[360];   // s1:0 q1:12 s2:24 q2:48 s3:72 q3:120 s4:168 q4:264
__device__ float  g_Wc[6*288];
__device__ float  g_bc[6];

__global__ void k_zero() {
    int t = threadIdx.x;
    if (t < 360) g_stats[t] = 0.0;
}

// ---------------- transpose x (4096,600) -> xT (600,4096) ----------------
__global__ void k_tr(const float* __restrict__ x) {
    __shared__ float tile[32][33];
    int bx = blockIdx.x * 32;
    int fy = blockIdx.y * 32;
    int tx = threadIdx.x, ty = threadIdx.y;
    #pragma unroll
    for (int m = 0; m < 4; m++) {
        int ff = fy + tx;
        tile[ty + m*8][tx] = (ff < 600) ? x[(bx + ty + m*8)*600 + ff] : 0.f;
    }
    __syncthreads();
    #pragma unroll
    for (int m = 0; m < 4; m++) {
        int ff = fy + ty + m*8;
        if (ff < 600) g_xT[ff*NB + bx + tx] = tile[tx][ty + m*8];
    }
}

// ---------------- Phase 1: lift conv + pool(relu,stats) + pool(max) ----------------
// task t in 0..224: hh=t/25, op=t%25. Two sequential passes (2 positions each),
// acc registers reused across passes (unroll 1).
__global__ __launch_bounds__(128) void k_p1(const float* __restrict__ w1) {
    __shared__ u64 wd[504];           // [(c*7+j)*12 + co]
    __shared__ float ssum[12], ssq[12];
    int tid = threadIdx.x, lane = tid & 31, wid = tid >> 5;
    int b = blockIdx.x * 64 + lane * 2;
    for (int i = tid; i < 504; i += 128) { int co = i/42, k = i%42; wd[k*12+co] = dupw(w1[i]); }
    if (tid < 12) { ssum[tid] = 0.f; ssq[tid] = 0.f; }
    __syncthreads();
    float s[12], q[12];
    #pragma unroll
    for (int u = 0; u < 12; u++) { s[u] = 0.f; q[u] = 0.f; }
    for (int t = blockIdx.y*4 + wid; t < 225; t += 32) {
        int hh = t / 25, op = t % 25;
        int sc = 1 << hh;
        float inv = 1.f/(float)sc;
        float2 vprev[12];
        #pragma unroll 1
        for (int pass = 0; pass < 2; pass++) {
            int px = 4*op + 2*pass;
            u64 acc[12][2];
            #pragma unroll
            for (int u = 0; u < 12; u++) { acc[u][0] = 0ull; acc[u][1] = 0ull; }
            for (int c = 0; c < 6; c++) {
                const float* pc = &g_xT[(size_t)c*NB + b];
                #pragma unroll
                for (int j = 0; j < 7; j++) {
                    int t0 = px + (j-3)*sc;
                    u64 a0 = (t0   >= 0 && t0   < 100) ? ld2(pc + (size_t)(t0  )*6*NB) : 0ull;
                    u64 a1 = (t0+1 >= 0 && t0+1 < 100) ? ld2(pc + (size_t)(t0+1)*6*NB) : 0ull;
                    const u64* wp = &wd[(c*7 + j)*12];
                    #pragma unroll
                    for (int u = 0; u < 12; u++) {
                        u64 w = wp[u];
                        acc[u][0] = fma2(w, a0, acc[u][0]);
                        acc[u][1] = fma2(w, a1, acc[u][1]);
                    }
                }
            }
            #pragma unroll
            for (int u = 0; u < 12; u++) {
                float2 p0 = up2(acc[u][0]), p1 = up2(acc[u][1]);
                float vx = fmaxf(fmaxf(p0.x, p1.x), 0.f)*inv;
                float vy = fmaxf(fmaxf(p0.y, p1.y), 0.f)*inv;
                s[u] += vx + vy;
                q[u] += vx*vx + vy*vy;
                if (pass == 0) {
                    vprev[u] = make_float2(vx, vy);
                } else {
                    *reinterpret_cast<float2*>(&g_m1[(size_t)((u*9+hh)*25 + op)*NB + b]) =
                        make_float2(fmaxf(vprev[u].x, vx), fmaxf(vprev[u].y, vy));
                }
            }
        }
    }
    #pragma unroll
    for (int u = 0; u < 12; u++) {
        #pragma unroll
        for (int o = 16; o; o >>= 1) {
            s[u] += __shfl_down_sync(0xffffffffu, s[u], o);
            q[u] += __shfl_down_sync(0xffffffffu, q[u], o);
        }
    }
    if (lane == 0) {
        #pragma unroll
        for (int u = 0; u < 12; u++) { atomicAdd(&ssum[u], s[u]); atomicAdd(&ssq[u], q[u]); }
    }
    __syncthreads();
    if (tid < 12) {
        atomicAdd(&g_stats[tid],    (double)ssum[tid]);
        atomicAdd(&g_stats[12+tid], (double)ssq[tid]);
    }
}

// ---------------- Phase 2: gg_conv w2 (bn1 folded, bias fused) + pool(stats) + pool ----------------
// cog = gw&1 (co-tile 12); quads (ii 0..6, op 0..5): two sequential passes.
__global__ __launch_bounds__(128) void k_p2(const float* __restrict__ w2,
                                            const float* __restrict__ g1,
                                            const float* __restrict__ b1) {
    __shared__ u64 wd[4320];          // [(c*15+r*5+j)*24 + co], scaled by A1[c]
    __shared__ float A1[12], Bc[12], V[120];   // V[co*5+j]
    __shared__ float ssum[24], ssq[24];
    int tid = threadIdx.x, lane = tid & 31, wid = tid >> 5;
    int b = blockIdx.x * 64 + lane * 2;
    if (tid < 12) {
        double m = g_stats[tid] / 1843200.0;
        double v = g_stats[12+tid] / 1843200.0 - m*m;
        float a = g1[tid] * rsqrtf((float)v + EPSF);
        A1[tid] = a;
        Bc[tid] = b1[tid] - (float)m*a;
    }
    if (tid < 24) { ssum[tid] = 0.f; ssq[tid] = 0.f; }
    __syncthreads();
    for (int i = tid; i < 4320; i += 128) {
        int co = i/180, k = i%180, c = k/15;
        wd[k*24+co] = dupw(w2[i] * A1[c]);
    }
    for (int i = tid; i < 120; i += 128) {
        int co = i / 5, j = i % 5;
        float acc = 0.f;
        for (int c = 0; c < 12; c++) {
            float bc = Bc[c];
            for (int r = 0; r < 3; r++) acc += w2[co*180 + c*15 + r*5 + j] * bc;
        }
        V[i] = acc;
    }
    __syncthreads();
    int gw = blockIdx.y * 4 + wid;    // 0..23
    int cog = gw & 1;
    int co0 = cog * 12;
    float s[12], q[12];
    #pragma unroll
    for (int u = 0; u < 12; u++) { s[u] = 0.f; q[u] = 0.f; }
    for (int t = gw >> 1; t < 42; t += 12) {
        int ii = t / 6, op = t % 6;
        int sc = 1 << ii;
        float inv = 1.f/(float)sc;
        float2 vprev[12];
        #pragma unroll 1
        for (int pass = 0; pass < 2; pass++) {
            int px = 4*op + 2*pass;
            u64 acc[12][2];
            #pragma unroll
            for (int u = 0; u < 12; u++) { acc[u][0] = 0ull; acc[u][1] = 0ull; }
            for (int c = 0; c < 12; c++) {
                #pragma unroll
                for (int r = 0; r < 3; r++) {
                    const float* pb = &g_m1[(size_t)((c*9 + ii + r)*25)*NB + b];
                    const u64* wk = &wd[(c*15 + r*5)*24 + co0];
                    #pragma unroll
                    for (int j = 0; j < 5; j++) {
                        int x0 = px + (j-2)*sc;
                        u64 a0 = (x0   >= 0 && x0   < 25) ? ld2(pb + (size_t)(x0  )*NB) : 0ull;
                        u64 a1 = (x0+1 >= 0 && x0+1 < 25) ? ld2(pb + (size_t)(x0+1)*NB) : 0ull;
                        const u64* wp = wk + j*24;
                        #pragma unroll
                        for (int u = 0; u < 12; u++) {
                            u64 w = wp[u];
                            acc[u][0] = fma2(w, a0, acc[u][0]);
                            acc[u][1] = fma2(w, a1, acc[u][1]);
                        }
                    }
                }
            }
            #pragma unroll
            for (int u = 0; u < 12; u++) {
                float bias0 = 0.f, bias1 = 0.f;
                #pragma unroll
                for (int j = 0; j < 5; j++) {
                    int x0 = px + (j-2)*sc;
                    float vj = V[(co0+u)*5 + j];
                    if (x0   >= 0 && x0   < 25) bias0 += vj;
                    if (x0+1 >= 0 && x0+1 < 25) bias1 += vj;
                }
                float2 p0 = up2(acc[u][0]), p1 = up2(acc[u][1]);
                float vx = fmaxf(fmaxf(p0.x + bias0, p1.x + bias1), 0.f)*inv;
                float vy = fmaxf(fmaxf(p0.y + bias0, p1.y + bias1), 0.f)*inv;
                s[u] += vx + vy;
                q[u] += vx*vx + vy*vy;
                if (pass == 0) {
                    vprev[u] = make_float2(vx, vy);
                } else {
                    *reinterpret_cast<float2*>(&g_m2[(size_t)(((co0+u)*7+ii)*6 + op)*NB + b]) =
                        make_float2(fmaxf(vprev[u].x, vx), fmaxf(vprev[u].y, vy));
                }
            }
        }
    }
    #pragma unroll
    for (int u = 0; u < 12; u++) {
        #pragma unroll
        for (int o = 16; o; o >>= 1) {
            s[u] += __shfl_down_sync(0xffffffffu, s[u], o);
            q[u] += __shfl_down_sync(0xffffffffu, q[u], o);
        }
    }
    if (lane == 0) {
        #pragma unroll
        for (int u = 0; u < 12; u++) { atomicAdd(&ssum[co0+u], s[u]); atomicAdd(&ssq[co0+u], q[u]); }
    }
    __syncthreads();
    if (tid < 24) {
        atomicAdd(&g_stats[24+tid], (double)ssum[tid]);
        atomicAdd(&g_stats[48+tid], (double)ssq[tid]);
    }
}

// ---------------- Phase 3: gg_conv w3 (bn2 folded, bias fused) + pool(relu,stats) ----------------
// blockIdx.y: half = y/3 (24 of 48 cos), tg = y%3. cog = gw&1 (co-tile 12).
// tasks (ii 0..4, pr 0..2): single pair, stored directly (no pooled-2).
__global__ __launch_bounds__(128) void k_p3(const float* __restrict__ w3,
                                            const float* __restrict__ g2,
                                            const float* __restrict__ b2) {
    extern __shared__ u64 wd3[];        // 8640: [(c*15+r*5+j)*24 + u], scaled by A2[c]
    __shared__ float A2[24], Bc[24], V[120];  // V[u*5+j] for this half's 24 cos
    __shared__ float ssum[24], ssq[24];
    int tid = threadIdx.x, lane = tid & 31, wid = tid >> 5;
    int b = blockIdx.x * 64 + lane * 2;
    int half = blockIdx.y / 3;
    int tg   = blockIdx.y % 3;
    int cbase = half * 24;
    if (tid < 24) {
        double m = g_stats[24+tid] / 344064.0;
        double v = g_stats[48+tid] / 344064.0 - m*m;
        float a = g2[tid] * rsqrtf((float)v + EPSF);
        A2[tid] = a;
        Bc[tid] = b2[tid] - (float)m*a;
        ssum[tid] = 0.f; ssq[tid] = 0.f;
    }
    __syncthreads();
    for (int i = tid; i < 8640; i += 128) {
        int u = i/360, k = i%360, c = k/15;
        wd3[k*24+u] = dupw(w3[(cbase+u)*360 + k] * A2[c]);
    }
    for (int i = tid; i < 120; i += 128) {
        int u = i / 5, j = i % 5;
        float acc = 0.f;
        for (int c = 0; c < 24; c++) {
            float bc = Bc[c];
            for (int r = 0; r < 3; r++) acc += w3[(cbase+u)*360 + c*15 + r*5 + j] * bc;
        }
        V[i] = acc;
    }
    __syncthreads();
    int gw = tg * 4 + wid;    // 0..11
    int cog = gw & 1;
    int co0 = cog * 12;
    float s[12], q[12];
    #pragma unroll
    for (int u = 0; u < 12; u++) { s[u] = 0.f; q[u] = 0.f; }
    for (int t = gw >> 1; t < 15; t += 6) {
        int ii = t / 3, pr = t % 3;
        int sc = 1 << ii;
        float inv = 1.f/(float)sc;
        int px = 2*pr;
        u64 acc[12][2];
        #pragma unroll
        for (int u = 0; u < 12; u++) { acc[u][0] = 0ull; acc[u][1] = 0ull; }
        for (int c = 0; c < 24; c++) {
            #pragma unroll
            for (int r = 0; r < 3; r++) {
                const float* pb = &g_m2[(size_t)((c*7 + ii + r)*6)*NB + b];
                const u64* wk = &wd3[(c*15 + r*5)*24 + co0];
                #pragma unroll
                for (int j = 0; j < 5; j++) {
                    int x0 = px + (j-2)*sc;
                    u64 a0 = (x0   >= 0 && x0   < 6) ? ld2(pb + (size_t)(x0  )*NB) : 0ull;
                    u64 a1 = (x0+1 >= 0 && x0+1 < 6) ? ld2(pb + (size_t)(x0+1)*NB) : 0ull;
                    const u64* wp = wk + j*24;
                    #pragma unroll
                    for (int u = 0; u < 12; u++) {
                        u64 w = wp[u];
                        acc[u][0] = fma2(w, a0, acc[u][0]);
                        acc[u][1] = fma2(w, a1, acc[u][1]);
                    }
                }
            }
        }
        #pragma unroll
        for (int u = 0; u < 12; u++) {
            float bias0 = 0.f, bias1 = 0.f;
            #pragma unroll
            for (int j = 0; j < 5; j++) {
                int x0 = px + (j-2)*sc;
                float vj = V[(co0+u)*5 + j];
                if (x0   >= 0 && x0   < 6) bias0 += vj;
                if (x0+1 >= 0 && x0+1 < 6) bias1 += vj;
            }
            float2 p0 = up2(acc[u][0]), p1 = up2(acc[u][1]);
            float vx = fmaxf(fmaxf(p0.x + bias0, p1.x + bias1), 0.f)*inv;
            float vy = fmaxf(fmaxf(p0.y + bias0, p1.y + bias1), 0.f)*inv;
            s[u] += vx + vy;
            q[u] += vx*vx + vy*vy;
            *reinterpret_cast<float2*>(&g_a3[(size_t)((cbase+co0+u)*15 + ii*3 + pr)*NB + b]) =
                make_float2(vx, vy);
        }
    }
    #pragma unroll
    for (int u = 0; u < 12; u++) {
        #pragma unroll
        for (int o = 16; o; o >>= 1) {
            s[u] += __shfl_down_sync(0xffffffffu, s[u], o);
            q[u] += __shfl_down_sync(0xffffffffu, q[u], o);
        }
    }
    if (lane == 0) {
        #pragma unroll
        for (int u = 0; u < 12; u++) { atomicAdd(&ssum[co0+u], s[u]); atomicAdd(&ssq[co0+u], q[u]); }
    }
    __syncthreads();
    if (tid < 24) {
        atomicAdd(&g_stats[72+cbase+tid],  (double)ssum[tid]);
        atomicAdd(&g_stats[120+cbase+tid], (double)ssq[tid]);
    }
}

// ---------------- Phase 4: gg_conv w4 (bn3 folded, bias fused) + pool(relu,stats) ----------------
// blockIdx.y: 24 cos each. 6 warps: cog(3: co-tile 8) x unit(2: ii-pair{0,1} / ii-single{2})
__global__ __launch_bounds__(192) void k_p4(const float* __restrict__ w4,
                                            const float* __restrict__ g3,
                                            const float* __restrict__ b3) {
    extern __shared__ u64 wd4[];        // 10368: [(c*9+r*3+j)*24 + u], scaled by A3[c]
    __shared__ float A3[48], Bc[48], V[72];  // V[u*3+j]
    __shared__ float ssum[24], ssq[24];
    int tid = threadIdx.x, lane = tid & 31, wid = tid >> 5;
    int b = blockIdx.x * 64 + lane * 2;
    int cbase = blockIdx.y * 24;
    if (tid < 48) {
        double m = g_stats[72+tid] / 61440.0;
        double v = g_stats[120+tid] / 61440.0 - m*m;
        float a = g3[tid] * rsqrtf((float)v + EPSF);
        A3[tid] = a;
        Bc[tid] = b3[tid] - (float)m*a;
    }
    if (tid < 24) { ssum[tid] = 0.f; ssq[tid] = 0.f; }
    __syncthreads();
    for (int i = tid; i < 10368; i += 192) {
        int u = i/432, k = i%432, c = k/9;
        wd4[k*24+u] = dupw(w4[(cbase+u)*432 + k] * A3[c]);
    }
    for (int i = tid; i < 72; i += 192) {
        int u = i / 3, j = i % 3;
        float acc = 0.f;
        for (int c = 0; c < 48; c++) {
            float bc = Bc[c];
            for (int r = 0; r < 3; r++) acc += w4[(cbase+u)*432 + c*9 + r*3 + j] * bc;
        }
        V[i] = acc;
    }
    __syncthreads();
    int cog = wid >> 1;     // 0..2
    int unit = wid & 1;
    int co0 = cog * 8;
    float s[8], q[8];
    #pragma unroll
    for (int u = 0; u < 8; u++) { s[u] = 0.f; q[u] = 0.f; }
    if (unit == 0) {
        // ii = 0 and 1, sharing weight loads
        u64 acc[8][2][2];
        #pragma unroll
        for (int u = 0; u < 8; u++)
            #pragma unroll
            for (int i2 = 0; i2 < 2; i2++) { acc[u][i2][0] = 0ull; acc[u][i2][1] = 0ull; }
        for (int c = 0; c < 48; c++) {
            #pragma unroll
            for (int r = 0; r < 3; r++) {
                const float* pb0 = &g_a3[(size_t)((c*5 + 0 + r)*3)*NB + b];
                const float* pb1 = &g_a3[(size_t)((c*5 + 1 + r)*3)*NB + b];
                const u64* wk = &wd4[(c*9 + r*3)*24 + co0];
                #pragma unroll
                for (int j = 0; j < 3; j++) {
                    int x0a = (j-1);        // ii=0, s=1
                    int x0b = (j-1)*2;      // ii=1, s=2
                    u64 a00 = (x0a   >= 0 && x0a   < 3) ? ld2(pb0 + (size_t)(x0a  )*NB) : 0ull;
                    u64 a01 = (x0a+1 >= 0 && x0a+1 < 3) ? ld2(pb0 + (size_t)(x0a+1)*NB) : 0ull;
                    u64 a10 = (x0b   >= 0 && x0b   < 3) ? ld2(pb1 + (size_t)(x0b  )*NB) : 0ull;
                    u64 a11 = (x0b+1 >= 0 && x0b+1 < 3) ? ld2(pb1 + (size_t)(x0b+1)*NB) : 0ull;
                    const u64* wp = wk + j*24;
                    #pragma unroll
                    for (int u = 0; u < 8; u++) {
                        u64 w = wp[u];
                        acc[u][0][0] = fma2(w, a00, acc[u][0][0]);
                        acc[u][0][1] = fma2(w, a01, acc[u][0][1]);
                        acc[u][1][0] = fma2(w, a10, acc[u][1][0]);
                        acc[u][1][1] = fma2(w, a11, acc[u][1][1]);
                    }
                }
            }
        }
        #pragma unroll
        for (int i2 = 0; i2 < 2; i2++) {
            int sc = 1 << i2;
            float inv = (i2 == 0) ? 1.f : 0.5f;
            #pragma unroll
            for (int u = 0; u < 8; u++) {
                float bias0 = 0.f, bias1 = 0.f;
                #pragma unroll
                for (int j = 0; j < 3; j++) {
                    int x0 = (j-1)*sc;
                    float vj = V[(co0+u)*3 + j];
                    if (x0   >= 0 && x0   < 3) bias0 += vj;
                    if (x0+1 >= 0 && x0+1 < 3) bias1 += vj;
                }
                float2 p0 = up2(acc[u][i2][0]), p1 = up2(acc[u][i2][1]);
                float vx = fmaxf(fmaxf(p0.x + bias0, p1.x + bias1), 0.f)*inv;
                float vy = fmaxf(fmaxf(p0.y + bias0, p1.y + bias1), 0.f)*inv;
                s[u] += vx + vy;
                q[u] += vx*vx + vy*vy;
                *reinterpret_cast<float2*>(&g_a4T[(size_t)((cbase+co0+u)*3 + i2)*NB + b]) =
                    make_float2(vx, vy);
            }
        }
    } else {
        // ii = 2, s = 4
        u64 acc[8][2];
        #pragma unroll
        for (int u = 0; u < 8; u++) { acc[u][0] = 0ull; acc[u][1] = 0ull; }
        for (int c = 0; c < 48; c++) {
            #pragma unroll
            for (int r = 0; r < 3; r++) {
                const float* pb = &g_a3[(size_t)((c*5 + 2 + r)*3)*NB + b];
                const u64* wk = &wd4[(c*9 + r*3)*24 + co0];
                #pragma unroll
                for (int j = 0; j < 3; j++) {
                    int x0 = (j-1)*4;
                    u64 a0 = (x0   >= 0 && x0   < 3) ? ld2(pb + (size_t)(x0  )*NB) : 0ull;
                    u64 a1 = (x0+1 >= 0 && x0+1 < 3) ? ld2(pb + (size_t)(x0+1)*NB) : 0ull;
                    const u64* wp = wk + j*24;
                    #pragma unroll
                    for (int u = 0; u < 8; u++) {
                        u64 w = wp[u];
                        acc[u][0] = fma2(w, a0, acc[u][0]);
                        acc[u][1] = fma2(w, a1, acc[u][1]);
                    }
                }
            }
        }
        #pragma unroll
        for (int u = 0; u < 8; u++) {
            float bias0 = 0.f, bias1 = 0.f;
            #pragma unroll
            for (int j = 0; j < 3; j++) {
                int x0 = (j-1)*4;
                float vj = V[(co0+u)*3 + j];
                if (x0   >= 0 && x0   < 3) bias0 += vj;
                if (x0+1 >= 0 && x0+1 < 3) bias1 += vj;
            }
            float2 p0 = up2(acc[u][0]), p1 = up2(acc[u][1]);
            float vx = fmaxf(fmaxf(p0.x + bias0, p1.x + bias1), 0.f)*0.25f;
            float vy = fmaxf(fmaxf(p0.y + bias0, p1.y + bias1), 0.f)*0.25f;
            s[u] += vx + vy;
            q[u] += vx*vx + vy*vy;
            *reinterpret_cast<float2*>(&g_a4T[(size_t)((cbase+co0+u)*3 + 2)*NB + b]) =
                make_float2(vx, vy);
        }
    }
    #pragma unroll
    for (int u = 0; u < 8; u++) {
        #pragma unroll
        for (int o = 16; o; o >>= 1) {
            s[u] += __shfl_down_sync(0xffffffffu, s[u], o);
            q[u] += __shfl_down_sync(0xffffffffu, q[u], o);
        }
    }
    if (lane == 0) {
        #pragma unroll
        for (int u = 0; u < 8; u++) { atomicAdd(&ssum[co0+u], s[u]); atomicAdd(&ssq[co0+u], q[u]); }
    }
    __syncthreads();
    if (tid < 24) {
        atomicAdd(&g_stats[168+cbase+tid], (double)ssum[tid]);
        atomicAdd(&g_stats[264+cbase+tid], (double)ssq[tid]);
    }
}

// ---------------- Phase 5a: bn4 affine + collapse 3 FCs into (6x288) + bias ----------------
__global__ __launch_bounds__(256) void k_phase5a(const float* __restrict__ g4, const float* __restrict__ b4,
                                                 const float* __restrict__ f1w, const float* __restrict__ f1b,
                                                 const float* __restrict__ f2w, const float* __restrict__ f2b,
                                                 const float* __restrict__ f3w, const float* __restrict__ f3b) {
    __shared__ float A4[96], B4[96], W23[576], bcs[6];
    int tid = threadIdx.x;
    if (tid < 96) {
        double m = g_stats[168+tid] / 12288.0;
        double v = g_stats[264+tid] / 12288.0 - m*m;
        float a = g4[tid] * rsqrtf((float)v + EPSF);
        A4[tid] = a; B4[tid] = b4[tid] - (float)m*a;
    }
    if (tid < 6) bcs[tid] = 0.f;
    for (int idx = tid; idx < 576; idx += 256) {
        int j = idx / 96, k = idx % 96;
        float s = 0.f;
        for (int l = 0; l < 48; l++) s += f3w[j*48 + l] * f2w[l*96 + k];
        W23[idx] = s;
    }
    __syncthreads();
    for (int idx = tid; idx < 1728; idx += 256) {
        int j = idx / 288, i = idx % 288;
        int c = i / 3;
        float s0 = 0.f;
        for (int k = 0; k < 96; k++) s0 += W23[j*96 + k] * f1w[k*288 + i];
        g_Wc[idx] = s0 * A4[c];
        atomicAdd(&bcs[j], s0 * B4[c]);
    }
    __syncthreads();
    if (tid < 6) {
        int j = tid;
        float bb = f3b[j];
        for (int l = 0; l < 48; l++) bb += f3w[j*48 + l] * f2b[l];
        for (int k = 0; k < 96; k++) bb += W23[j*96 + k] * f1b[k];
        g_bc[j] = bcs[j] + bb;
    }
}

// ---------------- Phase 5b: out[b][6] from a4T planes, 4 samples/thread ----------------
__global__ __launch_bounds__(256) void k_phase5b(float* __restrict__ out) {
    __shared__ float Wcs[1728];
    for (int i = threadIdx.x; i < 1728; i += 256) Wcs[i] = g_Wc[i];
    __syncthreads();
    int b = (blockIdx.x*256 + threadIdx.x)*4;
    float acc[6][4];
    #pragma unroll
    for (int j = 0; j < 6; j++)
        #pragma unroll
        for (int m = 0; m < 4; m++) acc[j][m] = g_bc[j];
    for (int f = 0; f < 288; f++) {
        float4 v = *reinterpret_cast<const float4*>(&g_a4T[(size_t)f*NB + b]);
        #pragma unroll
        for (int j = 0; j < 6; j++) {
            float w = Wcs[j*288 + f];
            acc[j][0] += v.x*w; acc[j][1] += v.y*w; acc[j][2] += v.z*w; acc[j][3] += v.w*w;
        }
    }
    #pragma unroll
    for (int m = 0; m < 4; m++)
        #pragma unroll
        for (int j = 0; j < 6; j++)
            out[(b+m)*6 + j] = acc[j][m];
}

// ---------------- launcher ----------------
extern "C" void kernel_launch(void* const* d_in, const int* in_sizes, int n_in,
                              void* d_out, int out_size) {
    const float* x   = (const float*)d_in[0];
    const float* w1  = (const float*)d_in[1];
    const float* w2  = (const float*)d_in[2];
    const float* w3  = (const float*)d_in[3];
    const float* w4  = (const float*)d_in[4];
    const float* g1  = (const float*)d_in[5];
    const float* b1  = (const float*)d_in[6];
    const float* g2  = (const float*)d_in[7];
    const float* b2  = (const float*)d_in[8];
    const float* g3  = (const float*)d_in[9];
    const float* b3  = (const float*)d_in[10];
    const float* g4  = (const float*)d_in[11];
    const float* b4  = (const float*)d_in[12];
    const float* f1w = (const float*)d_in[13];
    const float* f1b = (const float*)d_in[14];
    const float* f2w = (const float*)d_in[15];
    const float* f2b = (const float*)d_in[16];
    const float* f3w = (const float*)d_in[17];
    const float* f3b = (const float*)d_in[18];
    float* out = (float*)d_out;

    static const int SM3 = 8640 * 8;
    static const int SM4 = 10368 * 8;
    cudaFuncSetAttribute(k_p3, cudaFuncAttributeMaxDynamicSharedMemorySize, SM3);
    cudaFuncSetAttribute(k_p4, cudaFuncAttributeMaxDynamicSharedMemorySize, SM4);

    // NOTE: launch order puts k_p2 4th — the profiler captures the 4th launch.
    k_zero<<<1, 384>>>();
    k_tr<<<dim3(128, 19), dim3(32, 8)>>>(x);
    k_p1<<<dim3(64, 8), 128>>>(w1);
    k_p2<<<dim3(64, 6), 128>>>(w2, g1, b1);
    k_p3<<<dim3(64, 6), 128, SM3>>>(w3, g2, b2);
    k_p4<<<dim3(64, 4), 192, SM4>>>(w4, g3, b3);
    k_phase5a<<<1, 256>>>(g4, b4, f1w, f1b, f2w, f2b, f3w, f3b);
    k_phase5b<<<4, 256>>>(out);
}

// round 9
// speedup vs baseline: 1.1400x; 1.0083x over previous
#include <cuda_runtime.h>

#define EPSF 2e-5f
#define NB 4096

typedef unsigned long long u64;

__device__ __forceinline__ u64 ld2(const float* p) {
    return *reinterpret_cast<const u64*>(p);
}
__device__ __forceinline__ u64 fma2(u64 a, u64 b, u64 c) {
    u64 d;
    asm("fma.rn.f32x2 %0, %1, %2, %3;" : "=l"(d) : "l"(a), "l"(b), "l"(c));
    return d;
}
__device__ __forceinline__ float2 up2(u64 v) {
    float2 r;
    asm("mov.b64 {%0,%1}, %2;" : "=f"(r.x), "=f"(r.y) : "l"(v));
    return r;
}
__device__ __forceinline__ u64 dupw(float w) {
    u64 d;
    asm("mov.b64 %0, {%1,%1};" : "=l"(d) : "f"(w));
    return d;
}

// ---------------- scratch planes, [feature][batch] ----------------
__device__ __align__(16) float  g_xT [600*NB];   // [(t*6+c)][b]
__device__ __align__(16) float  g_m1 [2700*NB];  // (12,9,25) double-pooled relu'd lift (pre-bn)
__device__ __align__(16) float  g_m2 [1008*NB];  // (24,7,6)  double-pooled relu'd conv2 (pre-bn)
__device__ __align__(16) float  g_a3 [720*NB];   // (48,5,3)  pooled relu'd conv3 (pre-bn)
__device__ __align__(16) float  g_a4T[288*NB];   // (96,3)    pooled relu'd conv4 (pre-bn)
__device__ double g_stats[360];   // s1:0 q1:12 s2:24 q2:48 s3:72 q3:120 s4:168 q4:264
__device__ float  g_Wc[6*288];
__device__ float  g_bc[6];

__global__ void k_zero() {
    int t = threadIdx.x;
    if (t < 360) g_stats[t] = 0.0;
}

// ---------------- transpose x (4096,600) -> xT (600,4096) ----------------
__global__ void k_tr(const float* __restrict__ x) {
    __shared__ float tile[32][33];
    int bx = blockIdx.x * 32;
    int fy = blockIdx.y * 32;
    int tx = threadIdx.x, ty = threadIdx.y;
    #pragma unroll
    for (int m = 0; m < 4; m++) {
        int ff = fy + tx;
        tile[ty + m*8][tx] = (ff < 600) ? x[(bx + ty + m*8)*600 + ff] : 0.f;
    }
    __syncthreads();
    #pragma unroll
    for (int m = 0; m < 4; m++) {
        int ff = fy + ty + m*8;
        if (ff < 600) g_xT[ff*NB + bx + tx] = tile[tx][ty + m*8];
    }
}

// ---------------- Phase 1: lift conv + pool(relu,stats) + pool(max) ----------------
// task t in 0..224: hh=t/25, op=t%25. Two sequential passes (2 positions each).
__global__ __launch_bounds__(128, 4) void k_p1(const float* __restrict__ w1) {
    __shared__ u64 wd[504];           // [(c*7+j)*12 + co]
    __shared__ float ssum[12], ssq[12];
    int tid = threadIdx.x, lane = tid & 31, wid = tid >> 5;
    int b = blockIdx.x * 64 + lane * 2;
    for (int i = tid; i < 504; i += 128) { int co = i/42, k = i%42; wd[k*12+co] = dupw(w1[i]); }
    if (tid < 12) { ssum[tid] = 0.f; ssq[tid] = 0.f; }
    __syncthreads();
    float s[12], q[12];
    #pragma unroll
    for (int u = 0; u < 12; u++) { s[u] = 0.f; q[u] = 0.f; }
    for (int t = blockIdx.y*4 + wid; t < 225; t += 60) {
        int hh = t / 25, op = t % 25;
        int sc = 1 << hh;
        float inv = 1.f/(float)sc;
        float2 vprev[12];
        #pragma unroll 1
        for (int pass = 0; pass < 2; pass++) {
            int px = 4*op + 2*pass;
            u64 acc[12][2];
            #pragma unroll
            for (int u = 0; u < 12; u++) { acc[u][0] = 0ull; acc[u][1] = 0ull; }
            for (int c = 0; c < 6; c++) {
                const float* pc = &g_xT[(size_t)c*NB + b];
                #pragma unroll
                for (int j = 0; j < 7; j++) {
                    int t0 = px + (j-3)*sc;
                    u64 a0 = (t0   >= 0 && t0   < 100) ? ld2(pc + (size_t)(t0  )*6*NB) : 0ull;
                    u64 a1 = (t0+1 >= 0 && t0+1 < 100) ? ld2(pc + (size_t)(t0+1)*6*NB) : 0ull;
                    const u64* wp = &wd[(c*7 + j)*12];
                    #pragma unroll
                    for (int u = 0; u < 12; u++) {
                        u64 w = wp[u];
                        acc[u][0] = fma2(w, a0, acc[u][0]);
                        acc[u][1] = fma2(w, a1, acc[u][1]);
                    }
                }
            }
            #pragma unroll
            for (int u = 0; u < 12; u++) {
                float2 p0 = up2(acc[u][0]), p1 = up2(acc[u][1]);
                float vx = fmaxf(fmaxf(p0.x, p1.x), 0.f)*inv;
                float vy = fmaxf(fmaxf(p0.y, p1.y), 0.f)*inv;
                s[u] += vx + vy;
                q[u] += vx*vx + vy*vy;
                if (pass == 0) {
                    vprev[u] = make_float2(vx, vy);
                } else {
                    *reinterpret_cast<float2*>(&g_m1[(size_t)((u*9+hh)*25 + op)*NB + b]) =
                        make_float2(fmaxf(vprev[u].x, vx), fmaxf(vprev[u].y, vy));
                }
            }
        }
    }
    #pragma unroll
    for (int u = 0; u < 12; u++) {
        #pragma unroll
        for (int o = 16; o; o >>= 1) {
            s[u] += __shfl_down_sync(0xffffffffu, s[u], o);
            q[u] += __shfl_down_sync(0xffffffffu, q[u], o);
        }
    }
    if (lane == 0) {
        #pragma unroll
        for (int u = 0; u < 12; u++) { atomicAdd(&ssum[u], s[u]); atomicAdd(&ssq[u], q[u]); }
    }
    __syncthreads();
    if (tid < 12) {
        atomicAdd(&g_stats[tid],    (double)ssum[tid]);
        atomicAdd(&g_stats[12+tid], (double)ssq[tid]);
    }
}

// ---------------- Phase 2: gg_conv w2 (bn1 folded, bias fused) + pool(stats) + pool ----------------
// gw = blockIdx.y*4+wid in 0..83: exactly one task. cog=gw&1 (co-tile 12),
// t=gw>>1: ii=t/6, op=t%6. Two sequential passes.
__global__ __launch_bounds__(128, 4) void k_p2(const float* __restrict__ w2,
                                               const float* __restrict__ g1,
                                               const float* __restrict__ b1) {
    __shared__ u64 wd[4320];          // [(c*15+r*5+j)*24 + co], scaled by A1[c]
    __shared__ float A1[12], Bc[12], V[120];   // V[co*5+j]
    __shared__ float ssum[24], ssq[24];
    int tid = threadIdx.x, lane = tid & 31, wid = tid >> 5;
    int b = blockIdx.x * 64 + lane * 2;
    if (tid < 12) {
        double m = g_stats[tid] / 1843200.0;
        double v = g_stats[12+tid] / 1843200.0 - m*m;
        float a = g1[tid] * rsqrtf((float)v + EPSF);
        A1[tid] = a;
        Bc[tid] = b1[tid] - (float)m*a;
    }
    if (tid < 24) { ssum[tid] = 0.f; ssq[tid] = 0.f; }
    __syncthreads();
    for (int i = tid; i < 4320; i += 128) {
        int co = i/180, k = i%180, c = k/15;
        wd[k*24+co] = dupw(w2[i] * A1[c]);
    }
    for (int i = tid; i < 120; i += 128) {
        int co = i / 5, j = i % 5;
        float acc = 0.f;
        for (int c = 0; c < 12; c++) {
            float bc = Bc[c];
            for (int r = 0; r < 3; r++) acc += w2[co*180 + c*15 + r*5 + j] * bc;
        }
        V[i] = acc;
    }
    __syncthreads();
    int gw = blockIdx.y * 4 + wid;    // 0..83
    int cog = gw & 1;
    int co0 = cog * 12;
    int t = gw >> 1;                  // 0..41
    int ii = t / 6, op = t % 6;
    int sc = 1 << ii;
    float inv = 1.f/(float)sc;
    float s[12], q[12];
    #pragma unroll
    for (int u = 0; u < 12; u++) { s[u] = 0.f; q[u] = 0.f; }
    float2 vprev[12];
    #pragma unroll 1
    for (int pass = 0; pass < 2; pass++) {
        int px = 4*op + 2*pass;
        u64 acc[12][2];
        #pragma unroll
        for (int u = 0; u < 12; u++) { acc[u][0] = 0ull; acc[u][1] = 0ull; }
        for (int c = 0; c < 12; c++) {
            #pragma unroll
            for (int r = 0; r < 3; r++) {
                const float* pb = &g_m1[(size_t)((c*9 + ii + r)*25)*NB + b];
                const u64* wk = &wd[(c*15 + r*5)*24 + co0];
                #pragma unroll
                for (int j = 0; j < 5; j++) {
                    int x0 = px + (j-2)*sc;
                    u64 a0 = (x0   >= 0 && x0   < 25) ? ld2(pb + (size_t)(x0  )*NB) : 0ull;
                    u64 a1 = (x0+1 >= 0 && x0+1 < 25) ? ld2(pb + (size_t)(x0+1)*NB) : 0ull;
                    const u64* wp = wk + j*24;
                    #pragma unroll
                    for (int u = 0; u < 12; u++) {
                        u64 w = wp[u];
                        acc[u][0] = fma2(w, a0, acc[u][0]);
                        acc[u][1] = fma2(w, a1, acc[u][1]);
                    }
                }
            }
        }
        #pragma unroll
        for (int u = 0; u < 12; u++) {
            float bias0 = 0.f, bias1 = 0.f;
            #pragma unroll
            for (int j = 0; j < 5; j++) {
                int x0 = px + (j-2)*sc;
                float vj = V[(co0+u)*5 + j];
                if (x0   >= 0 && x0   < 25) bias0 += vj;
                if (x0+1 >= 0 && x0+1 < 25) bias1 += vj;
            }
            float2 p0 = up2(acc[u][0]), p1 = up2(acc[u][1]);
            float vx = fmaxf(fmaxf(p0.x + bias0, p1.x + bias1), 0.f)*inv;
            float vy = fmaxf(fmaxf(p0.y + bias0, p1.y + bias1), 0.f)*inv;
            s[u] += vx + vy;
            q[u] += vx*vx + vy*vy;
            if (pass == 0) {
                vprev[u] = make_float2(vx, vy);
            } else {
                *reinterpret_cast<float2*>(&g_m2[(size_t)(((co0+u)*7+ii)*6 + op)*NB + b]) =
                    make_float2(fmaxf(vprev[u].x, vx), fmaxf(vprev[u].y, vy));
            }
        }
    }
    #pragma unroll
    for (int u = 0; u < 12; u++) {
        #pragma unroll
        for (int o = 16; o; o >>= 1) {
            s[u] += __shfl_down_sync(0xffffffffu, s[u], o);
            q[u] += __shfl_down_sync(0xffffffffu, q[u], o);
        }
    }
    if (lane == 0) {
        #pragma unroll
        for (int u = 0; u < 12; u++) { atomicAdd(&ssum[co0+u], s[u]); atomicAdd(&ssq[co0+u], q[u]); }
    }
    __syncthreads();
    if (tid < 24) {
        atomicAdd(&g_stats[24+tid], (double)ssum[tid]);
        atomicAdd(&g_stats[48+tid], (double)ssq[tid]);
    }
}

// ---------------- Phase 3: gg_conv w3 (bn2 folded, bias fused) + pool(relu,stats) ----------------
// blockIdx.y in 0..9: half = y/5 (24 of 48 cos), tg = y%5. gw = tg*4+wid in 0..19:
// cog = gw&1 (co-tile 12), tasks t = gw>>1; t < 15; t += 10.
__global__ __launch_bounds__(128, 3) void k_p3(const float* __restrict__ w3,
                                               const float* __restrict__ g2,
                                               const float* __restrict__ b2) {
    extern __shared__ u64 wd3[];        // 8640: [(c*15+r*5+j)*24 + u], scaled by A2[c]
    __shared__ float A2[24], Bc[24], V[120];  // V[u*5+j] for this half's 24 cos
    __shared__ float ssum[24], ssq[24];
    int tid = threadIdx.x, lane = tid & 31, wid = tid >> 5;
    int b = blockIdx.x * 64 + lane * 2;
    int half = blockIdx.y / 5;
    int tg   = blockIdx.y % 5;
    int cbase = half * 24;
    if (tid < 24) {
        double m = g_stats[24+tid] / 344064.0;
        double v = g_stats[48+tid] / 344064.0 - m*m;
        float a = g2[tid] * rsqrtf((float)v + EPSF);
        A2[tid] = a;
        Bc[tid] = b2[tid] - (float)m*a;
        ssum[tid] = 0.f; ssq[tid] = 0.f;
    }
    __syncthreads();
    for (int i = tid; i < 8640; i += 128) {
        int u = i/360, k = i%360, c = k/15;
        wd3[k*24+u] = dupw(w3[(cbase+u)*360 + k] * A2[c]);
    }
    for (int i = tid; i < 120; i += 128) {
        int u = i / 5, j = i % 5;
        float acc = 0.f;
        for (int c = 0; c < 24; c++) {
            float bc = Bc[c];
            for (int r = 0; r < 3; r++) acc += w3[(cbase+u)*360 + c*15 + r*5 + j] * bc;
        }
        V[i] = acc;
    }
    __syncthreads();
    int gw = tg * 4 + wid;    // 0..19
    int cog = gw & 1;
    int co0 = cog * 12;
    float s[12], q[12];
    #pragma unroll
    for (int u = 0; u < 12; u++) { s[u] = 0.f; q[u] = 0.f; }
    for (int t = gw >> 1; t < 15; t += 10) {
        int ii = t / 3, pr = t % 3;
        int sc = 1 << ii;
        float inv = 1.f/(float)sc;
        int px = 2*pr;
        u64 acc[12][2];
        #pragma unroll
        for (int u = 0; u < 12; u++) { acc[u][0] = 0ull; acc[u][1] = 0ull; }
        for (int c = 0; c < 24; c++) {
            #pragma unroll
            for (int r = 0; r < 3; r++) {
                const float* pb = &g_m2[(size_t)((c*7 + ii + r)*6)*NB + b];
                const u64* wk = &wd3[(c*15 + r*5)*24 + co0];
                #pragma unroll
                for (int j = 0; j < 5; j++) {
                    int x0 = px + (j-2)*sc;
                    u64 a0 = (x0   >= 0 && x0   < 6) ? ld2(pb + (size_t)(x0  )*NB) : 0ull;
                    u64 a1 = (x0+1 >= 0 && x0+1 < 6) ? ld2(pb + (size_t)(x0+1)*NB) : 0ull;
                    const u64* wp = wk + j*24;
                    #pragma unroll
                    for (int u = 0; u < 12; u++) {
                        u64 w = wp[u];
                        acc[u][0] = fma2(w, a0, acc[u][0]);
                        acc[u][1] = fma2(w, a1, acc[u][1]);
                    }
                }
            }
        }
        #pragma unroll
        for (int u = 0; u < 12; u++) {
            float bias0 = 0.f, bias1 = 0.f;
            #pragma unroll
            for (int j = 0; j < 5; j++) {
                int x0 = px + (j-2)*sc;
                float vj = V[(co0+u)*5 + j];
                if (x0   >= 0 && x0   < 6) bias0 += vj;
                if (x0+1 >= 0 && x0+1 < 6) bias1 += vj;
            }
            float2 p0 = up2(acc[u][0]), p1 = up2(acc[u][1]);
            float vx = fmaxf(fmaxf(p0.x + bias0, p1.x + bias1), 0.f)*inv;
            float vy = fmaxf(fmaxf(p0.y + bias0, p1.y + bias1), 0.f)*inv;
            s[u] += vx + vy;
            q[u] += vx*vx + vy*vy;
            *reinterpret_cast<float2*>(&g_a3[(size_t)((cbase+co0+u)*15 + ii*3 + pr)*NB + b]) =
                make_float2(vx, vy);
        }
    }
    #pragma unroll
    for (int u = 0; u < 12; u++) {
        #pragma unroll
        for (int o = 16; o; o >>= 1) {
            s[u] += __shfl_down_sync(0xffffffffu, s[u], o);
            q[u] += __shfl_down_sync(0xffffffffu, q[u], o);
        }
    }
    if (lane == 0) {
        #pragma unroll
        for (int u = 0; u < 12; u++) { atomicAdd(&ssum[co0+u], s[u]); atomicAdd(&ssq[co0+u], q[u]); }
    }
    __syncthreads();
    if (tid < 24) {
        atomicAdd(&g_stats[72+cbase+tid],  (double)ssum[tid]);
        atomicAdd(&g_stats[120+cbase+tid], (double)ssq[tid]);
    }
}

// ---------------- Phase 4: gg_conv w4 (bn3 folded, bias fused) + pool(relu,stats) ----------------
// blockIdx.y: 24 cos each. 6 warps: cog(3: co-tile 8) x unit(2: ii-pair{0,1} / ii-single{2})
__global__ __launch_bounds__(192, 2) void k_p4(const float* __restrict__ w4,
                                               const float* __restrict__ g3,
                                               const float* __restrict__ b3) {
    extern __shared__ u64 wd4[];        // 10368: [(c*9+r*3+j)*24 + u], scaled by A3[c]
    __shared__ float A3[48], Bc[48], V[72];  // V[u*3+j]
    __shared__ float ssum[24], ssq[24];
    int tid = threadIdx.x, lane = tid & 31, wid = tid >> 5;
    int b = blockIdx.x * 64 + lane * 2;
    int cbase = blockIdx.y * 24;
    if (tid < 48) {
        double m = g_stats[72+tid] / 61440.0;
        double v = g_stats[120+tid] / 61440.0 - m*m;
        float a = g3[tid] * rsqrtf((float)v + EPSF);
        A3[tid] = a;
        Bc[tid] = b3[tid] - (float)m*a;
    }
    if (tid < 24) { ssum[tid] = 0.f; ssq[tid] = 0.f; }
    __syncthreads();
    for (int i = tid; i < 10368; i += 192) {
        int u = i/432, k = i%432, c = k/9;
        wd4[k*24+u] = dupw(w4[(cbase+u)*432 + k] * A3[c]);
    }
    for (int i = tid; i < 72; i += 192) {
        int u = i / 3, j = i % 3;
        float acc = 0.f;
        for (int c = 0; c < 48; c++) {
            float bc = Bc[c];
            for (int r = 0; r < 3; r++) acc += w4[(cbase+u)*432 + c*9 + r*3 + j] * bc;
        }
        V[i] = acc;
    }
    __syncthreads();
    int cog = wid >> 1;     // 0..2
    int unit = wid & 1;
    int co0 = cog * 8;
    float s[8], q[8];
    #pragma unroll
    for (int u = 0; u < 8; u++) { s[u] = 0.f; q[u] = 0.f; }
    if (unit == 0) {
        // ii = 0 and 1, sharing weight loads
        u64 acc[8][2][2];
        #pragma unroll
        for (int u = 0; u < 8; u++)
            #pragma unroll
            for (int i2 = 0; i2 < 2; i2++) { acc[u][i2][0] = 0ull; acc[u][i2][1] = 0ull; }
        for (int c = 0; c < 48; c++) {
            #pragma unroll
            for (int r = 0; r < 3; r++) {
                const float* pb0 = &g_a3[(size_t)((c*5 + 0 + r)*3)*NB + b];
                const float* pb1 = &g_a3[(size_t)((c*5 + 1 + r)*3)*NB + b];
                const u64* wk = &wd4[(c*9 + r*3)*24 + co0];
                #pragma unroll
                for (int j = 0; j < 3; j++) {
                    int x0a = (j-1);        // ii=0, s=1
                    int x0b = (j-1)*2;      // ii=1, s=2
                    u64 a00 = (x0a   >= 0 && x0a   < 3) ? ld2(pb0 + (size_t)(x0a  )*NB) : 0ull;
                    u64 a01 = (x0a+1 >= 0 && x0a+1 < 3) ? ld2(pb0 + (size_t)(x0a+1)*NB) : 0ull;
                    u64 a10 = (x0b   >= 0 && x0b   < 3) ? ld2(pb1 + (size_t)(x0b  )*NB) : 0ull;
                    u64 a11 = (x0b+1 >= 0 && x0b+1 < 3) ? ld2(pb1 + (size_t)(x0b+1)*NB) : 0ull;
                    const u64* wp = wk + j*24;
                    #pragma unroll
                    for (int u = 0; u < 8; u++) {
                        u64 w = wp[u];
                        acc[u][0][0] = fma2(w, a00, acc[u][0][0]);
                        acc[u][0][1] = fma2(w, a01, acc[u][0][1]);
                        acc[u][1][0] = fma2(w, a10, acc[u][1][0]);
                        acc[u][1][1] = fma2(w, a11, acc[u][1][1]);
                    }
                }
            }
        }
        #pragma unroll
        for (int i2 = 0; i2 < 2; i2++) {
            int sc = 1 << i2;
            float inv = (i2 == 0) ? 1.f : 0.5f;
            #pragma unroll
            for (int u = 0; u < 8; u++) {
                float bias0 = 0.f, bias1 = 0.f;
                #pragma unroll
                for (int j = 0; j < 3; j++) {
                    int x0 = (j-1)*sc;
                    float vj = V[(co0+u)*3 + j];
                    if (x0   >= 0 && x0   < 3) bias0 += vj;
                    if (x0+1 >= 0 && x0+1 < 3) bias1 += vj;
                }
                float2 p0 = up2(acc[u][i2][0]), p1 = up2(acc[u][i2][1]);
                float vx = fmaxf(fmaxf(p0.x + bias0, p1.x + bias1), 0.f)*inv;
                float vy = fmaxf(fmaxf(p0.y + bias0, p1.y + bias1), 0.f)*inv;
                s[u] += vx + vy;
                q[u] += vx*vx + vy*vy;
                *reinterpret_cast<float2*>(&g_a4T[(size_t)((cbase+co0+u)*3 + i2)*NB + b]) =
                    make_float2(vx, vy);
            }
        }
    } else {
        // ii = 2, s = 4
        u64 acc[8][2];
        #pragma unroll
        for (int u = 0; u < 8; u++) { acc[u][0] = 0ull; acc[u][1] = 0ull; }
        for (int c = 0; c < 48; c++) {
            #pragma unroll
            for (int r = 0; r < 3; r++) {
                const float* pb = &g_a3[(size_t)((c*5 + 2 + r)*3)*NB + b];
                const u64* wk = &wd4[(c*9 + r*3)*24 + co0];
                #pragma unroll
                for (int j = 0; j < 3; j++) {
                    int x0 = (j-1)*4;
                    u64 a0 = (x0   >= 0 && x0   < 3) ? ld2(pb + (size_t)(x0  )*NB) : 0ull;
                    u64 a1 = (x0+1 >= 0 && x0+1 < 3) ? ld2(pb + (size_t)(x0+1)*NB) : 0ull;
                    const u64* wp = wk + j*24;
                    #pragma unroll
                    for (int u = 0; u < 8; u++) {
                        u64 w = wp[u];
                        acc[u][0] = fma2(w, a0, acc[u][0]);
                        acc[u][1] = fma2(w, a1, acc[u][1]);
                    }
                }
            }
        }
        #pragma unroll
        for (int u = 0; u < 8; u++) {
            float bias0 = 0.f, bias1 = 0.f;
            #pragma unroll
            for (int j = 0; j < 3; j++) {
                int x0 = (j-1)*4;
                float vj = V[(co0+u)*3 + j];
                if (x0   >= 0 && x0   < 3) bias0 += vj;
                if (x0+1 >= 0 && x0+1 < 3) bias1 += vj;
            }
            float2 p0 = up2(acc[u][0]), p1 = up2(acc[u][1]);
            float vx = fmaxf(fmaxf(p0.x + bias0, p1.x + bias1), 0.f)*0.25f;
            float vy = fmaxf(fmaxf(p0.y + bias0, p1.y + bias1), 0.f)*0.25f;
            s[u] += vx + vy;
            q[u] += vx*vx + vy*vy;
            *reinterpret_cast<float2*>(&g_a4T[(size_t)((cbase+co0+u)*3 + 2)*NB + b]) =
                make_float2(vx, vy);
        }
    }
    #pragma unroll
    for (int u = 0; u < 8; u++) {
        #pragma unroll
        for (int o = 16; o; o >>= 1) {
            s[u] += __shfl_down_sync(0xffffffffu, s[u], o);
            q[u] += __shfl_down_sync(0xffffffffu, q[u], o);
        }
    }
    if (lane == 0) {
        #pragma unroll
        for (int u = 0; u < 8; u++) { atomicAdd(&ssum[co0+u], s[u]); atomicAdd(&ssq[co0+u], q[u]); }
    }
    __syncthreads();
    if (tid < 24) {
        atomicAdd(&g_stats[168+cbase+tid], (double)ssum[tid]);
        atomicAdd(&g_stats[264+cbase+tid], (double)ssq[tid]);
    }
}

// ---------------- Phase 5a: bn4 affine + collapse 3 FCs into (6x288) + bias ----------------
__global__ __launch_bounds__(256) void k_phase5a(const float* __restrict__ g4, const float* __restrict__ b4,
                                                 const float* __restrict__ f1w, const float* __restrict__ f1b,
                                                 const float* __restrict__ f2w, const float* __restrict__ f2b,
                                                 const float* __restrict__ f3w, const float* __restrict__ f3b) {
    __shared__ float A4[96], B4[96], W23[576], bcs[6];
    int tid = threadIdx.x;
    if (tid < 96) {
        double m = g_stats[168+tid] / 12288.0;
        double v = g_stats[264+tid] / 12288.0 - m*m;
        float a = g4[tid] * rsqrtf((float)v + EPSF);
        A4[tid] = a; B4[tid] = b4[tid] - (float)m*a;
    }
    if (tid < 6) bcs[tid] = 0.f;
    for (int idx = tid; idx < 576; idx += 256) {
        int j = idx / 96, k = idx % 96;
        float s = 0.f;
        for (int l = 0; l < 48; l++) s += f3w[j*48 + l] * f2w[l*96 + k];
        W23[idx] = s;
    }
    __syncthreads();
    for (int idx = tid; idx < 1728; idx += 256) {
        int j = idx / 288, i = idx % 288;
        int c = i / 3;
        float s0 = 0.f;
        for (int k = 0; k < 96; k++) s0 += W23[j*96 + k] * f1w[k*288 + i];
        g_Wc[idx] = s0 * A4[c];
        atomicAdd(&bcs[j], s0 * B4[c]);
    }
    __syncthreads();
    if (tid < 6) {
        int j = tid;
        float bb = f3b[j];
        for (int l = 0; l < 48; l++) bb += f3w[j*48 + l] * f2b[l];
        for (int k = 0; k < 96; k++) bb += W23[j*96 + k] * f1b[k];
        g_bc[j] = bcs[j] + bb;
    }
}

// ---------------- Phase 5b: out[b][6] from a4T planes, 4 samples/thread ----------------
__global__ __launch_bounds__(256) void k_phase5b(float* __restrict__ out) {
    __shared__ float Wcs[1728];
    for (int i = threadIdx.x; i < 1728; i += 256) Wcs[i] = g_Wc[i];
    __syncthreads();
    int b = (blockIdx.x*256 + threadIdx.x)*4;
    float acc[6][4];
    #pragma unroll
    for (int j = 0; j < 6; j++)
        #pragma unroll
        for (int m = 0; m < 4; m++) acc[j][m] = g_bc[j];
    for (int f = 0; f < 288; f++) {
        float4 v = *reinterpret_cast<const float4*>(&g_a4T[(size_t)f*NB + b]);
        #pragma unroll
        for (int j = 0; j < 6; j++) {
            float w = Wcs[j*288 + f];
            acc[j][0] += v.x*w; acc[j][1] += v.y*w; acc[j][2] += v.z*w; acc[j][3] += v.w*w;
        }
    }
    #pragma unroll
    for (int m = 0; m < 4; m++)
        #pragma unroll
        for (int j = 0; j < 6; j++)
            out[(b+m)*6 + j] = acc[j][m];
}

// ---------------- launcher ----------------
extern "C" void kernel_launch(void* const* d_in, const int* in_sizes, int n_in,
                              void* d_out, int out_size) {
    const float* x   = (const float*)d_in[0];
    const float* w1  = (const float*)d_in[1];
    const float* w2  = (const float*)d_in[2];
    const float* w3  = (const float*)d_in[3];
    const float* w4  = (const float*)d_in[4];
    const float* g1  = (const float*)d_in[5];
    const float* b1  = (const float*)d_in[6];
    const float* g2  = (const float*)d_in[7];
    const float* b2  = (const float*)d_in[8];
    const float* g3  = (const float*)d_in[9];
    const float* b3  = (const float*)d_in[10];
    const float* g4  = (const float*)d_in[11];
    const float* b4  = (const float*)d_in[12];
    const float* f1w = (const float*)d_in[13];
    const float* f1b = (const float*)d_in[14];
    const float* f2w = (const float*)d_in[15];
    const float* f2b = (const float*)d_in[16];
    const float* f3w = (const float*)d_in[17];
    const float* f3b = (const float*)d_in[18];
    float* out = (float*)d_out;

    static const int SM3 = 8640 * 8;
    static const int SM4 = 10368 * 8;
    cudaFuncSetAttribute(k_p3, cudaFuncAttributeMaxDynamicSharedMemorySize, SM3);
    cudaFuncSetAttribute(k_p4, cudaFuncAttributeMaxDynamicSharedMemorySize, SM4);

    // NOTE: launch order puts k_p2 4th — the profiler captures the 4th launch.
    k_zero<<<1, 384>>>();
    k_tr<<<dim3(128, 19), dim3(32, 8)>>>(x);
    k_p1<<<dim3(64, 15), 128>>>(w1);
    k_p2<<<dim3(64, 21), 128>>>(w2, g1, b1);
    k_p3<<<dim3(64, 10), 128, SM3>>>(w3, g2, b2);
    k_p4<<<dim3(64, 4), 192, SM4>>>(w4, g3, b3);
    k_phase5a<<<1, 256>>>(g4, b4, f1w, f1b, f2w, f2b, f3w, f3b);
    k_phase5b<<<4, 256>>>(out);
}

// round 10
// speedup vs baseline: 1.3009x; 1.1411x over previous
#include <cuda_runtime.h>

#define EPSF 2e-5f
#define NB 4096

typedef unsigned long long u64;

__device__ __forceinline__ u64 ld2(const float* p) {
    return *reinterpret_cast<const u64*>(p);
}
__device__ __forceinline__ u64 fma2(u64 a, u64 b, u64 c) {
    u64 d;
    asm("fma.rn.f32x2 %0, %1, %2, %3;" : "=l"(d) : "l"(a), "l"(b), "l"(c));
    return d;
}
__device__ __forceinline__ float2 up2(u64 v) {
    float2 r;
    asm("mov.b64 {%0,%1}, %2;" : "=f"(r.x), "=f"(r.y) : "l"(v));
    return r;
}
__device__ __forceinline__ u64 dupw(float w) {
    u64 d;
    asm("mov.b64 %0, {%1,%1};" : "=l"(d) : "f"(w));
    return d;
}
__device__ __forceinline__ float wsum(float v) {
    #pragma unroll
    for (int o = 16; o; o >>= 1) v += __shfl_down_sync(0xffffffffu, v, o);
    return v;
}

// ---------------- scratch planes, [feature][batch] ----------------
__device__ __align__(16) float  g_xT [600*NB];   // [(t*6+c)][b]
__device__ __align__(16) float  g_m1 [2700*NB];  // (12,9,25) double-pooled relu'd lift (pre-bn)
__device__ __align__(16) float  g_m2 [1008*NB];  // (24,7,6)  double-pooled relu'd conv2 (pre-bn)
__device__ __align__(16) float  g_a3 [720*NB];   // (48,5,3)  pooled relu'd conv3 (pre-bn)
__device__ __align__(16) float  g_a4T[288*NB];   // (96,3)    pooled relu'd conv4 (pre-bn)
__device__ double g_stats[360];   // s1:0 q1:12 s2:24 q2:48 s3:72 q3:120 s4:168 q4:264
__device__ float  g_Wc[6*288];
__device__ float  g_bc[6];

__global__ void k_zero() {
    int t = threadIdx.x;
    if (t < 360) g_stats[t] = 0.0;
}

// ---------------- transpose x (4096,600) -> xT (600,4096) ----------------
__global__ void k_tr(const float* __restrict__ x) {
    __shared__ float tile[32][33];
    int bx = blockIdx.x * 32;
    int fy = blockIdx.y * 32;
    int tx = threadIdx.x, ty = threadIdx.y;
    #pragma unroll
    for (int m = 0; m < 4; m++) {
        int ff = fy + tx;
        tile[ty + m*8][tx] = (ff < 600) ? x[(bx + ty + m*8)*600 + ff] : 0.f;
    }
    __syncthreads();
    #pragma unroll
    for (int m = 0; m < 4; m++) {
        int ff = fy + ty + m*8;
        if (ff < 600) g_xT[ff*NB + bx + tx] = tile[tx][ty + m*8];
    }
}

// ---------------- Phase 1: lift conv + pool(relu,stats) + pool(max) ----------------
// one task per warp: t = blockIdx.y*4+wid in 0..224: hh=t/25, op=t%25. Two passes.
__global__ __launch_bounds__(128, 5) void k_p1(const float* __restrict__ w1) {
    __shared__ __align__(16) u64 wd[504];     // [(c*7+j)*12 + co]
    __shared__ float2 vps[12][128];
    __shared__ float ssum[12], ssq[12];
    int tid = threadIdx.x, lane = tid & 31, wid = tid >> 5;
    int b = blockIdx.x * 64 + lane * 2;
    for (int i = tid; i < 504; i += 128) { int co = i/42, k = i%42; wd[k*12+co] = dupw(w1[i]); }
    if (tid < 12) { ssum[tid] = 0.f; ssq[tid] = 0.f; }
    __syncthreads();
    int t = blockIdx.y * 4 + wid;             // 0..227
    if (t < 225) {
        int hh = t / 25, op = t % 25;
        int sc = 1 << hh;
        float inv = 1.f/(float)sc;
        #pragma unroll 1
        for (int pass = 0; pass < 2; pass++) {
            int px = 4*op + 2*pass;
            u64 acc[12][2];
            #pragma unroll
            for (int u = 0; u < 12; u++) { acc[u][0] = 0ull; acc[u][1] = 0ull; }
            for (int c = 0; c < 6; c++) {
                const float* pc = &g_xT[(size_t)c*NB + b];
                #pragma unroll
                for (int j = 0; j < 7; j++) {
                    int t0 = px + (j-3)*sc;
                    u64 a0 = (t0   >= 0 && t0   < 100) ? ld2(pc + (size_t)(t0  )*6*NB) : 0ull;
                    u64 a1 = (t0+1 >= 0 && t0+1 < 100) ? ld2(pc + (size_t)(t0+1)*6*NB) : 0ull;
                    const ulonglong2* wp = reinterpret_cast<const ulonglong2*>(&wd[(c*7 + j)*12]);
                    #pragma unroll
                    for (int u2 = 0; u2 < 6; u2++) {
                        ulonglong2 ww = wp[u2];
                        acc[2*u2  ][0] = fma2(ww.x, a0, acc[2*u2  ][0]);
                        acc[2*u2  ][1] = fma2(ww.x, a1, acc[2*u2  ][1]);
                        acc[2*u2+1][0] = fma2(ww.y, a0, acc[2*u2+1][0]);
                        acc[2*u2+1][1] = fma2(ww.y, a1, acc[2*u2+1][1]);
                    }
                }
            }
            #pragma unroll
            for (int u = 0; u < 12; u++) {
                float2 p0 = up2(acc[u][0]), p1 = up2(acc[u][1]);
                float vx = fmaxf(fmaxf(p0.x, p1.x), 0.f)*inv;
                float vy = fmaxf(fmaxf(p0.y, p1.y), 0.f)*inv;
                if (pass == 0) {
                    vps[u][tid] = make_float2(vx, vy);
                } else {
                    float2 vp = vps[u][tid];
                    *reinterpret_cast<float2*>(&g_m1[(size_t)((u*9+hh)*25 + op)*NB + b]) =
                        make_float2(fmaxf(vp.x, vx), fmaxf(vp.y, vy));
                    float su = wsum(vp.x + vp.y + vx + vy);
                    float qu = wsum(vp.x*vp.x + vp.y*vp.y + vx*vx + vy*vy);
                    if (lane == 0) { atomicAdd(&ssum[u], su); atomicAdd(&ssq[u], qu); }
                }
            }
        }
    }
    __syncthreads();
    if (tid < 12) {
        atomicAdd(&g_stats[tid],    (double)ssum[tid]);
        atomicAdd(&g_stats[12+tid], (double)ssq[tid]);
    }
}

// ---------------- Phase 2: gg_conv w2 (bn1 folded, bias fused) + pool(stats) + pool ----------------
// block owns ONE cog (12 cos). t = tg*4+wid in 0..41: ii=t/6, op=t%6. Two passes.
__global__ __launch_bounds__(128, 5) void k_p2(const float* __restrict__ w2,
                                               const float* __restrict__ g1,
                                               const float* __restrict__ b1) {
    __shared__ __align__(16) u64 wd[2160];    // [k*12 + u], k=(c*15+r*5+j), scaled by A1[c]
    __shared__ float2 vps[12][128];
    __shared__ float A1[12], Bc[12], V[60];   // V[u*5+j]
    __shared__ float ssum[12], ssq[12];
    int tid = threadIdx.x, lane = tid & 31, wid = tid >> 5;
    int b = blockIdx.x * 64 + lane * 2;
    int cog = blockIdx.y & 1;
    int tg  = blockIdx.y >> 1;
    int co0g = cog * 12;
    if (tid < 12) {
        double m = g_stats[tid] / 1843200.0;
        double v = g_stats[12+tid] / 1843200.0 - m*m;
        float a = g1[tid] * rsqrtf((float)v + EPSF);
        A1[tid] = a;
        Bc[tid] = b1[tid] - (float)m*a;
        ssum[tid] = 0.f; ssq[tid] = 0.f;
    }
    __syncthreads();
    for (int i = tid; i < 2160; i += 128) {
        int u = i/180, k = i%180, c = k/15;
        wd[k*12+u] = dupw(w2[(co0g+u)*180 + k] * A1[c]);
    }
    for (int i = tid; i < 60; i += 128) {
        int u = i / 5, j = i % 5;
        float acc = 0.f;
        for (int c = 0; c < 12; c++) {
            float bc = Bc[c];
            for (int r = 0; r < 3; r++) acc += w2[(co0g+u)*180 + c*15 + r*5 + j] * bc;
        }
        V[i] = acc;
    }
    __syncthreads();
    int t = tg * 4 + wid;                     // 0..43
    if (t < 42) {
        int ii = t / 6, op = t % 6;
        int sc = 1 << ii;
        float inv = 1.f/(float)sc;
        #pragma unroll 1
        for (int pass = 0; pass < 2; pass++) {
            int px = 4*op + 2*pass;
            u64 acc[12][2];
            #pragma unroll
            for (int u = 0; u < 12; u++) { acc[u][0] = 0ull; acc[u][1] = 0ull; }
            for (int c = 0; c < 12; c++) {
                #pragma unroll
                for (int r = 0; r < 3; r++) {
                    const float* pb = &g_m1[(size_t)((c*9 + ii + r)*25)*NB + b];
                    const u64* wk = &wd[(c*15 + r*5)*12];
                    #pragma unroll
                    for (int j = 0; j < 5; j++) {
                        int x0 = px + (j-2)*sc;
                        u64 a0 = (x0   >= 0 && x0   < 25) ? ld2(pb + (size_t)(x0  )*NB) : 0ull;
                        u64 a1 = (x0+1 >= 0 && x0+1 < 25) ? ld2(pb + (size_t)(x0+1)*NB) : 0ull;
                        const ulonglong2* wp = reinterpret_cast<const ulonglong2*>(wk + j*12);
                        #pragma unroll
                        for (int u2 = 0; u2 < 6; u2++) {
                            ulonglong2 ww = wp[u2];
                            acc[2*u2  ][0] = fma2(ww.x, a0, acc[2*u2  ][0]);
                            acc[2*u2  ][1] = fma2(ww.x, a1, acc[2*u2  ][1]);
                            acc[2*u2+1][0] = fma2(ww.y, a0, acc[2*u2+1][0]);
                            acc[2*u2+1][1] = fma2(ww.y, a1, acc[2*u2+1][1]);
                        }
                    }
                }
            }
            #pragma unroll
            for (int u = 0; u < 12; u++) {
                float bias0 = 0.f, bias1 = 0.f;
                #pragma unroll
                for (int j = 0; j < 5; j++) {
                    int x0 = px + (j-2)*sc;
                    float vj = V[u*5 + j];
                    if (x0   >= 0 && x0   < 25) bias0 += vj;
                    if (x0+1 >= 0 && x0+1 < 25) bias1 += vj;
                }
                float2 p0 = up2(acc[u][0]), p1 = up2(acc[u][1]);
                float vx = fmaxf(fmaxf(p0.x + bias0, p1.x + bias1), 0.f)*inv;
                float vy = fmaxf(fmaxf(p0.y + bias0, p1.y + bias1), 0.f)*inv;
                if (pass == 0) {
                    vps[u][tid] = make_float2(vx, vy);
                } else {
                    float2 vp = vps[u][tid];
                    *reinterpret_cast<float2*>(&g_m2[(size_t)(((co0g+u)*7+ii)*6 + op)*NB + b]) =
                        make_float2(fmaxf(vp.x, vx), fmaxf(vp.y, vy));
                    float su = wsum(vp.x + vp.y + vx + vy);
                    float qu = wsum(vp.x*vp.x + vp.y*vp.y + vx*vx + vy*vy);
                    if (lane == 0) { atomicAdd(&ssum[u], su); atomicAdd(&ssq[u], qu); }
                }
            }
        }
    }
    __syncthreads();
    if (tid < 12) {
        atomicAdd(&g_stats[24+co0g+tid], (double)ssum[tid]);
        atomicAdd(&g_stats[48+co0g+tid], (double)ssq[tid]);
    }
}

// ---------------- Phase 3: gg_conv w3 (bn2 folded, bias fused) + pool(relu,stats) ----------------
// block owns 12 cos (quarter q = blockIdx.y>>2). t = (blockIdx.y&3)*4+wid in 0..14: ii=t/3, pr=t%3.
__global__ __launch_bounds__(128, 5) void k_p3(const float* __restrict__ w3,
                                               const float* __restrict__ g2,
                                               const float* __restrict__ b2) {
    __shared__ __align__(16) u64 wd3[4320];   // [k*12 + u], k 0..359, scaled by A2[c]
    __shared__ float A2[24], Bc[24], V[60];   // V[u*5+j]
    __shared__ float ssum[12], ssq[12];
    int tid = threadIdx.x, lane = tid & 31, wid = tid >> 5;
    int b = blockIdx.x * 64 + lane * 2;
    int q  = blockIdx.y >> 2;
    int tg = blockIdx.y & 3;
    int cbase = q * 12;
    if (tid < 24) {
        double m = g_stats[24+tid] / 344064.0;
        double v = g_stats[48+tid] / 344064.0 - m*m;
        float a = g2[tid] * rsqrtf((float)v + EPSF);
        A2[tid] = a;
        Bc[tid] = b2[tid] - (float)m*a;
    }
    if (tid < 12) { ssum[tid] = 0.f; ssq[tid] = 0.f; }
    __syncthreads();
    for (int i = tid; i < 4320; i += 128) {
        int u = i/360, k = i%360, c = k/15;
        wd3[k*12+u] = dupw(w3[(cbase+u)*360 + k] * A2[c]);
    }
    for (int i = tid; i < 60; i += 128) {
        int u = i / 5, j = i % 5;
        float acc = 0.f;
        for (int c = 0; c < 24; c++) {
            float bc = Bc[c];
            for (int r = 0; r < 3; r++) acc += w3[(cbase+u)*360 + c*15 + r*5 + j] * bc;
        }
        V[i] = acc;
    }
    __syncthreads();
    int t = tg * 4 + wid;                     // 0..15
    if (t < 15) {
        int ii = t / 3, pr = t % 3;
        int sc = 1 << ii;
        float inv = 1.f/(float)sc;
        int px = 2*pr;
        u64 acc[12][2];
        #pragma unroll
        for (int u = 0; u < 12; u++) { acc[u][0] = 0ull; acc[u][1] = 0ull; }
        for (int c = 0; c < 24; c++) {
            #pragma unroll
            for (int r = 0; r < 3; r++) {
                const float* pb = &g_m2[(size_t)((c*7 + ii + r)*6)*NB + b];
                const u64* wk = &wd3[(c*15 + r*5)*12];
                #pragma unroll
                for (int j = 0; j < 5; j++) {
                    int x0 = px + (j-2)*sc;
                    u64 a0 = (x0   >= 0 && x0   < 6) ? ld2(pb + (size_t)(x0  )*NB) : 0ull;
                    u64 a1 = (x0+1 >= 0 && x0+1 < 6) ? ld2(pb + (size_t)(x0+1)*NB) : 0ull;
                    const ulonglong2* wp = reinterpret_cast<const ulonglong2*>(wk + j*12);
                    #pragma unroll
                    for (int u2 = 0; u2 < 6; u2++) {
                        ulonglong2 ww = wp[u2];
                        acc[2*u2  ][0] = fma2(ww.x, a0, acc[2*u2  ][0]);
                        acc[2*u2  ][1] = fma2(ww.x, a1, acc[2*u2  ][1]);
                        acc[2*u2+1][0] = fma2(ww.y, a0, acc[2*u2+1][0]);
                        acc[2*u2+1][1] = fma2(ww.y, a1, acc[2*u2+1][1]);
                    }
                }
            }
        }
        #pragma unroll
        for (int u = 0; u < 12; u++) {
            float bias0 = 0.f, bias1 = 0.f;
            #pragma unroll
            for (int j = 0; j < 5; j++) {
                int x0 = px + (j-2)*sc;
                float vj = V[u*5 + j];
                if (x0   >= 0 && x0   < 6) bias0 += vj;
                if (x0+1 >= 0 && x0+1 < 6) bias1 += vj;
            }
            float2 p0 = up2(acc[u][0]), p1 = up2(acc[u][1]);
            float vx = fmaxf(fmaxf(p0.x + bias0, p1.x + bias1), 0.f)*inv;
            float vy = fmaxf(fmaxf(p0.y + bias0, p1.y + bias1), 0.f)*inv;
            *reinterpret_cast<float2*>(&g_a3[(size_t)((cbase+u)*15 + ii*3 + pr)*NB + b]) =
                make_float2(vx, vy);
            float su = wsum(vx + vy);
            float qu = wsum(vx*vx + vy*vy);
            if (lane == 0) { atomicAdd(&ssum[u], su); atomicAdd(&ssq[u], qu); }
        }
    }
    __syncthreads();
    if (tid < 12) {
        atomicAdd(&g_stats[72+cbase+tid],  (double)ssum[tid]);
        atomicAdd(&g_stats[120+cbase+tid], (double)ssq[tid]);
    }
}

// ---------------- Phase 4: gg_conv w4 (bn3 folded, bias fused) + pool(relu,stats) ----------------
// block owns 12 cos (blockIdx.y 0..7). 4 warps: cog(2: co-tile 6) x unit(2: ii{0,1} / ii{2}).
__global__ __launch_bounds__(128, 5) void k_p4(const float* __restrict__ w4,
                                               const float* __restrict__ g3,
                                               const float* __restrict__ b3) {
    __shared__ __align__(16) u64 wd4[5184];   // [k*12 + u], k 0..431, scaled by A3[c]
    __shared__ float A3[48], Bc[48], V[36];   // V[u*3+j]
    __shared__ float ssum[12], ssq[12];
    int tid = threadIdx.x, lane = tid & 31, wid = tid >> 5;
    int b = blockIdx.x * 64 + lane * 2;
    int cbase = blockIdx.y * 12;
    if (tid < 48) {
        double m = g_stats[72+tid] / 61440.0;
        double v = g_stats[120+tid] / 61440.0 - m*m;
        float a = g3[tid] * rsqrtf((float)v + EPSF);
        A3[tid] = a;
        Bc[tid] = b3[tid] - (float)m*a;
    }
    if (tid < 12) { ssum[tid] = 0.f; ssq[tid] = 0.f; }
    __syncthreads();
    for (int i = tid; i < 5184; i += 128) {
        int u = i/432, k = i%432, c = k/9;
        wd4[k*12+u] = dupw(w4[(cbase+u)*432 + k] * A3[c]);
    }
    for (int i = tid; i < 36; i += 128) {
        int u = i / 3, j = i % 3;
        float acc = 0.f;
        for (int c = 0; c < 48; c++) {
            float bc = Bc[c];
            for (int r = 0; r < 3; r++) acc += w4[(cbase+u)*432 + c*9 + r*3 + j] * bc;
        }
        V[i] = acc;
    }
    __syncthreads();
    int cog = wid >> 1;     // 0..1 (co-tile 6)
    int unit = wid & 1;
    int co0 = cog * 6;
    if (unit == 0) {
        // ii = 0 and 1, sharing weight loads
        u64 acc[6][2][2];
        #pragma unroll
        for (int u = 0; u < 6; u++)
            #pragma unroll
            for (int i2 = 0; i2 < 2; i2++) { acc[u][i2][0] = 0ull; acc[u][i2][1] = 0ull; }
        for (int c = 0; c < 48; c++) {
            #pragma unroll
            for (int r = 0; r < 3; r++) {
                const float* pb0 = &g_a3[(size_t)((c*5 + 0 + r)*3)*NB + b];
                const float* pb1 = &g_a3[(size_t)((c*5 + 1 + r)*3)*NB + b];
                const u64* wk = &wd4[(c*9 + r*3)*12 + co0];
                #pragma unroll
                for (int j = 0; j < 3; j++) {
                    int x0a = (j-1);        // ii=0, s=1
                    int x0b = (j-1)*2;      // ii=1, s=2
                    u64 a00 = (x0a   >= 0 && x0a   < 3) ? ld2(pb0 + (size_t)(x0a  )*NB) : 0ull;
                    u64 a01 = (x0a+1 >= 0 && x0a+1 < 3) ? ld2(pb0 + (size_t)(x0a+1)*NB) : 0ull;
                    u64 a10 = (x0b   >= 0 && x0b   < 3) ? ld2(pb1 + (size_t)(x0b  )*NB) : 0ull;
                    u64 a11 = (x0b+1 >= 0 && x0b+1 < 3) ? ld2(pb1 + (size_t)(x0b+1)*NB) : 0ull;
                    const ulonglong2* wp = reinterpret_cast<const ulonglong2*>(wk + j*12);
                    #pragma unroll
                    for (int u2 = 0; u2 < 3; u2++) {
                        ulonglong2 ww = wp[u2];
                        acc[2*u2  ][0][0] = fma2(ww.x, a00, acc[2*u2  ][0][0]);
                        acc[2*u2  ][0][1] = fma2(ww.x, a01, acc[2*u2  ][0][1]);
                        acc[2*u2  ][1][0] = fma2(ww.x, a10, acc[2*u2  ][1][0]);
                        acc[2*u2  ][1][1] = fma2(ww.x, a11, acc[2*u2  ][1][1]);
                        acc[2*u2+1][0][0] = fma2(ww.y, a00, acc[2*u2+1][0][0]);
                        acc[2*u2+1][0][1] = fma2(ww.y, a01, acc[2*u2+1][0][1]);
                        acc[2*u2+1][1][0] = fma2(ww.y, a10, acc[2*u2+1][1][0]);
                        acc[2*u2+1][1][1] = fma2(ww.y, a11, acc[2*u2+1][1][1]);
                    }
                }
            }
        }
        #pragma unroll
        for (int i2 = 0; i2 < 2; i2++) {
            int sc = 1 << i2;
            float inv = (i2 == 0) ? 1.f : 0.5f;
            #pragma unroll
            for (int u = 0; u < 6; u++) {
                float bias0 = 0.f, bias1 = 0.f;
                #pragma unroll
                for (int j = 0; j < 3; j++) {
                    int x0 = (j-1)*sc;
                    float vj = V[(co0+u)*3 + j];
                    if (x0   >= 0 && x0   < 3) bias0 += vj;
                    if (x0+1 >= 0 && x0+1 < 3) bias1 += vj;
                }
                float2 p0 = up2(acc[u][i2][0]), p1 = up2(acc[u][i2][1]);
                float vx = fmaxf(fmaxf(p0.x + bias0, p1.x + bias1), 0.f)*inv;
                float vy = fmaxf(fmaxf(p0.y + bias0, p1.y + bias1), 0.f)*inv;
                *reinterpret_cast<float2*>(&g_a4T[(size_t)((cbase+co0+u)*3 + i2)*NB + b]) =
                    make_float2(vx, vy);
                float su = wsum(vx + vy);
                float qu = wsum(vx*vx + vy*vy);
                if (lane == 0) { atomicAdd(&ssum[co0+u], su); atomicAdd(&ssq[co0+u], qu); }
            }
        }
    } else {
        // ii = 2, s = 4
        u64 acc[6][2];
        #pragma unroll
        for (int u = 0; u < 6; u++) { acc[u][0] = 0ull; acc[u][1] = 0ull; }
        for (int c = 0; c < 48; c++) {
            #pragma unroll
            for (int r = 0; r < 3; r++) {
                const float* pb = &g_a3[(size_t)((c*5 + 2 + r)*3)*NB + b];
                const u64* wk = &wd4[(c*9 + r*3)*12 + co0];
                #pragma unroll
                for (int j = 0; j < 3; j++) {
                    int x0 = (j-1)*4;
                    u64 a0 = (x0   >= 0 && x0   < 3) ? ld2(pb + (size_t)(x0  )*NB) : 0ull;
                    u64 a1 = (x0+1 >= 0 && x0+1 < 3) ? ld2(pb + (size_t)(x0+1)*NB) : 0ull;
                    const ulonglong2* wp = reinterpret_cast<const ulonglong2*>(wk + j*12);
                    #pragma unroll
                    for (int u2 = 0; u2 < 3; u2++) {
                        ulonglong2 ww = wp[u2];
                        acc[2*u2  ][0] = fma2(ww.x, a0, acc[2*u2  ][0]);
                        acc[2*u2  ][1] = fma2(ww.x, a1, acc[2*u2  ][1]);
                        acc[2*u2+1][0] = fma2(ww.y, a0, acc[2*u2+1][0]);
                        acc[2*u2+1][1] = fma2(ww.y, a1, acc[2*u2+1][1]);
                    }
                }
            }
        }
        #pragma unroll
        for (int u = 0; u < 6; u++) {
            float bias0 = 0.f, bias1 = 0.f;
            #pragma unroll
            for (int j = 0; j < 3; j++) {
                int x0 = (j-1)*4;
                float vj = V[(co0+u)*3 + j];
                if (x0   >= 0 && x0   < 3) bias0 += vj;
                if (x0+1 >= 0 && x0+1 < 3) bias1 += vj;
            }
            float2 p0 = up2(acc[u][0]), p1 = up2(acc[u][1]);
            float vx = fmaxf(fmaxf(p0.x + bias0, p1.x + bias1), 0.f)*0.25f;
            float vy = fmaxf(fmaxf(p0.y + bias0, p1.y + bias1), 0.f)*0.25f;
            *reinterpret_cast<float2*>(&g_a4T[(size_t)((cbase+co0+u)*3 + 2)*NB + b]) =
                make_float2(vx, vy);
            float su = wsum(vx + vy);
            float qu = wsum(vx*vx + vy*vy);
            if (lane == 0) { atomicAdd(&ssum[co0+u], su); atomicAdd(&ssq[co0+u], qu); }
        }
    }
    __syncthreads();
    if (tid < 12) {
        atomicAdd(&g_stats[168+cbase+tid], (double)ssum[tid]);
        atomicAdd(&g_stats[264+cbase+tid], (double)ssq[tid]);
    }
}

// ---------------- Phase 5a: bn4 affine + collapse 3 FCs into (6x288) + bias ----------------
__global__ __launch_bounds__(256) void k_phase5a(const float* __restrict__ g4, const float* __restrict__ b4,
                                                 const float* __restrict__ f1w, const float* __restrict__ f1b,
                                                 const float* __restrict__ f2w, const float* __restrict__ f2b,
                                                 const float* __restrict__ f3w, const float* __restrict__ f3b) {
    __shared__ float A4[96], B4[96], W23[576], bcs[6];
    int tid = threadIdx.x;
    if (tid < 96) {
        double m = g_stats[168+tid] / 12288.0;
        double v = g_stats[264+tid] / 12288.0 - m*m;
        float a = g4[tid] * rsqrtf((float)v + EPSF);
        A4[tid] = a; B4[tid] = b4[tid] - (float)m*a;
    }
    if (tid < 6) bcs[tid] = 0.f;
    for (int idx = tid; idx < 576; idx += 256) {
        int j = idx / 96, k = idx % 96;
        float s = 0.f;
        for (int l = 0; l < 48; l++) s += f3w[j*48 + l] * f2w[l*96 + k];
        W23[idx] = s;
    }
    __syncthreads();
    for (int idx = tid; idx < 1728; idx += 256) {
        int j = idx / 288, i = idx % 288;
        int c = i / 3;
        float s0 = 0.f;
        for (int k = 0; k < 96; k++) s0 += W23[j*96 + k] * f1w[k*288 + i];
        g_Wc[idx] = s0 * A4[c];
        atomicAdd(&bcs[j], s0 * B4[c]);
    }
    __syncthreads();
    if (tid < 6) {
        int j = tid;
        float bb = f3b[j];
        for (int l = 0; l < 48; l++) bb += f3w[j*48 + l] * f2b[l];
        for (int k = 0; k < 96; k++) bb += W23[j*96 + k] * f1b[k];
        g_bc[j] = bcs[j] + bb;
    }
}

// ---------------- Phase 5b: out[b][6] from a4T planes, 4 samples/thread ----------------
__global__ __launch_bounds__(256) void k_phase5b(float* __restrict__ out) {
    __shared__ float Wcs[1728];
    for (int i = threadIdx.x; i < 1728; i += 256) Wcs[i] = g_Wc[i];
    __syncthreads();
    int b = (blockIdx.x*256 + threadIdx.x)*4;
    float acc[6][4];
    #pragma unroll
    for (int j = 0; j < 6; j++)
        #pragma unroll
        for (int m = 0; m < 4; m++) acc[j][m] = g_bc[j];
    for (int f = 0; f < 288; f++) {
        float4 v = *reinterpret_cast<const float4*>(&g_a4T[(size_t)f*NB + b]);
        #pragma unroll
        for (int j = 0; j < 6; j++) {
            float w = Wcs[j*288 + f];
            acc[j][0] += v.x*w; acc[j][1] += v.y*w; acc[j][2] += v.z*w; acc[j][3] += v.w*w;
        }
    }
    #pragma unroll
    for (int m = 0; m < 4; m++)
        #pragma unroll
        for (int j = 0; j < 6; j++)
            out[(b+m)*6 + j] = acc[j][m];
}

// ---------------- launcher ----------------
extern "C" void kernel_launch(void* const* d_in, const int* in_sizes, int n_in,
                              void* d_out, int out_size) {
    const float* x   = (const float*)d_in[0];
    const float* w1  = (const float*)d_in[1];
    const float* w2  = (const float*)d_in[2];
    const float* w3  = (const float*)d_in[3];
    const float* w4  = (const float*)d_in[4];
    const float* g1  = (const float*)d_in[5];
    const float* b1  = (const float*)d_in[6];
    const float* g2  = (const float*)d_in[7];
    const float* b2  = (const float*)d_in[8];
    const float* g3  = (const float*)d_in[9];
    const float* b3  = (const float*)d_in[10];
    const float* g4  = (const float*)d_in[11];
    const float* b4  = (const float*)d_in[12];
    const float* f1w = (const float*)d_in[13];
    const float* f1b = (const float*)d_in[14];
    const float* f2w = (const float*)d_in[15];
    const float* f2b = (const float*)d_in[16];
    const float* f3w = (const float*)d_in[17];
    const float* f3b = (const float*)d_in[18];
    float* out = (float*)d_out;

    // NOTE: launch order puts k_p2 4th — the profiler captures the 4th launch.
    k_zero<<<1, 384>>>();
    k_tr<<<dim3(128, 19), dim3(32, 8)>>>(x);
    k_p1<<<dim3(64, 57), 128>>>(w1);
    k_p2<<<dim3(64, 22), 128>>>(w2, g1, b1);
    k_p3<<<dim3(64, 16), 128>>>(w3, g2, b2);
    k_p4<<<dim3(64, 8), 128>>>(w4, g3, b3);
    k_phase5a<<<1, 256>>>(g4, b4, f1w, f1b, f2w, f2b, f3w, f3b);
    k_phase5b<<<4, 256>>>(out);
}

// round 11
// speedup vs baseline: 1.5979x; 1.2283x over previous
#include <cuda_runtime.h>

#define EPSF 2e-5f
#define NB 4096

typedef unsigned long long u64;

__device__ __forceinline__ u64 ld2(const float* p) {
    return *reinterpret_cast<const u64*>(p);
}
__device__ __forceinline__ u64 fma2(u64 a, u64 b, u64 c) {
    u64 d;
    asm("fma.rn.f32x2 %0, %1, %2, %3;" : "=l"(d) : "l"(a), "l"(b), "l"(c));
    return d;
}
__device__ __forceinline__ float2 up2(u64 v) {
    float2 r;
    asm("mov.b64 {%0,%1}, %2;" : "=f"(r.x), "=f"(r.y) : "l"(v));
    return r;
}
__device__ __forceinline__ u64 dupw(float w) {
    u64 d;
    asm("mov.b64 %0, {%1,%1};" : "=l"(d) : "f"(w));
    return d;
}
__device__ __forceinline__ float wsum(float v) {
    #pragma unroll
    for (int o = 16; o; o >>= 1) v += __shfl_down_sync(0xffffffffu, v, o);
    return v;
}

// ---------------- scratch planes, [feature][batch] ----------------
__device__ __align__(16) float  g_xT [600*NB];   // [c*100 + t][b]
__device__ __align__(16) float  g_m1 [2700*NB];  // (12,9,25) double-pooled relu'd lift (pre-bn)
__device__ __align__(16) float  g_m2 [1008*NB];  // (24,7,6)  double-pooled relu'd conv2 (pre-bn)
__device__ __align__(16) float  g_a3 [720*NB];   // (48,5,3)  pooled relu'd conv3 (pre-bn)
__device__ __align__(16) float  g_a4T[288*NB];   // (96,3)    pooled relu'd conv4 (pre-bn)
__device__ double g_stats[360];   // s1:0 q1:12 s2:24 q2:48 s3:72 q3:120 s4:168 q4:264
__device__ float  g_Wc[6*288];
__device__ float  g_bc[6];

__global__ void k_zero() {
    int t = threadIdx.x;
    if (t < 360) g_stats[t] = 0.0;
}

// ---------------- transpose x (4096,600) -> xT [c*100+t][b] ----------------
__global__ void k_tr(const float* __restrict__ x) {
    __shared__ float tile[32][33];
    int bx = blockIdx.x * 32;
    int fy = blockIdx.y * 32;
    int tx = threadIdx.x, ty = threadIdx.y;
    #pragma unroll
    for (int m = 0; m < 4; m++) {
        int ff = fy + tx;
        tile[ty + m*8][tx] = (ff < 600) ? x[(bx + ty + m*8)*600 + ff] : 0.f;
    }
    __syncthreads();
    #pragma unroll
    for (int m = 0; m < 4; m++) {
        int ff = fy + ty + m*8;
        if (ff < 600) {
            int c = ff % 6, t = ff / 6;
            g_xT[(size_t)(c*100 + t)*NB + bx + tx] = tile[tx][ty + m*8];
        }
    }
}

// ---------------- Phase 1 task (templated on scale) ----------------
template<int HH>
__device__ __forceinline__ void p1_task(const u64* __restrict__ wd, int op, int b,
                                        float* __restrict__ ssum, float* __restrict__ ssq,
                                        float2 (*__restrict__ vps)[128], int tid, int lane) {
    constexpr int SC = 1 << HH;
    constexpr float INV = 1.f / (float)SC;
    #pragma unroll 1
    for (int pass = 0; pass < 2; pass++) {
        int px = 4*op + 2*pass;
        u64 acc[12][2];
        #pragma unroll
        for (int u = 0; u < 12; u++) { acc[u][0] = 0ull; acc[u][1] = 0ull; }
        #pragma unroll
        for (int c = 0; c < 6; c++) {
            const float* pbx = &g_xT[(size_t)(c*100 + px)*NB + b];
            #pragma unroll
            for (int j = 0; j < 7; j++) {
                const int off = (j-3)*SC;
                if (off >= -99 && off <= 99) {         // compile-time prune
                    int x0 = px + off;
                    u64 a0 = ((unsigned)x0     < 100u) ? ld2(pbx + (ptrdiff_t)off*NB)      : 0ull;
                    u64 a1 = ((unsigned)(x0+1) < 100u) ? ld2(pbx + (ptrdiff_t)off*NB + NB) : 0ull;
                    const ulonglong2* wp = reinterpret_cast<const ulonglong2*>(&wd[(c*7 + j)*12]);
                    #pragma unroll
                    for (int u2 = 0; u2 < 6; u2++) {
                        ulonglong2 ww = wp[u2];
                        acc[2*u2  ][0] = fma2(ww.x, a0, acc[2*u2  ][0]);
                        acc[2*u2  ][1] = fma2(ww.x, a1, acc[2*u2  ][1]);
                        acc[2*u2+1][0] = fma2(ww.y, a0, acc[2*u2+1][0]);
                        acc[2*u2+1][1] = fma2(ww.y, a1, acc[2*u2+1][1]);
                    }
                }
            }
        }
        #pragma unroll
        for (int u = 0; u < 12; u++) {
            float2 p0 = up2(acc[u][0]), p1 = up2(acc[u][1]);
            float vx = fmaxf(fmaxf(p0.x, p1.x), 0.f)*INV;
            float vy = fmaxf(fmaxf(p0.y, p1.y), 0.f)*INV;
            if (pass == 0) {
                vps[u][tid] = make_float2(vx, vy);
            } else {
                float2 vp = vps[u][tid];
                *reinterpret_cast<float2*>(&g_m1[(size_t)((u*9+HH)*25 + op)*NB + b]) =
                    make_float2(fmaxf(vp.x, vx), fmaxf(vp.y, vy));
                float su = wsum(vp.x + vp.y + vx + vy);
                float qu = wsum(vp.x*vp.x + vp.y*vp.y + vx*vx + vy*vy);
                if (lane == 0) { atomicAdd(&ssum[u], su); atomicAdd(&ssq[u], qu); }
            }
        }
    }
}

__global__ __launch_bounds__(128, 5) void k_p1(const float* __restrict__ w1) {
    __shared__ __align__(16) u64 wd[504];     // [(c*7+j)*12 + co]
    __shared__ float2 vps[12][128];
    __shared__ float ssum[12], ssq[12];
    int tid = threadIdx.x, lane = tid & 31, wid = tid >> 5;
    int b = blockIdx.x * 64 + lane * 2;
    for (int i = tid; i < 504; i += 128) { int co = i/42, k = i%42; wd[k*12+co] = dupw(w1[i]); }
    if (tid < 12) { ssum[tid] = 0.f; ssq[tid] = 0.f; }
    __syncthreads();
    int t = blockIdx.y * 4 + wid;             // 0..227
    if (t < 225) {
        int hh = t / 25, op = t % 25;
        switch (hh) {
            case 0: p1_task<0>(wd, op, b, ssum, ssq, vps, tid, lane); break;
            case 1: p1_task<1>(wd, op, b, ssum, ssq, vps, tid, lane); break;
            case 2: p1_task<2>(wd, op, b, ssum, ssq, vps, tid, lane); break;
            case 3: p1_task<3>(wd, op, b, ssum, ssq, vps, tid, lane); break;
            case 4: p1_task<4>(wd, op, b, ssum, ssq, vps, tid, lane); break;
            case 5: p1_task<5>(wd, op, b, ssum, ssq, vps, tid, lane); break;
            case 6: p1_task<6>(wd, op, b, ssum, ssq, vps, tid, lane); break;
            case 7: p1_task<7>(wd, op, b, ssum, ssq, vps, tid, lane); break;
            default: p1_task<8>(wd, op, b, ssum, ssq, vps, tid, lane); break;
        }
    }
    __syncthreads();
    if (tid < 12) {
        atomicAdd(&g_stats[tid],    (double)ssum[tid]);
        atomicAdd(&g_stats[12+tid], (double)ssq[tid]);
    }
}

// ---------------- Phase 2 task (templated on scale) ----------------
template<int II>
__device__ __forceinline__ void p2_task(const u64* __restrict__ wd, const float* __restrict__ V,
                                        int op, int b, int co0g,
                                        float* __restrict__ ssum, float* __restrict__ ssq,
                                        float2 (*__restrict__ vps)[128], int tid, int lane) {
    constexpr int SC = 1 << II;
    constexpr float INV = 1.f / (float)SC;
    #pragma unroll 1
    for (int pass = 0; pass < 2; pass++) {
        int px = 4*op + 2*pass;
        u64 acc[12][2];
        #pragma unroll
        for (int u = 0; u < 12; u++) { acc[u][0] = 0ull; acc[u][1] = 0ull; }
        for (int c = 0; c < 12; c++) {
            #pragma unroll
            for (int r = 0; r < 3; r++) {
                const float* pbx = &g_m1[(size_t)((c*9 + II + r)*25 + px)*NB + b];
                const u64* wk = &wd[(c*15 + r*5)*12];
                #pragma unroll
                for (int j = 0; j < 5; j++) {
                    const int off = (j-2)*SC;
                    if (off >= -23 && off <= 24) {     // compile-time prune
                        int x0 = px + off;
                        u64 a0 = ((unsigned)x0     < 25u) ? ld2(pbx + (ptrdiff_t)off*NB)      : 0ull;
                        u64 a1 = ((unsigned)(x0+1) < 25u) ? ld2(pbx + (ptrdiff_t)off*NB + NB) : 0ull;
                        const ulonglong2* wp = reinterpret_cast<const ulonglong2*>(wk + j*12);
                        #pragma unroll
                        for (int u2 = 0; u2 < 6; u2++) {
                            ulonglong2 ww = wp[u2];
                            acc[2*u2  ][0] = fma2(ww.x, a0, acc[2*u2  ][0]);
                            acc[2*u2  ][1] = fma2(ww.x, a1, acc[2*u2  ][1]);
                            acc[2*u2+1][0] = fma2(ww.y, a0, acc[2*u2+1][0]);
                            acc[2*u2+1][1] = fma2(ww.y, a1, acc[2*u2+1][1]);
                        }
                    }
                }
            }
        }
        #pragma unroll
        for (int u = 0; u < 12; u++) {
            float bias0 = 0.f, bias1 = 0.f;
            #pragma unroll
            for (int j = 0; j < 5; j++) {
                const int off = (j-2)*SC;
                if (off >= -23 && off <= 24) {
                    int x0 = px + off;
                    float vj = V[u*5 + j];
                    if ((unsigned)x0     < 25u) bias0 += vj;
                    if ((unsigned)(x0+1) < 25u) bias1 += vj;
                }
            }
            float2 p0 = up2(acc[u][0]), p1 = up2(acc[u][1]);
            float vx = fmaxf(fmaxf(p0.x + bias0, p1.x + bias1), 0.f)*INV;
            float vy = fmaxf(fmaxf(p0.y + bias0, p1.y + bias1), 0.f)*INV;
            if (pass == 0) {
                vps[u][tid] = make_float2(vx, vy);
            } else {
                float2 vp = vps[u][tid];
                *reinterpret_cast<float2*>(&g_m2[(size_t)(((co0g+u)*7+II)*6 + op)*NB + b]) =
                    make_float2(fmaxf(vp.x, vx), fmaxf(vp.y, vy));
                float su = wsum(vp.x + vp.y + vx + vy);
                float qu = wsum(vp.x*vp.x + vp.y*vp.y + vx*vx + vy*vy);
                if (lane == 0) { atomicAdd(&ssum[u], su); atomicAdd(&ssq[u], qu); }
            }
        }
    }
}

__global__ __launch_bounds__(128, 5) void k_p2(const float* __restrict__ w2,
                                               const float* __restrict__ g1,
                                               const float* __restrict__ b1) {
    __shared__ __align__(16) u64 wd[2160];    // [k*12 + u], scaled by A1[c]
    __shared__ float2 vps[12][128];
    __shared__ float A1[12], Bc[12], V[60];
    __shared__ float ssum[12], ssq[12];
    int tid = threadIdx.x, lane = tid & 31, wid = tid >> 5;
    int b = blockIdx.x * 64 + lane * 2;
    int cog = blockIdx.y & 1;
    int tg  = blockIdx.y >> 1;
    int co0g = cog * 12;
    if (tid < 12) {
        double m = g_stats[tid] / 1843200.0;
        double v = g_stats[12+tid] / 1843200.0 - m*m;
        float a = g1[tid] * rsqrtf((float)v + EPSF);
        A1[tid] = a;
        Bc[tid] = b1[tid] - (float)m*a;
        ssum[tid] = 0.f; ssq[tid] = 0.f;
    }
    __syncthreads();
    for (int i = tid; i < 2160; i += 128) {
        int u = i/180, k = i%180, c = k/15;
        wd[k*12+u] = dupw(w2[(co0g+u)*180 + k] * A1[c]);
    }
    for (int i = tid; i < 60; i += 128) {
        int u = i / 5, j = i % 5;
        float acc = 0.f;
        for (int c = 0; c < 12; c++) {
            float bc = Bc[c];
            for (int r = 0; r < 3; r++) acc += w2[(co0g+u)*180 + c*15 + r*5 + j] * bc;
        }
        V[i] = acc;
    }
    __syncthreads();
    int t = tg * 4 + wid;                     // 0..43
    if (t < 42) {
        int ii = t / 6, op = t % 6;
        switch (ii) {
            case 0: p2_task<0>(wd, V, op, b, co0g, ssum, ssq, vps, tid, lane); break;
            case 1: p2_task<1>(wd, V, op, b, co0g, ssum, ssq, vps, tid, lane); break;
            case 2: p2_task<2>(wd, V, op, b, co0g, ssum, ssq, vps, tid, lane); break;
            case 3: p2_task<3>(wd, V, op, b, co0g, ssum, ssq, vps, tid, lane); break;
            case 4: p2_task<4>(wd, V, op, b, co0g, ssum, ssq, vps, tid, lane); break;
            case 5: p2_task<5>(wd, V, op, b, co0g, ssum, ssq, vps, tid, lane); break;
            default: p2_task<6>(wd, V, op, b, co0g, ssum, ssq, vps, tid, lane); break;
        }
    }
    __syncthreads();
    if (tid < 12) {
        atomicAdd(&g_stats[24+co0g+tid], (double)ssum[tid]);
        atomicAdd(&g_stats[48+co0g+tid], (double)ssq[tid]);
    }
}

// ---------------- Phase 3 task (templated on scale) ----------------
template<int II>
__device__ __forceinline__ void p3_task(const u64* __restrict__ wd3, const float* __restrict__ V,
                                        int pr, int b, int cbase,
                                        float* __restrict__ ssum, float* __restrict__ ssq, int lane) {
    constexpr int SC = 1 << II;
    constexpr float INV = 1.f / (float)SC;
    int px = 2*pr;
    u64 acc[12][2];
    #pragma unroll
    for (int u = 0; u < 12; u++) { acc[u][0] = 0ull; acc[u][1] = 0ull; }
    for (int c = 0; c < 24; c++) {
        #pragma unroll
        for (int r = 0; r < 3; r++) {
            const float* pbx = &g_m2[(size_t)((c*7 + II + r)*6 + px)*NB + b];
            const u64* wk = &wd3[(c*15 + r*5)*12];
            #pragma unroll
            for (int j = 0; j < 5; j++) {
                const int off = (j-2)*SC;
                if (off >= -5 && off <= 5) {           // compile-time prune
                    int x0 = px + off;
                    u64 a0 = ((unsigned)x0     < 6u) ? ld2(pbx + (ptrdiff_t)off*NB)      : 0ull;
                    u64 a1 = ((unsigned)(x0+1) < 6u) ? ld2(pbx + (ptrdiff_t)off*NB + NB) : 0ull;
                    const ulonglong2* wp = reinterpret_cast<const ulonglong2*>(wk + j*12);
                    #pragma unroll
                    for (int u2 = 0; u2 < 6; u2++) {
                        ulonglong2 ww = wp[u2];
                        acc[2*u2  ][0] = fma2(ww.x, a0, acc[2*u2  ][0]);
                        acc[2*u2  ][1] = fma2(ww.x, a1, acc[2*u2  ][1]);
                        acc[2*u2+1][0] = fma2(ww.y, a0, acc[2*u2+1][0]);
                        acc[2*u2+1][1] = fma2(ww.y, a1, acc[2*u2+1][1]);
                    }
                }
            }
        }
    }
    #pragma unroll
    for (int u = 0; u < 12; u++) {
        float bias0 = 0.f, bias1 = 0.f;
        #pragma unroll
        for (int j = 0; j < 5; j++) {
            const int off = (j-2)*SC;
            if (off >= -5 && off <= 5) {
                int x0 = px + off;
                float vj = V[u*5 + j];
                if ((unsigned)x0     < 6u) bias0 += vj;
                if ((unsigned)(x0+1) < 6u) bias1 += vj;
            }
        }
        float2 p0 = up2(acc[u][0]), p1 = up2(acc[u][1]);
        float vx = fmaxf(fmaxf(p0.x + bias0, p1.x + bias1), 0.f)*INV;
        float vy = fmaxf(fmaxf(p0.y + bias0, p1.y + bias1), 0.f)*INV;
        *reinterpret_cast<float2*>(&g_a3[(size_t)((cbase+u)*15 + II*3 + pr)*NB + b]) =
            make_float2(vx, vy);
        float su = wsum(vx + vy);
        float qu = wsum(vx*vx + vy*vy);
        if (lane == 0) { atomicAdd(&ssum[u], su); atomicAdd(&ssq[u], qu); }
    }
}

__global__ __launch_bounds__(128, 5) void k_p3(const float* __restrict__ w3,
                                               const float* __restrict__ g2,
                                               const float* __restrict__ b2) {
    __shared__ __align__(16) u64 wd3[4320];   // [k*12 + u], scaled by A2[c]
    __shared__ float A2[24], Bc[24], V[60];
    __shared__ float ssum[12], ssq[12];
    int tid = threadIdx.x, lane = tid & 31, wid = tid >> 5;
    int b = blockIdx.x * 64 + lane * 2;
    int q  = blockIdx.y >> 2;
    int tg = blockIdx.y & 3;
    int cbase = q * 12;
    if (tid < 24) {
        double m = g_stats[24+tid] / 344064.0;
        double v = g_stats[48+tid] / 344064.0 - m*m;
        float a = g2[tid] * rsqrtf((float)v + EPSF);
        A2[tid] = a;
        Bc[tid] = b2[tid] - (float)m*a;
    }
    if (tid < 12) { ssum[tid] = 0.f; ssq[tid] = 0.f; }
    __syncthreads();
    for (int i = tid; i < 4320; i += 128) {
        int u = i/360, k = i%360, c = k/15;
        wd3[k*12+u] = dupw(w3[(cbase+u)*360 + k] * A2[c]);
    }
    for (int i = tid; i < 60; i += 128) {
        int u = i / 5, j = i % 5;
        float acc = 0.f;
        for (int c = 0; c < 24; c++) {
            float bc = Bc[c];
            for (int r = 0; r < 3; r++) acc += w3[(cbase+u)*360 + c*15 + r*5 + j] * bc;
        }
        V[i] = acc;
    }
    __syncthreads();
    int t = tg * 4 + wid;                     // 0..15
    if (t < 15) {
        int ii = t / 3, pr = t % 3;
        switch (ii) {
            case 0: p3_task<0>(wd3, V, pr, b, cbase, ssum, ssq, lane); break;
            case 1: p3_task<1>(wd3, V, pr, b, cbase, ssum, ssq, lane); break;
            case 2: p3_task<2>(wd3, V, pr, b, cbase, ssum, ssq, lane); break;
            case 3: p3_task<3>(wd3, V, pr, b, cbase, ssum, ssq, lane); break;
            default: p3_task<4>(wd3, V, pr, b, cbase, ssum, ssq, lane); break;
        }
    }
    __syncthreads();
    if (tid < 12) {
        atomicAdd(&g_stats[72+cbase+tid],  (double)ssum[tid]);
        atomicAdd(&g_stats[120+cbase+tid], (double)ssq[tid]);
    }
}

// ---------------- Phase 4: fully compile-time pruned (px=0) ----------------
__global__ __launch_bounds__(128, 5) void k_p4(const float* __restrict__ w4,
                                               const float* __restrict__ g3,
                                               const float* __restrict__ b3) {
    __shared__ __align__(16) u64 wd4[5184];   // [k*12 + u], scaled by A3[c]
    __shared__ float A3[48], Bc[48], V[36];
    __shared__ float ssum[12], ssq[12];
    int tid = threadIdx.x, lane = tid & 31, wid = tid >> 5;
    int b = blockIdx.x * 64 + lane * 2;
    int cbase = blockIdx.y * 12;
    if (tid < 48) {
        double m = g_stats[72+tid] / 61440.0;
        double v = g_stats[120+tid] / 61440.0 - m*m;
        float a = g3[tid] * rsqrtf((float)v + EPSF);
        A3[tid] = a;
        Bc[tid] = b3[tid] - (float)m*a;
    }
    if (tid < 12) { ssum[tid] = 0.f; ssq[tid] = 0.f; }
    __syncthreads();
    for (int i = tid; i < 5184; i += 128) {
        int u = i/432, k = i%432, c = k/9;
        wd4[k*12+u] = dupw(w4[(cbase+u)*432 + k] * A3[c]);
    }
    for (int i = tid; i < 36; i += 128) {
        int u = i / 3, j = i % 3;
        float acc = 0.f;
        for (int c = 0; c < 48; c++) {
            float bc = Bc[c];
            for (int r = 0; r < 3; r++) acc += w4[(cbase+u)*432 + c*9 + r*3 + j] * bc;
        }
        V[i] = acc;
    }
    __syncthreads();
    int cog = wid >> 1;     // 0..1 (co-tile 6)
    int unit = wid & 1;
    int co0 = cog * 6;
    if (unit == 0) {
        // ii = 0 (s=1) and ii = 1 (s=2); all bounds compile-time, 6 loads per (c,r).
        u64 acc[6][2][2];
        #pragma unroll
        for (int u = 0; u < 6; u++)
            #pragma unroll
            for (int i2 = 0; i2 < 2; i2++) { acc[u][i2][0] = 0ull; acc[u][i2][1] = 0ull; }
        for (int c = 0; c < 48; c++) {
            #pragma unroll
            for (int r = 0; r < 3; r++) {
                const float* pb0 = &g_a3[(size_t)((c*5 + 0 + r)*3)*NB + b];
                const float* pb1 = &g_a3[(size_t)((c*5 + 1 + r)*3)*NB + b];
                const u64* wk = &wd4[(c*9 + r*3)*12 + co0];
                u64 v00 = ld2(pb0), v01 = ld2(pb0 + NB), v02 = ld2(pb0 + 2*NB);
                u64 v10 = ld2(pb1), v11 = ld2(pb1 + NB), v12 = ld2(pb1 + 2*NB);
                const ulonglong2* w0p = reinterpret_cast<const ulonglong2*>(wk);
                const ulonglong2* w1p = reinterpret_cast<const ulonglong2*>(wk + 12);
                const ulonglong2* w2p = reinterpret_cast<const ulonglong2*>(wk + 24);
                #pragma unroll
                for (int u2 = 0; u2 < 3; u2++) {
                    ulonglong2 ww0 = w0p[u2], ww1 = w1p[u2], ww2 = w2p[u2];
                    // j=0 (off -1/-2): ii0 pos1 only (x=0)
                    acc[2*u2  ][0][1] = fma2(ww0.x, v00, acc[2*u2  ][0][1]);
                    acc[2*u2+1][0][1] = fma2(ww0.y, v00, acc[2*u2+1][0][1]);
                    // j=1 (off 0): ii0 x={0,1}; ii1 x={0,1}
                    acc[2*u2  ][0][0] = fma2(ww1.x, v00, acc[2*u2  ][0][0]);
                    acc[2*u2  ][0][1] = fma2(ww1.x, v01, acc[2*u2  ][0][1]);
                    acc[2*u2  ][1][0] = fma2(ww1.x, v10, acc[2*u2  ][1][0]);
                    acc[2*u2  ][1][1] = fma2(ww1.x, v11, acc[2*u2  ][1][1]);
                    acc[2*u2+1][0][0] = fma2(ww1.y, v00, acc[2*u2+1][0][0]);
                    acc[2*u2+1][0][1] = fma2(ww1.y, v01, acc[2*u2+1][0][1]);
                    acc[2*u2+1][1][0] = fma2(ww1.y, v10, acc[2*u2+1][1][0]);
                    acc[2*u2+1][1][1] = fma2(ww1.y, v11, acc[2*u2+1][1][1]);
                    // j=2 (off +1/+2): ii0 x={1,2}; ii1 x=2 (pos0 only)
                    acc[2*u2  ][0][0] = fma2(ww2.x, v01, acc[2*u2  ][0][0]);
                    acc[2*u2  ][0][1] = fma2(ww2.x, v02, acc[2*u2  ][0][1]);
                    acc[2*u2  ][1][0] = fma2(ww2.x, v12, acc[2*u2  ][1][0]);
                    acc[2*u2+1][0][0] = fma2(ww2.y, v01, acc[2*u2+1][0][0]);
                    acc[2*u2+1][0][1] = fma2(ww2.y, v02, acc[2*u2+1][0][1]);
                    acc[2*u2+1][1][0] = fma2(ww2.y, v12, acc[2*u2+1][1][0]);
                }
            }
        }
        #pragma unroll
        for (int i2 = 0; i2 < 2; i2++) {
            int sc = 1 << i2;
            float inv = (i2 == 0) ? 1.f : 0.5f;
            #pragma unroll
            for (int u = 0; u < 6; u++) {
                float bias0 = 0.f, bias1 = 0.f;
                #pragma unroll
                for (int j = 0; j < 3; j++) {
                    int x0 = (j-1)*sc;
                    float vj = V[(co0+u)*3 + j];
                    if (x0   >= 0 && x0   < 3) bias0 += vj;
                    if (x0+1 >= 0 && x0+1 < 3) bias1 += vj;
                }
                float2 p0 = up2(acc[u][i2][0]), p1 = up2(acc[u][i2][1]);
                float vx = fmaxf(fmaxf(p0.x + bias0, p1.x + bias1), 0.f)*inv;
                float vy = fmaxf(fmaxf(p0.y + bias0, p1.y + bias1), 0.f)*inv;
                *reinterpret_cast<float2*>(&g_a4T[(size_t)((cbase+co0+u)*3 + i2)*NB + b]) =
                    make_float2(vx, vy);
                float su = wsum(vx + vy);
                float qu = wsum(vx*vx + vy*vy);
                if (lane == 0) { atomicAdd(&ssum[co0+u], su); atomicAdd(&ssq[co0+u], qu); }
            }
        }
    } else {
        // ii = 2 (s=4): only j=1 survives.
        u64 acc[6][2];
        #pragma unroll
        for (int u = 0; u < 6; u++) { acc[u][0] = 0ull; acc[u][1] = 0ull; }
        for (int c = 0; c < 48; c++) {
            #pragma unroll
            for (int r = 0; r < 3; r++) {
                const float* pb = &g_a3[(size_t)((c*5 + 2 + r)*3)*NB + b];
                const u64* wk = &wd4[(c*9 + r*3)*12 + co0];
                u64 v0 = ld2(pb), v1 = ld2(pb + NB);
                const ulonglong2* wp = reinterpret_cast<const ulonglong2*>(wk + 12);  // j=1
                #pragma unroll
                for (int u2 = 0; u2 < 3; u2++) {
                    ulonglong2 ww = wp[u2];
                    acc[2*u2  ][0] = fma2(ww.x, v0, acc[2*u2  ][0]);
                    acc[2*u2  ][1] = fma2(ww.x, v1, acc[2*u2  ][1]);
                    acc[2*u2+1][0] = fma2(ww.y, v0, acc[2*u2+1][0]);
                    acc[2*u2+1][1] = fma2(ww.y, v1, acc[2*u2+1][1]);
                }
            }
        }
        #pragma unroll
        for (int u = 0; u < 6; u++) {
            float vj = V[(co0+u)*3 + 1];     // only j=1 in bounds for x=0 and x=1
            float2 p0 = up2(acc[u][0]), p1 = up2(acc[u][1]);
            float vx = fmaxf(fmaxf(p0.x + vj, p1.x + vj), 0.f)*0.25f;
            float vy = fmaxf(fmaxf(p0.y + vj, p1.y + vj), 0.f)*0.25f;
            *reinterpret_cast<float2*>(&g_a4T[(size_t)((cbase+co0+u)*3 + 2)*NB + b]) =
                make_float2(vx, vy);
            float su = wsum(vx + vy);
            float qu = wsum(vx*vx + vy*vy);
            if (lane == 0) { atomicAdd(&ssum[co0+u], su); atomicAdd(&ssq[co0+u], qu); }
        }
    }
    __syncthreads();
    if (tid < 12) {
        atomicAdd(&g_stats[168+cbase+tid], (double)ssum[tid]);
        atomicAdd(&g_stats[264+cbase+tid], (double)ssq[tid]);
    }
}

// ---------------- Phase 5a: bn4 affine + collapse 3 FCs into (6x288) + bias ----------------
__global__ __launch_bounds__(256) void k_phase5a(const float* __restrict__ g4, const float* __restrict__ b4,
                                                 const float* __restrict__ f1w, const float* __restrict__ f1b,
                                                 const float* __restrict__ f2w, const float* __restrict__ f2b,
                                                 const float* __restrict__ f3w, const float* __restrict__ f3b) {
    __shared__ float A4[96], B4[96], W23[576], bcs[6];
    int tid = threadIdx.x;
    if (tid < 96) {
        double m = g_stats[168+tid] / 12288.0;
        double v = g_stats[264+tid] / 12288.0 - m*m;
        float a = g4[tid] * rsqrtf((float)v + EPSF);
        A4[tid] = a; B4[tid] = b4[tid] - (float)m*a;
    }
    if (tid < 6) bcs[tid] = 0.f;
    for (int idx = tid; idx < 576; idx += 256) {
        int j = idx / 96, k = idx % 96;
        float s = 0.f;
        for (int l = 0; l < 48; l++) s += f3w[j*48 + l] * f2w[l*96 + k];
        W23[idx] = s;
    }
    __syncthreads();
    for (int idx = tid; idx < 1728; idx += 256) {
        int j = idx / 288, i = idx % 288;
        int c = i / 3;
        float s0 = 0.f;
        for (int k = 0; k < 96; k++) s0 += W23[j*96 + k] * f1w[k*288 + i];
        g_Wc[idx] = s0 * A4[c];
        atomicAdd(&bcs[j], s0 * B4[c]);
    }
    __syncthreads();
    if (tid < 6) {
        int j = tid;
        float bb = f3b[j];
        for (int l = 0; l < 48; l++) bb += f3w[j*48 + l] * f2b[l];
        for (int k = 0; k < 96; k++) bb += W23[j*96 + k] * f1b[k];
        g_bc[j] = bcs[j] + bb;
    }
}

// ---------------- Phase 5b: out[b][6] from a4T planes, 4 samples/thread ----------------
__global__ __launch_bounds__(256) void k_phase5b(float* __restrict__ out) {
    __shared__ float Wcs[1728];
    for (int i = threadIdx.x; i < 1728; i += 256) Wcs[i] = g_Wc[i];
    __syncthreads();
    int b = (blockIdx.x*256 + threadIdx.x)*4;
    float acc[6][4];
    #pragma unroll
    for (int j = 0; j < 6; j++)
        #pragma unroll
        for (int m = 0; m < 4; m++) acc[j][m] = g_bc[j];
    for (int f = 0; f < 288; f++) {
        float4 v = *reinterpret_cast<const float4*>(&g_a4T[(size_t)f*NB + b]);
        #pragma unroll
        for (int j = 0; j < 6; j++) {
            float w = Wcs[j*288 + f];
            acc[j][0] += v.x*w; acc[j][1] += v.y*w; acc[j][2] += v.z*w; acc[j][3] += v.w*w;
        }
    }
    #pragma unroll
    for (int m = 0; m < 4; m++)
        #pragma unroll
        for (int j = 0; j < 6; j++)
            out[(b+m)*6 + j] = acc[j][m];
}

// ---------------- launcher ----------------
extern "C" void kernel_launch(void* const* d_in, const int* in_sizes, int n_in,
                              void* d_out, int out_size) {
    const float* x   = (const float*)d_in[0];
    const float* w1  = (const float*)d_in[1];
    const float* w2  = (const float*)d_in[2];
    const float* w3  = (const float*)d_in[3];
    const float* w4  = (const float*)d_in[4];
    const float* g1  = (const float*)d_in[5];
    const float* b1  = (const float*)d_in[6];
    const float* g2  = (const float*)d_in[7];
    const float* b2  = (const float*)d_in[8];
    const float* g3  = (const float*)d_in[9];
    const float* b3  = (const float*)d_in[10];
    const float* g4  = (const float*)d_in[11];
    const float* b4  = (const float*)d_in[12];
    const float* f1w = (const float*)d_in[13];
    const float* f1b = (const float*)d_in[14];
    const float* f2w = (const float*)d_in[15];
    const float* f2b = (const float*)d_in[16];
    const float* f3w = (const float*)d_in[17];
    const float* f3b = (const float*)d_in[18];
    float* out = (float*)d_out;

    // NOTE: launch order puts k_p2 4th — the profiler captures the 4th launch.
    k_zero<<<1, 384>>>();
    k_tr<<<dim3(128, 19), dim3(32, 8)>>>(x);
    k_p1<<<dim3(64, 57), 128>>>(w1);
    k_p2<<<dim3(64, 22), 128>>>(w2, g1, b1);
    k_p3<<<dim3(64, 16), 128>>>(w3, g2, b2);
    k_p4<<<dim3(64, 8), 128>>>(w4, g3, b3);
    k_phase5a<<<1, 256>>>(g4, b4, f1w, f1b, f2w, f2b, f3w, f3b);
    k_phase5b<<<4, 256>>>(out);
}

// round 12
// speedup vs baseline: 1.7016x; 1.0649x over previous
#include <cuda_runtime.h>

#define EPSF 2e-5f
#define NB 4096

typedef unsigned long long u64;

__device__ __forceinline__ u64 ld2(const float* p) {
    return *reinterpret_cast<const u64*>(p);
}
__device__ __forceinline__ ulonglong2 ld4(const float* p) {
    return *reinterpret_cast<const ulonglong2*>(p);
}
__device__ __forceinline__ u64 fma2(u64 a, u64 b, u64 c) {
    u64 d;
    asm("fma.rn.f32x2 %0, %1, %2, %3;" : "=l"(d) : "l"(a), "l"(b), "l"(c));
    return d;
}
__device__ __forceinline__ float2 up2(u64 v) {
    float2 r;
    asm("mov.b64 {%0,%1}, %2;" : "=f"(r.x), "=f"(r.y) : "l"(v));
    return r;
}
__device__ __forceinline__ u64 dupw(float w) {
    u64 d;
    asm("mov.b64 %0, {%1,%1};" : "=l"(d) : "f"(w));
    return d;
}
__device__ __forceinline__ float wsum(float v) {
    #pragma unroll
    for (int o = 16; o; o >>= 1) v += __shfl_down_sync(0xffffffffu, v, o);
    return v;
}

// ---------------- scratch planes, [feature][batch] ----------------
__device__ __align__(16) float  g_xT [600*NB];   // [c*100 + t][b]
__device__ __align__(16) float  g_m1 [2700*NB];  // (12,9,25) double-pooled relu'd lift (pre-bn)
__device__ __align__(16) float  g_m2 [1008*NB];  // (24,7,6)  double-pooled relu'd conv2 (pre-bn)
__device__ __align__(16) float  g_a3 [720*NB];   // (48,5,3)  pooled relu'd conv3 (pre-bn)
__device__ __align__(16) float  g_a4T[288*NB];   // (96,3)    pooled relu'd conv4 (pre-bn)
__device__ double g_stats[360];
__device__ float  g_Wc[6*288];
__device__ float  g_bc[6];

__global__ void k_zero() {
    int t = threadIdx.x;
    if (t < 360) g_stats[t] = 0.0;
}

// ---------------- transpose x (4096,600) -> xT [c*100+t][b] ----------------
__global__ void k_tr(const float* __restrict__ x) {
    __shared__ float tile[32][33];
    int bx = blockIdx.x * 32;
    int fy = blockIdx.y * 32;
    int tx = threadIdx.x, ty = threadIdx.y;
    #pragma unroll
    for (int m = 0; m < 4; m++) {
        int ff = fy + tx;
        tile[ty + m*8][tx] = (ff < 600) ? x[(bx + ty + m*8)*600 + ff] : 0.f;
    }
    __syncthreads();
    #pragma unroll
    for (int m = 0; m < 4; m++) {
        int ff = fy + ty + m*8;
        if (ff < 600) {
            int c = ff % 6, t = ff / 6;
            g_xT[(size_t)(c*100 + t)*NB + bx + tx] = tile[tx][ty + m*8];
        }
    }
}

// ---------------- Phase 1 task: 4 samples/thread, co-tile 6 ----------------
template<int HH>
__device__ __forceinline__ void p1_task(const u64* __restrict__ wd, int op, int b, int co0,
                                        float* __restrict__ ssum, float* __restrict__ ssq,
                                        float4 (*__restrict__ vps)[128], int tid, int lane) {
    constexpr int SC = 1 << HH;
    constexpr float INV = 1.f / (float)SC;
    #pragma unroll 1
    for (int pass = 0; pass < 2; pass++) {
        int px = 4*op + 2*pass;
        u64 acc[6][2][2];
        #pragma unroll
        for (int u = 0; u < 6; u++)
            #pragma unroll
            for (int p = 0; p < 2; p++) { acc[u][p][0] = 0ull; acc[u][p][1] = 0ull; }
        #pragma unroll
        for (int c = 0; c < 6; c++) {
            const float* pbx = &g_xT[(size_t)(c*100 + px)*NB + b];
            #pragma unroll
            for (int j = 0; j < 7; j++) {
                const int off = (j-3)*SC;
                if (off >= -99 && off <= 99) {
                    int x0 = px + off;
                    ulonglong2 z = make_ulonglong2(0ull, 0ull);
                    ulonglong2 a0 = ((unsigned)x0     < 100u) ? ld4(pbx + (ptrdiff_t)off*NB)      : z;
                    ulonglong2 a1 = ((unsigned)(x0+1) < 100u) ? ld4(pbx + (ptrdiff_t)off*NB + NB) : z;
                    const ulonglong2* wp = reinterpret_cast<const ulonglong2*>(&wd[(c*7 + j)*6]);
                    #pragma unroll
                    for (int u2 = 0; u2 < 3; u2++) {
                        ulonglong2 ww = wp[u2];
                        acc[2*u2  ][0][0] = fma2(ww.x, a0.x, acc[2*u2  ][0][0]);
                        acc[2*u2  ][0][1] = fma2(ww.x, a0.y, acc[2*u2  ][0][1]);
                        acc[2*u2  ][1][0] = fma2(ww.x, a1.x, acc[2*u2  ][1][0]);
                        acc[2*u2  ][1][1] = fma2(ww.x, a1.y, acc[2*u2  ][1][1]);
                        acc[2*u2+1][0][0] = fma2(ww.y, a0.x, acc[2*u2+1][0][0]);
                        acc[2*u2+1][0][1] = fma2(ww.y, a0.y, acc[2*u2+1][0][1]);
                        acc[2*u2+1][1][0] = fma2(ww.y, a1.x, acc[2*u2+1][1][0]);
                        acc[2*u2+1][1][1] = fma2(ww.y, a1.y, acc[2*u2+1][1][1]);
                    }
                }
            }
        }
        #pragma unroll
        for (int u = 0; u < 6; u++) {
            float2 q00 = up2(acc[u][0][0]), q01 = up2(acc[u][0][1]);
            float2 q10 = up2(acc[u][1][0]), q11 = up2(acc[u][1][1]);
            float v0 = fmaxf(fmaxf(q00.x, q10.x), 0.f)*INV;
            float v1 = fmaxf(fmaxf(q00.y, q10.y), 0.f)*INV;
            float v2 = fmaxf(fmaxf(q01.x, q11.x), 0.f)*INV;
            float v3 = fmaxf(fmaxf(q01.y, q11.y), 0.f)*INV;
            if (pass == 0) {
                vps[u][tid] = make_float4(v0, v1, v2, v3);
            } else {
                float4 vp = vps[u][tid];
                *reinterpret_cast<float4*>(&g_m1[(size_t)(((co0+u)*9+HH)*25 + op)*NB + b]) =
                    make_float4(fmaxf(vp.x, v0), fmaxf(vp.y, v1), fmaxf(vp.z, v2), fmaxf(vp.w, v3));
                float su = wsum(vp.x + vp.y + vp.z + vp.w + v0 + v1 + v2 + v3);
                float qu = wsum(vp.x*vp.x + vp.y*vp.y + vp.z*vp.z + vp.w*vp.w
                                + v0*v0 + v1*v1 + v2*v2 + v3*v3);
                if (lane == 0) { atomicAdd(&ssum[u], su); atomicAdd(&ssq[u], qu); }
            }
        }
    }
}

__global__ __launch_bounds__(128, 5) void k_p1(const float* __restrict__ w1) {
    __shared__ __align__(16) u64 wd[252];     // [(c*7+j)*6 + u]
    __shared__ float4 vps[6][128];
    __shared__ float ssum[6], ssq[6];
    int tid = threadIdx.x, lane = tid & 31, wid = tid >> 5;
    int b = blockIdx.x * 128 + lane * 4;
    int cog = blockIdx.y & 1;
    int tg  = blockIdx.y >> 1;
    int co0 = cog * 6;
    for (int i = tid; i < 252; i += 128) { int k = i/6, u = i%6; wd[i] = dupw(w1[(co0+u)*42 + k]); }
    if (tid < 6) { ssum[tid] = 0.f; ssq[tid] = 0.f; }
    __syncthreads();
    int t = tg * 4 + wid;             // 0..227
    if (t < 225) {
        int hh = t / 25, op = t % 25;
        switch (hh) {
            case 0: p1_task<0>(wd, op, b, co0, ssum, ssq, vps, tid, lane); break;
            case 1: p1_task<1>(wd, op, b, co0, ssum, ssq, vps, tid, lane); break;
            case 2: p1_task<2>(wd, op, b, co0, ssum, ssq, vps, tid, lane); break;
            case 3: p1_task<3>(wd, op, b, co0, ssum, ssq, vps, tid, lane); break;
            case 4: p1_task<4>(wd, op, b, co0, ssum, ssq, vps, tid, lane); break;
            case 5: p1_task<5>(wd, op, b, co0, ssum, ssq, vps, tid, lane); break;
            case 6: p1_task<6>(wd, op, b, co0, ssum, ssq, vps, tid, lane); break;
            case 7: p1_task<7>(wd, op, b, co0, ssum, ssq, vps, tid, lane); break;
            default: p1_task<8>(wd, op, b, co0, ssum, ssq, vps, tid, lane); break;
        }
    }
    __syncthreads();
    if (tid < 6) {
        atomicAdd(&g_stats[co0+tid],    (double)ssum[tid]);
        atomicAdd(&g_stats[12+co0+tid], (double)ssq[tid]);
    }
}

// ---------------- Phase 2 task: 4 samples/thread, co-tile 6 ----------------
template<int II>
__device__ __forceinline__ void p2_task(const u64* __restrict__ wd, const float* __restrict__ V,
                                        int op, int b, int co0g,
                                        float* __restrict__ ssum, float* __restrict__ ssq,
                                        float4 (*__restrict__ vps)[128], int tid, int lane) {
    constexpr int SC = 1 << II;
    constexpr float INV = 1.f / (float)SC;
    #pragma unroll 1
    for (int pass = 0; pass < 2; pass++) {
        int px = 4*op + 2*pass;
        u64 acc[6][2][2];
        #pragma unroll
        for (int u = 0; u < 6; u++)
            #pragma unroll
            for (int p = 0; p < 2; p++) { acc[u][p][0] = 0ull; acc[u][p][1] = 0ull; }
        for (int c = 0; c < 12; c++) {
            #pragma unroll
            for (int r = 0; r < 3; r++) {
                const float* pbx = &g_m1[(size_t)((c*9 + II + r)*25 + px)*NB + b];
                const u64* wk = &wd[(c*15 + r*5)*6];
                #pragma unroll
                for (int j = 0; j < 5; j++) {
                    const int off = (j-2)*SC;
                    if (off >= -23 && off <= 24) {
                        int x0 = px + off;
                        ulonglong2 z = make_ulonglong2(0ull, 0ull);
                        ulonglong2 a0 = ((unsigned)x0     < 25u) ? ld4(pbx + (ptrdiff_t)off*NB)      : z;
                        ulonglong2 a1 = ((unsigned)(x0+1) < 25u) ? ld4(pbx + (ptrdiff_t)off*NB + NB) : z;
                        const ulonglong2* wp = reinterpret_cast<const ulonglong2*>(wk + j*6);
                        #pragma unroll
                        for (int u2 = 0; u2 < 3; u2++) {
                            ulonglong2 ww = wp[u2];
                            acc[2*u2  ][0][0] = fma2(ww.x, a0.x, acc[2*u2  ][0][0]);
                            acc[2*u2  ][0][1] = fma2(ww.x, a0.y, acc[2*u2  ][0][1]);
                            acc[2*u2  ][1][0] = fma2(ww.x, a1.x, acc[2*u2  ][1][0]);
                            acc[2*u2  ][1][1] = fma2(ww.x, a1.y, acc[2*u2  ][1][1]);
                            acc[2*u2+1][0][0] = fma2(ww.y, a0.x, acc[2*u2+1][0][0]);
                            acc[2*u2+1][0][1] = fma2(ww.y, a0.y, acc[2*u2+1][0][1]);
                            acc[2*u2+1][1][0] = fma2(ww.y, a1.x, acc[2*u2+1][1][0]);
                            acc[2*u2+1][1][1] = fma2(ww.y, a1.y, acc[2*u2+1][1][1]);
                        }
                    }
                }
            }
        }
        #pragma unroll
        for (int u = 0; u < 6; u++) {
            float bias0 = 0.f, bias1 = 0.f;
            #pragma unroll
            for (int j = 0; j < 5; j++) {
                const int off = (j-2)*SC;
                if (off >= -23 && off <= 24) {
                    int x0 = px + off;
                    float vj = V[u*5 + j];
                    if ((unsigned)x0     < 25u) bias0 += vj;
                    if ((unsigned)(x0+1) < 25u) bias1 += vj;
                }
            }
            float2 q00 = up2(acc[u][0][0]), q01 = up2(acc[u][0][1]);
            float2 q10 = up2(acc[u][1][0]), q11 = up2(acc[u][1][1]);
            float v0 = fmaxf(fmaxf(q00.x + bias0, q10.x + bias1), 0.f)*INV;
            float v1 = fmaxf(fmaxf(q00.y + bias0, q10.y + bias1), 0.f)*INV;
            float v2 = fmaxf(fmaxf(q01.x + bias0, q11.x + bias1), 0.f)*INV;
            float v3 = fmaxf(fmaxf(q01.y + bias0, q11.y + bias1), 0.f)*INV;
            if (pass == 0) {
                vps[u][tid] = make_float4(v0, v1, v2, v3);
            } else {
                float4 vp = vps[u][tid];
                *reinterpret_cast<float4*>(&g_m2[(size_t)(((co0g+u)*7+II)*6 + op)*NB + b]) =
                    make_float4(fmaxf(vp.x, v0), fmaxf(vp.y, v1), fmaxf(vp.z, v2), fmaxf(vp.w, v3));
                float su = wsum(vp.x + vp.y + vp.z + vp.w + v0 + v1 + v2 + v3);
                float qu = wsum(vp.x*vp.x + vp.y*vp.y + vp.z*vp.z + vp.w*vp.w
                                + v0*v0 + v1*v1 + v2*v2 + v3*v3);
                if (lane == 0) { atomicAdd(&ssum[u], su); atomicAdd(&ssq[u], qu); }
            }
        }
    }
}

__global__ __launch_bounds__(128, 5) void k_p2(const float* __restrict__ w2,
                                               const float* __restrict__ g1,
                                               const float* __restrict__ b1) {
    __shared__ __align__(16) u64 wd[1080];    // [k*6 + u], scaled by A1[c]
    __shared__ float4 vps[6][128];
    __shared__ float A1[12], Bc[12], V[30];
    __shared__ float ssum[6], ssq[6];
    int tid = threadIdx.x, lane = tid & 31, wid = tid >> 5;
    int b = blockIdx.x * 128 + lane * 4;
    int cog = blockIdx.y & 3;
    int tg  = blockIdx.y >> 2;
    int co0g = cog * 6;
    if (tid < 12) {
        double m = g_stats[tid] / 1843200.0;
        double v = g_stats[12+tid] / 1843200.0 - m*m;
        float a = g1[tid] * rsqrtf((float)v + EPSF);
        A1[tid] = a;
        Bc[tid] = b1[tid] - (float)m*a;
    }
    if (tid < 6) { ssum[tid] = 0.f; ssq[tid] = 0.f; }
    __syncthreads();
    for (int i = tid; i < 1080; i += 128) {
        int k = i/6, u = i%6, c = k/15;
        wd[i] = dupw(w2[(co0g+u)*180 + k] * A1[c]);
    }
    for (int i = tid; i < 30; i += 128) {
        int u = i / 5, j = i % 5;
        float acc = 0.f;
        for (int c = 0; c < 12; c++) {
            float bc = Bc[c];
            for (int r = 0; r < 3; r++) acc += w2[(co0g+u)*180 + c*15 + r*5 + j] * bc;
        }
        V[i] = acc;
    }
    __syncthreads();
    int t = tg * 4 + wid;                     // 0..43
    if (t < 42) {
        int ii = t / 6, op = t % 6;
        switch (ii) {
            case 0: p2_task<0>(wd, V, op, b, co0g, ssum, ssq, vps, tid, lane); break;
            case 1: p2_task<1>(wd, V, op, b, co0g, ssum, ssq, vps, tid, lane); break;
            case 2: p2_task<2>(wd, V, op, b, co0g, ssum, ssq, vps, tid, lane); break;
            case 3: p2_task<3>(wd, V, op, b, co0g, ssum, ssq, vps, tid, lane); break;
            case 4: p2_task<4>(wd, V, op, b, co0g, ssum, ssq, vps, tid, lane); break;
            case 5: p2_task<5>(wd, V, op, b, co0g, ssum, ssq, vps, tid, lane); break;
            default: p2_task<6>(wd, V, op, b, co0g, ssum, ssq, vps, tid, lane); break;
        }
    }
    __syncthreads();
    if (tid < 6) {
        atomicAdd(&g_stats[24+co0g+tid], (double)ssum[tid]);
        atomicAdd(&g_stats[48+co0g+tid], (double)ssq[tid]);
    }
}

// ---------------- Phase 3 task: 4 samples/thread, co-tile 6 ----------------
template<int II>
__device__ __forceinline__ void p3_task(const u64* __restrict__ wd3, const float* __restrict__ V,
                                        int pr, int b, int cbase,
                                        float* __restrict__ ssum, float* __restrict__ ssq, int lane) {
    constexpr int SC = 1 << II;
    constexpr float INV = 1.f / (float)SC;
    int px = 2*pr;
    u64 acc[6][2][2];
    #pragma unroll
    for (int u = 0; u < 6; u++)
        #pragma unroll
        for (int p = 0; p < 2; p++) { acc[u][p][0] = 0ull; acc[u][p][1] = 0ull; }
    for (int c = 0; c < 24; c++) {
        #pragma unroll
        for (int r = 0; r < 3; r++) {
            const float* pbx = &g_m2[(size_t)((c*7 + II + r)*6 + px)*NB + b];
            const u64* wk = &wd3[(c*15 + r*5)*6];
            #pragma unroll
            for (int j = 0; j < 5; j++) {
                const int off = (j-2)*SC;
                if (off >= -5 && off <= 5) {
                    int x0 = px + off;
                    ulonglong2 z = make_ulonglong2(0ull, 0ull);
                    ulonglong2 a0 = ((unsigned)x0     < 6u) ? ld4(pbx + (ptrdiff_t)off*NB)      : z;
                    ulonglong2 a1 = ((unsigned)(x0+1) < 6u) ? ld4(pbx + (ptrdiff_t)off*NB + NB) : z;
                    const ulonglong2* wp = reinterpret_cast<const ulonglong2*>(wk + j*6);
                    #pragma unroll
                    for (int u2 = 0; u2 < 3; u2++) {
                        ulonglong2 ww = wp[u2];
                        acc[2*u2  ][0][0] = fma2(ww.x, a0.x, acc[2*u2  ][0][0]);
                        acc[2*u2  ][0][1] = fma2(ww.x, a0.y, acc[2*u2  ][0][1]);
                        acc[2*u2  ][1][0] = fma2(ww.x, a1.x, acc[2*u2  ][1][0]);
                        acc[2*u2  ][1][1] = fma2(ww.x, a1.y, acc[2*u2  ][1][1]);
                        acc[2*u2+1][0][0] = fma2(ww.y, a0.x, acc[2*u2+1][0][0]);
                        acc[2*u2+1][0][1] = fma2(ww.y, a0.y, acc[2*u2+1][0][1]);
                        acc[2*u2+1][1][0] = fma2(ww.y, a1.x, acc[2*u2+1][1][0]);
                        acc[2*u2+1][1][1] = fma2(ww.y, a1.y, acc[2*u2+1][1][1]);
                    }
                }
            }
        }
    }
    #pragma unroll
    for (int u = 0; u < 6; u++) {
        float bias0 = 0.f, bias1 = 0.f;
        #pragma unroll
        for (int j = 0; j < 5; j++) {
            const int off = (j-2)*SC;
            if (off >= -5 && off <= 5) {
                int x0 = px + off;
                float vj = V[u*5 + j];
                if ((unsigned)x0     < 6u) bias0 += vj;
                if ((unsigned)(x0+1) < 6u) bias1 += vj;
            }
        }
        float2 q00 = up2(acc[u][0][0]), q01 = up2(acc[u][0][1]);
        float2 q10 = up2(acc[u][1][0]), q11 = up2(acc[u][1][1]);
        float v0 = fmaxf(fmaxf(q00.x + bias0, q10.x + bias1), 0.f)*INV;
        float v1 = fmaxf(fmaxf(q00.y + bias0, q10.y + bias1), 0.f)*INV;
        float v2 = fmaxf(fmaxf(q01.x + bias0, q11.x + bias1), 0.f)*INV;
        float v3 = fmaxf(fmaxf(q01.y + bias0, q11.y + bias1), 0.f)*INV;
        *reinterpret_cast<float4*>(&g_a3[(size_t)((cbase+u)*15 + II*3 + pr)*NB + b]) =
            make_float4(v0, v1, v2, v3);
        float su = wsum(v0 + v1 + v2 + v3);
        float qu = wsum(v0*v0 + v1*v1 + v2*v2 + v3*v3);
        if (lane == 0) { atomicAdd(&ssum[u], su); atomicAdd(&ssq[u], qu); }
    }
}

__global__ __launch_bounds__(128, 5) void k_p3(const float* __restrict__ w3,
                                               const float* __restrict__ g2,
                                               const float* __restrict__ b2) {
    __shared__ __align__(16) u64 wd3[2160];   // [k*6 + u], scaled by A2[c]
    __shared__ float A2[24], Bc[24], V[30];
    __shared__ float ssum[6], ssq[6];
    int tid = threadIdx.x, lane = tid & 31, wid = tid >> 5;
    int b = blockIdx.x * 128 + lane * 4;
    int q  = blockIdx.y >> 2;                 // 0..7
    int tg = blockIdx.y & 3;
    int cbase = q * 6;
    if (tid < 24) {
        double m = g_stats[24+tid] / 344064.0;
        double v = g_stats[48+tid] / 344064.0 - m*m;
        float a = g2[tid] * rsqrtf((float)v + EPSF);
        A2[tid] = a;
        Bc[tid] = b2[tid] - (float)m*a;
    }
    if (tid < 6) { ssum[tid] = 0.f; ssq[tid] = 0.f; }
    __syncthreads();
    for (int i = tid; i < 2160; i += 128) {
        int k = i/6, u = i%6, c = k/15;
        wd3[i] = dupw(w3[(cbase+u)*360 + k] * A2[c]);
    }
    for (int i = tid; i < 30; i += 128) {
        int u = i / 5, j = i % 5;
        float acc = 0.f;
        for (int c = 0; c < 24; c++) {
            float bc = Bc[c];
            for (int r = 0; r < 3; r++) acc += w3[(cbase+u)*360 + c*15 + r*5 + j] * bc;
        }
        V[i] = acc;
    }
    __syncthreads();
    int t = tg * 4 + wid;                     // 0..15
    if (t < 15) {
        int ii = t / 3, pr = t % 3;
        switch (ii) {
            case 0: p3_task<0>(wd3, V, pr, b, cbase, ssum, ssq, lane); break;
            case 1: p3_task<1>(wd3, V, pr, b, cbase, ssum, ssq, lane); break;
            case 2: p3_task<2>(wd3, V, pr, b, cbase, ssum, ssq, lane); break;
            case 3: p3_task<3>(wd3, V, pr, b, cbase, ssum, ssq, lane); break;
            default: p3_task<4>(wd3, V, pr, b, cbase, ssum, ssq, lane); break;
        }
    }
    __syncthreads();
    if (tid < 6) {
        atomicAdd(&g_stats[72+cbase+tid],  (double)ssum[tid]);
        atomicAdd(&g_stats[120+cbase+tid], (double)ssq[tid]);
    }
}

// ---------------- Phase 4: fully compile-time pruned (2 samples/thread) ----------------
__global__ __launch_bounds__(128, 5) void k_p4(const float* __restrict__ w4,
                                               const float* __restrict__ g3,
                                               const float* __restrict__ b3) {
    __shared__ __align__(16) u64 wd4[5184];   // [k*12 + u], scaled by A3[c]
    __shared__ float A3[48], Bc[48], V[36];
    __shared__ float ssum[12], ssq[12];
    int tid = threadIdx.x, lane = tid & 31, wid = tid >> 5;
    int b = blockIdx.x * 64 + lane * 2;
    int cbase = blockIdx.y * 12;
    if (tid < 48) {
        double m = g_stats[72+tid] / 61440.0;
        double v = g_stats[120+tid] / 61440.0 - m*m;
        float a = g3[tid] * rsqrtf((float)v + EPSF);
        A3[tid] = a;
        Bc[tid] = b3[tid] - (float)m*a;
    }
    if (tid < 12) { ssum[tid] = 0.f; ssq[tid] = 0.f; }
    __syncthreads();
    for (int i = tid; i < 5184; i += 128) {
        int u = i/432, k = i%432, c = k/9;
        wd4[k*12+u] = dupw(w4[(cbase+u)*432 + k] * A3[c]);
    }
    for (int i = tid; i < 36; i += 128) {
        int u = i / 3, j = i % 3;
        float acc = 0.f;
        for (int c = 0; c < 48; c++) {
            float bc = Bc[c];
            for (int r = 0; r < 3; r++) acc += w4[(cbase+u)*432 + c*9 + r*3 + j] * bc;
        }
        V[i] = acc;
    }
    __syncthreads();
    int cog = wid >> 1;
    int unit = wid & 1;
    int co0 = cog * 6;
    if (unit == 0) {
        u64 acc[6][2][2];
        #pragma unroll
        for (int u = 0; u < 6; u++)
            #pragma unroll
            for (int i2 = 0; i2 < 2; i2++) { acc[u][i2][0] = 0ull; acc[u][i2][1] = 0ull; }
        for (int c = 0; c < 48; c++) {
            #pragma unroll
            for (int r = 0; r < 3; r++) {
                const float* pb0 = &g_a3[(size_t)((c*5 + 0 + r)*3)*NB + b];
                const float* pb1 = &g_a3[(size_t)((c*5 + 1 + r)*3)*NB + b];
                const u64* wk = &wd4[(c*9 + r*3)*12 + co0];
                u64 v00 = ld2(pb0), v01 = ld2(pb0 + NB), v02 = ld2(pb0 + 2*NB);
                u64 v10 = ld2(pb1), v11 = ld2(pb1 + NB), v12 = ld2(pb1 + 2*NB);
                const ulonglong2* w0p = reinterpret_cast<const ulonglong2*>(wk);
                const ulonglong2* w1p = reinterpret_cast<const ulonglong2*>(wk + 12);
                const ulonglong2* w2p = reinterpret_cast<const ulonglong2*>(wk + 24);
                #pragma unroll
                for (int u2 = 0; u2 < 3; u2++) {
                    ulonglong2 ww0 = w0p[u2], ww1 = w1p[u2], ww2 = w2p[u2];
                    acc[2*u2  ][0][1] = fma2(ww0.x, v00, acc[2*u2  ][0][1]);
                    acc[2*u2+1][0][1] = fma2(ww0.y, v00, acc[2*u2+1][0][1]);
                    acc[2*u2  ][0][0] = fma2(ww1.x, v00, acc[2*u2  ][0][0]);
                    acc[2*u2  ][0][1] = fma2(ww1.x, v01, acc[2*u2  ][0][1]);
                    acc[2*u2  ][1][0] = fma2(ww1.x, v10, acc[2*u2  ][1][0]);
                    acc[2*u2  ][1][1] = fma2(ww1.x, v11, acc[2*u2  ][1][1]);
                    acc[2*u2+1][0][0] = fma2(ww1.y, v00, acc[2*u2+1][0][0]);
                    acc[2*u2+1][0][1] = fma2(ww1.y, v01, acc[2*u2+1][0][1]);
                    acc[2*u2+1][1][0] = fma2(ww1.y, v10, acc[2*u2+1][1][0]);
                    acc[2*u2+1][1][1] = fma2(ww1.y, v11, acc[2*u2+1][1][1]);
                    acc[2*u2  ][0][0] = fma2(ww2.x, v01, acc[2*u2  ][0][0]);
                    acc[2*u2  ][0][1] = fma2(ww2.x, v02, acc[2*u2  ][0][1]);
                    acc[2*u2  ][1][0] = fma2(ww2.x, v12, acc[2*u2  ][1][0]);
                    acc[2*u2+1][0][0] = fma2(ww2.y, v01, acc[2*u2+1][0][0]);
                    acc[2*u2+1][0][1] = fma2(ww2.y, v02, acc[2*u2+1][0][1]);
                    acc[2*u2+1][1][0] = fma2(ww2.y, v12, acc[2*u2+1][1][0]);
                }
            }
        }
        #pragma unroll
        for (int i2 = 0; i2 < 2; i2++) {
            int sc = 1 << i2;
            float inv = (i2 == 0) ? 1.f : 0.5f;
            #pragma unroll
            for (int u = 0; u < 6; u++) {
                float bias0 = 0.f, bias1 = 0.f;
                #pragma unroll
                for (int j = 0; j < 3; j++) {
                    int x0 = (j-1)*sc;
                    float vj = V[(co0+u)*3 + j];
                    if (x0   >= 0 && x0   < 3) bias0 += vj;
                    if (x0+1 >= 0 && x0+1 < 3) bias1 += vj;
                }
                float2 p0 = up2(acc[u][i2][0]), p1 = up2(acc[u][i2][1]);
                float vx = fmaxf(fmaxf(p0.x + bias0, p1.x + bias1), 0.f)*inv;
                float vy = fmaxf(fmaxf(p0.y + bias0, p1.y + bias1), 0.f)*inv;
                *reinterpret_cast<float2*>(&g_a4T[(size_t)((cbase+co0+u)*3 + i2)*NB + b]) =
                    make_float2(vx, vy);
                float su = wsum(vx + vy);
                float qu = wsum(vx*vx + vy*vy);
                if (lane == 0) { atomicAdd(&ssum[co0+u], su); atomicAdd(&ssq[co0+u], qu); }
            }
        }
    } else {
        u64 acc[6][2];
        #pragma unroll
        for (int u = 0; u < 6; u++) { acc[u][0] = 0ull; acc[u][1] = 0ull; }
        for (int c = 0; c < 48; c++) {
            #pragma unroll
            for (int r = 0; r < 3; r++) {
                const float* pb = &g_a3[(size_t)((c*5 + 2 + r)*3)*NB + b];
                const u64* wk = &wd4[(c*9 + r*3)*12 + co0];
                u64 v0 = ld2(pb), v1 = ld2(pb + NB);
                const ulonglong2* wp = reinterpret_cast<const ulonglong2*>(wk + 12);
                #pragma unroll
                for (int u2 = 0; u2 < 3; u2++) {
                    ulonglong2 ww = wp[u2];
                    acc[2*u2  ][0] = fma2(ww.x, v0, acc[2*u2  ][0]);
                    acc[2*u2  ][1] = fma2(ww.x, v1, acc[2*u2  ][1]);
                    acc[2*u2+1][0] = fma2(ww.y, v0, acc[2*u2+1][0]);
                    acc[2*u2+1][1] = fma2(ww.y, v1, acc[2*u2+1][1]);
                }
            }
        }
        #pragma unroll
        for (int u = 0; u < 6; u++) {
            float vj = V[(co0+u)*3 + 1];
            float2 p0 = up2(acc[u][0]), p1 = up2(acc[u][1]);
            float vx = fmaxf(fmaxf(p0.x + vj, p1.x + vj), 0.f)*0.25f;
            float vy = fmaxf(fmaxf(p0.y + vj, p1.y + vj), 0.f)*0.25f;
            *reinterpret_cast<float2*>(&g_a4T[(size_t)((cbase+co0+u)*3 + 2)*NB + b]) =
                make_float2(vx, vy);
            float su = wsum(vx + vy);
            float qu = wsum(vx*vx + vy*vy);
            if (lane == 0) { atomicAdd(&ssum[co0+u], su); atomicAdd(&ssq[co0+u], qu); }
        }
    }
    __syncthreads();
    if (tid < 12) {
        atomicAdd(&g_stats[168+cbase+tid], (double)ssum[tid]);
        atomicAdd(&g_stats[264+cbase+tid], (double)ssq[tid]);
    }
}

// ---------------- Phase 5a: bn4 affine + collapse 3 FCs into (6x288) + bias ----------------
__global__ __launch_bounds__(256) void k_phase5a(const float* __restrict__ g4, const float* __restrict__ b4,
                                                 const float* __restrict__ f1w, const float* __restrict__ f1b,
                                                 const float* __restrict__ f2w, const float* __restrict__ f2b,
                                                 const float* __restrict__ f3w, const float* __restrict__ f3b) {
    __shared__ float A4[96], B4[96], W23[576], bcs[6];
    int tid = threadIdx.x;
    if (tid < 96) {
        double m = g_stats[168+tid] / 12288.0;
        double v = g_stats[264+tid] / 12288.0 - m*m;
        float a = g4[tid] * rsqrtf((float)v + EPSF);
        A4[tid] = a; B4[tid] = b4[tid] - (float)m*a;
    }
    if (tid < 6) bcs[tid] = 0.f;
    for (int idx = tid; idx < 576; idx += 256) {
        int j = idx / 96, k = idx % 96;
        float s = 0.f;
        for (int l = 0; l < 48; l++) s += f3w[j*48 + l] * f2w[l*96 + k];
        W23[idx] = s;
    }
    __syncthreads();
    for (int idx = tid; idx < 1728; idx += 256) {
        int j = idx / 288, i = idx % 288;
        int c = i / 3;
        float s0 = 0.f;
        for (int k = 0; k < 96; k++) s0 += W23[j*96 + k] * f1w[k*288 + i];
        g_Wc[idx] = s0 * A4[c];
        atomicAdd(&bcs[j], s0 * B4[c]);
    }
    __syncthreads();
    if (tid < 6) {
        int j = tid;
        float bb = f3b[j];
        for (int l = 0; l < 48; l++) bb += f3w[j*48 + l] * f2b[l];
        for (int k = 0; k < 96; k++) bb += W23[j*96 + k] * f1b[k];
        g_bc[j] = bcs[j] + bb;
    }
}

// ---------------- Phase 5b: out[b][6] from a4T planes, 4 samples/thread ----------------
__global__ __launch_bounds__(256) void k_phase5b(float* __restrict__ out) {
    __shared__ float Wcs[1728];
    for (int i = threadIdx.x; i < 1728; i += 256) Wcs[i] = g_Wc[i];
    __syncthreads();
    int b = (blockIdx.x*256 + threadIdx.x)*4;
    float acc[6][4];
    #pragma unroll
    for (int j = 0; j < 6; j++)
        #pragma unroll
        for (int m = 0; m < 4; m++) acc[j][m] = g_bc[j];
    for (int f = 0; f < 288; f++) {
        float4 v = *reinterpret_cast<const float4*>(&g_a4T[(size_t)f*NB + b]);
        #pragma unroll
        for (int j = 0; j < 6; j++) {
            float w = Wcs[j*288 + f];
            acc[j][0] += v.x*w; acc[j][1] += v.y*w; acc[j][2] += v.z*w; acc[j][3] += v.w*w;
        }
    }
    #pragma unroll
    for (int m = 0; m < 4; m++)
        #pragma unroll
        for (int j = 0; j < 6; j++)
            out[(b+m)*6 + j] = acc[j][m];
}

// ---------------- launcher ----------------
extern "C" void kernel_launch(void* const* d_in, const int* in_sizes, int n_in,
                              void* d_out, int out_size) {
    const float* x   = (const float*)d_in[0];
    const float* w1  = (const float*)d_in[1];
    const float* w2  = (const float*)d_in[2];
    const float* w3  = (const float*)d_in[3];
    const float* w4  = (const float*)d_in[4];
    const float* g1  = (const float*)d_in[5];
    const float* b1  = (const float*)d_in[6];
    const float* g2  = (const float*)d_in[7];
    const float* b2  = (const float*)d_in[8];
    const float* g3  = (const float*)d_in[9];
    const float* b3  = (const float*)d_in[10];
    const float* g4  = (const float*)d_in[11];
    const float* b4  = (const float*)d_in[12];
    const float* f1w = (const float*)d_in[13];
    const float* f1b = (const float*)d_in[14];
    const float* f2w = (const float*)d_in[15];
    const float* f2b = (const float*)d_in[16];
    const float* f3w = (const float*)d_in[17];
    const float* f3b = (const float*)d_in[18];
    float* out = (float*)d_out;

    // NOTE: launch order puts k_p2 4th — the profiler captures the 4th launch.
    k_zero<<<1, 384>>>();
    k_tr<<<dim3(128, 19), dim3(32, 8)>>>(x);
    k_p1<<<dim3(32, 114), 128>>>(w1);
    k_p2<<<dim3(32, 44), 128>>>(w2, g1, b1);
    k_p3<<<dim3(32, 32), 128>>>(w3, g2, b2);
    k_p4<<<dim3(64, 8), 128>>>(w4, g3, b3);
    k_phase5a<<<1, 256>>>(g4, b4, f1w, f1b, f2w, f2b, f3w, f3b);
    k_phase5b<<<4, 256>>>(out);
}